// round 1
// baseline (speedup 1.0000x reference)
#include <cuda_runtime.h>
#include <math.h>

// ---------------- problem constants ----------------
#define DM   1024          // d_model
#define NHD  16            // heads
#define DH   64            // head dim
#define SEQ  1024          // both src and tgt seq len
#define NB   2             // batch
#define NTOK 2048          // NB*SEQ
#define HFF  4096
#define NV   32000
#define NLE  6
#define NLD  6

// ---------------- scratch (static device globals; no runtime alloc) -------
__device__ float g_X [(size_t)NTOK*DM];
__device__ float g_Y [(size_t)NTOK*DM];
__device__ float g_MEM[(size_t)NTOK*DM];
__device__ float g_H [(size_t)NTOK*DM];
__device__ float g_Q [(size_t)NTOK*DM];
__device__ float g_K [(size_t)NTOK*DM];
__device__ float g_V [(size_t)NTOK*DM];
__device__ float g_AO[(size_t)NTOK*DM];
__device__ float g_SC[(size_t)NB*NHD*SEQ*SEQ];   // 128 MB attention scores
__device__ float g_FF[(size_t)NTOK*HFF];

// ---------------- reductions ----------------
__device__ __forceinline__ float warpSum(float v){
#pragma unroll
    for (int o=16;o>0;o>>=1) v += __shfl_xor_sync(0xffffffffu, v, o);
    return v;
}
__device__ __forceinline__ float warpMax(float v){
#pragma unroll
    for (int o=16;o>0;o>>=1) v = fmaxf(v, __shfl_xor_sync(0xffffffffu, v, o));
    return v;
}
__device__ float blockSum(float v){
    __shared__ float sh[32];
    int lane = threadIdx.x & 31, w = threadIdx.x >> 5;
    v = warpSum(v);
    if (lane==0) sh[w] = v;
    __syncthreads();
    if (w==0){
        float r = (lane < (int)(blockDim.x>>5)) ? sh[lane] : 0.f;
        r = warpSum(r);
        if (lane==0) sh[0] = r;
    }
    __syncthreads();
    float r = sh[0];
    __syncthreads();
    return r;
}
__device__ float blockMax(float v){
    __shared__ float sh[32];
    int lane = threadIdx.x & 31, w = threadIdx.x >> 5;
    v = warpMax(v);
    if (lane==0) sh[w] = v;
    __syncthreads();
    if (w==0){
        float r = (lane < (int)(blockDim.x>>5)) ? sh[lane] : -INFINITY;
        r = warpMax(r);
        if (lane==0) sh[0] = r;
    }
    __syncthreads();
    float r = sh[0];
    __syncthreads();
    return r;
}

// ---------------- generic batched GEMM ----------------
// C[z] = act(A[z] @ op(B[z]) + bias) (+ res[z])
// op(B) = B (row-major KxN) if !transB, else B^T with B row-major NxK.
// Batch offsets: off = (z/nh)*o_b + (z%nh)*o_h  for A, B, C(and res).
__global__ void __launch_bounds__(256) gemm_k(
    const float* __restrict__ A, const float* __restrict__ B,
    const float* __restrict__ bias, const float* __restrict__ res,
    float* __restrict__ C,
    int M, int N, int K, int lda, int ldb, int ldc,
    int transB, int doGelu,
    long aob, long aoh, long bob, long boh, long cob, long coh, int nh)
{
    int z  = blockIdx.z;
    int zb = z / nh, zh = z - zb*nh;
    A += zb*aob + zh*aoh;
    B += zb*bob + zh*boh;
    C += zb*cob + zh*coh;
    if (res) res += zb*cob + zh*coh;

    __shared__ float As[16][65];
    __shared__ float Bs[16][65];

    int tid = threadIdx.x;
    int tx = tid & 15, ty = tid >> 4;
    int row0 = blockIdx.y * 64;
    int col0 = blockIdx.x * 64;

    float acc[4][4];
#pragma unroll
    for (int i=0;i<4;i++)
#pragma unroll
        for (int j=0;j<4;j++) acc[i][j] = 0.f;

    for (int k0 = 0; k0 < K; k0 += 16) {
#pragma unroll
        for (int i = 0; i < 4; i++) {
            int lin = i*256 + tid;
            int m = lin >> 4, kk = lin & 15;
            int gm = row0 + m;
            As[kk][m] = (gm < M) ? A[(long)gm*lda + (k0+kk)] : 0.f;
        }
        if (!transB) {
#pragma unroll
            for (int i = 0; i < 4; i++) {
                int lin = i*256 + tid;
                int kk = lin >> 6, n = lin & 63;
                int gn = col0 + n;
                Bs[kk][n] = (gn < N) ? B[(long)(k0+kk)*ldb + gn] : 0.f;
            }
        } else {
#pragma unroll
            for (int i = 0; i < 4; i++) {
                int lin = i*256 + tid;
                int n = lin >> 4, kk = lin & 15;
                int gn = col0 + n;
                Bs[kk][n] = (gn < N) ? B[(long)gn*ldb + (k0+kk)] : 0.f;
            }
        }
        __syncthreads();
#pragma unroll
        for (int kk = 0; kk < 16; kk++) {
            float a[4], b[4];
#pragma unroll
            for (int i=0;i<4;i++) a[i] = As[kk][ty*4+i];
#pragma unroll
            for (int j=0;j<4;j++) b[j] = Bs[kk][tx*4+j];
#pragma unroll
            for (int i=0;i<4;i++)
#pragma unroll
                for (int j=0;j<4;j++)
                    acc[i][j] = fmaf(a[i], b[j], acc[i][j]);
        }
        __syncthreads();
    }

#pragma unroll
    for (int i=0;i<4;i++) {
        int gm = row0 + ty*4 + i;
        if (gm >= M) continue;
#pragma unroll
        for (int j=0;j<4;j++) {
            int gn = col0 + tx*4 + j;
            if (gn >= N) continue;
            float v = acc[i][j];
            if (bias) v += bias[gn];
            if (doGelu) v = 0.5f*v*(1.0f + erff(v*0.70710678118654752f));
            if (res) v += res[(long)gm*ldc + gn];
            C[(long)gm*ldc + gn] = v;
        }
    }
}

// ---------------- embedding + sinusoidal positional encoding --------------
__global__ void embed_k(const int* __restrict__ tok, const float* __restrict__ emb,
                        float* __restrict__ out)
{
    int t = blockIdx.x;
    int s = t & (SEQ-1);
    int id = tok[t];
    const float* e = emb + (long)id*DM;
    float* o = out + (long)t*DM;
    const float c = -logf(10000.0f) / (float)DM;
    for (int d = threadIdx.x; d < DM; d += blockDim.x) {
        int i2 = d & ~1;
        float ang = (float)s * expf((float)i2 * c);
        float pe = (d & 1) ? cosf(ang) : sinf(ang);
        o[d] = e[d]*32.0f + pe;   // sqrt(1024) == 32
    }
}

// ---------------- LayerNorm ----------------
__global__ void ln_k(const float* __restrict__ x, const float* __restrict__ g,
                     const float* __restrict__ b, float* __restrict__ out)
{
    long t = blockIdx.x;
    const float* xr = x + t*DM;
    float* o = out + t*DM;
    float s = 0.f, ss = 0.f;
    for (int d = threadIdx.x; d < DM; d += blockDim.x){
        float v = xr[d]; s += v; ss += v*v;
    }
    s  = blockSum(s);
    ss = blockSum(ss);
    float mean = s * (1.0f/DM);
    float var  = ss * (1.0f/DM) - mean*mean;
    float inv  = rsqrtf(var + 1e-5f);
    for (int d = threadIdx.x; d < DM; d += blockDim.x)
        o[d] = (xr[d]-mean)*inv*g[d] + b[d];
}

// ---------------- softmax over rows of length SEQ (in place) --------------
__global__ void softmax_k(float* __restrict__ p)
{
    float* r = p + (long)blockIdx.x * SEQ;
    float mx = -INFINITY;
    for (int d = threadIdx.x; d < SEQ; d += blockDim.x) mx = fmaxf(mx, r[d]);
    mx = blockMax(mx);
    float sum = 0.f;
    for (int d = threadIdx.x; d < SEQ; d += blockDim.x){
        float e = expf(r[d]-mx); r[d] = e; sum += e;
    }
    sum = blockSum(sum);
    float inv = 1.f/sum;
    for (int d = threadIdx.x; d < SEQ; d += blockDim.x) r[d] *= inv;
}

// ---------------- log_softmax over rows of length NV (in place) -----------
__global__ void logsoftmax_k(float* __restrict__ p)
{
    float* r = p + (long)blockIdx.x * NV;
    float mx = -INFINITY;
    for (int d = threadIdx.x; d < NV; d += blockDim.x) mx = fmaxf(mx, r[d]);
    mx = blockMax(mx);
    float sum = 0.f;
    for (int d = threadIdx.x; d < NV; d += blockDim.x) sum += expf(r[d]-mx);
    sum = blockSum(sum);
    float lse = mx + logf(sum);
    for (int d = threadIdx.x; d < NV; d += blockDim.x) r[d] -= lse;
}

// ---------------- host-side helpers ----------------
static void gemm(const float* A, const float* B, const float* bias, const float* res,
                 float* C, int M, int N, int K, int lda, int ldb, int ldc,
                 int transB, int gelu,
                 long aob=0, long aoh=0, long bob=0, long boh=0,
                 long cob=0, long coh=0, int nh=1, int nz=1)
{
    dim3 grid((N+63)/64, (M+63)/64, nz);
    gemm_k<<<grid, 256>>>(A,B,bias,res,C,M,N,K,lda,ldb,ldc,transB,gelu,
                          aob,aoh,bob,boh,cob,coh,nh);
}

// One full MHA block: x += proj(attn(Hq, Hkv))
static void attention(const float* Hq, const float* Hkv,
                      const float* wqkv, const float* bqkv,
                      const float* wproj, const float* bproj,
                      float* x,
                      float* Q, float* Kb, float* Vb, float* Sc, float* AO)
{
    gemm(Hq,  wqkv + 0*(size_t)DM*DM, bqkv + 0*DM, nullptr, Q,  NTOK, DM, DM, DM, DM, DM, 0, 0);
    gemm(Hkv, wqkv + 1*(size_t)DM*DM, bqkv + 1*DM, nullptr, Kb, NTOK, DM, DM, DM, DM, DM, 0, 0);
    gemm(Hkv, wqkv + 2*(size_t)DM*DM, bqkv + 2*DM, nullptr, Vb, NTOK, DM, DM, DM, DM, DM, 0, 0);
    // scores[b,h] = Q[b,h] @ K[b,h]^T   (M=SEQ, N=SEQ, K=DH) — NOTE: no scaling (faithful)
    gemm(Q, Kb, nullptr, nullptr, Sc, SEQ, SEQ, DH, DM, DM, SEQ, 1, 0,
         (long)SEQ*DM, DH, (long)SEQ*DM, DH,
         (long)NHD*SEQ*SEQ, (long)SEQ*SEQ, NHD, NB*NHD);
    softmax_k<<<NB*NHD*SEQ, 256>>>(Sc);
    // AO[b,h] = P[b,h] @ V[b,h]   (M=SEQ, N=DH, K=SEQ), written back in [tok, h*DH+d] layout
    gemm(Sc, Vb, nullptr, nullptr, AO, SEQ, DH, SEQ, SEQ, DM, DM, 0, 0,
         (long)NHD*SEQ*SEQ, (long)SEQ*SEQ, (long)SEQ*DM, DH,
         (long)SEQ*DM, DH, NHD, NB*NHD);
    // x = x + AO @ Wo + bo
    gemm(AO, wproj, bproj, x, x, NTOK, DM, DM, DM, DM, DM, 0, 0);
}

extern "C" void kernel_launch(void* const* d_in, const int* in_sizes, int n_in,
                              void* d_out, int out_size)
{
    const int*   src        = (const int*)  d_in[0];
    const int*   tgt        = (const int*)  d_in[1];
    // d_in[2..4]: masks — no-ops in the reference
    const float* emb        = (const float*)d_in[5];
    const float* enc_qkv_w  = (const float*)d_in[6];
    const float* enc_qkv_b  = (const float*)d_in[7];
    const float* enc_proj_w = (const float*)d_in[8];
    const float* enc_proj_b = (const float*)d_in[9];
    const float* enc_ff_w1  = (const float*)d_in[10];
    const float* enc_ff_b1  = (const float*)d_in[11];
    const float* enc_ff_w2  = (const float*)d_in[12];
    const float* enc_ff_b2  = (const float*)d_in[13];
    const float* enc_ln_g   = (const float*)d_in[14];
    const float* enc_ln_b   = (const float*)d_in[15];
    const float* enc_norm_g = (const float*)d_in[16];
    const float* enc_norm_b = (const float*)d_in[17];
    const float* dec_qkv_w  = (const float*)d_in[18];
    const float* dec_qkv_b  = (const float*)d_in[19];
    const float* dec_proj_w = (const float*)d_in[20];
    const float* dec_proj_b = (const float*)d_in[21];
    const float* dec_ff_w1  = (const float*)d_in[22];
    const float* dec_ff_b1  = (const float*)d_in[23];
    const float* dec_ff_w2  = (const float*)d_in[24];
    const float* dec_ff_b2  = (const float*)d_in[25];
    const float* dec_ln_g   = (const float*)d_in[26];
    const float* dec_ln_b   = (const float*)d_in[27];
    const float* dec_norm_g = (const float*)d_in[28];
    const float* dec_norm_b = (const float*)d_in[29];
    const float* gen_w      = (const float*)d_in[30];
    const float* gen_b      = (const float*)d_in[31];
    float* out = (float*)d_out;

    float *X,*Y,*MEMB,*H,*Q,*K,*V,*AO,*SC,*FF;
    cudaGetSymbolAddress((void**)&X,   g_X);
    cudaGetSymbolAddress((void**)&Y,   g_Y);
    cudaGetSymbolAddress((void**)&MEMB,g_MEM);
    cudaGetSymbolAddress((void**)&H,   g_H);
    cudaGetSymbolAddress((void**)&Q,   g_Q);
    cudaGetSymbolAddress((void**)&K,   g_K);
    cudaGetSymbolAddress((void**)&V,   g_V);
    cudaGetSymbolAddress((void**)&AO,  g_AO);
    cudaGetSymbolAddress((void**)&SC,  g_SC);
    cudaGetSymbolAddress((void**)&FF,  g_FF);

    // ---------------- encoder ----------------
    embed_k<<<NTOK,256>>>(src, emb, X);
    for (int l = 0; l < NLE; l++) {
        ln_k<<<NTOK,256>>>(X, enc_ln_g + (size_t)(l*2+0)*DM, enc_ln_b + (size_t)(l*2+0)*DM, H);
        attention(H, H,
                  enc_qkv_w + (size_t)l*3*DM*DM, enc_qkv_b + (size_t)l*3*DM,
                  enc_proj_w + (size_t)l*DM*DM,  enc_proj_b + (size_t)l*DM,
                  X, Q, K, V, SC, AO);
        ln_k<<<NTOK,256>>>(X, enc_ln_g + (size_t)(l*2+1)*DM, enc_ln_b + (size_t)(l*2+1)*DM, H);
        gemm(H,  enc_ff_w1 + (size_t)l*DM*HFF, enc_ff_b1 + (size_t)l*HFF, nullptr, FF,
             NTOK, HFF, DM, DM, HFF, HFF, 0, 1);
        gemm(FF, enc_ff_w2 + (size_t)l*HFF*DM, enc_ff_b2 + (size_t)l*DM, X, X,
             NTOK, DM, HFF, HFF, DM, DM, 0, 1);
    }
    ln_k<<<NTOK,256>>>(X, enc_norm_g, enc_norm_b, MEMB);

    // ---------------- decoder ----------------
    embed_k<<<NTOK,256>>>(tgt, emb, Y);
    for (int l = 0; l < NLD; l++) {
        // self-attention
        ln_k<<<NTOK,256>>>(Y, dec_ln_g + (size_t)(l*3+0)*DM, dec_ln_b + (size_t)(l*3+0)*DM, H);
        attention(H, H,
                  dec_qkv_w + (size_t)(l*2+0)*3*DM*DM, dec_qkv_b + (size_t)(l*2+0)*3*DM,
                  dec_proj_w + (size_t)(l*2+0)*DM*DM,  dec_proj_b + (size_t)(l*2+0)*DM,
                  Y, Q, K, V, SC, AO);
        // cross-attention (K/V from encoder memory)
        ln_k<<<NTOK,256>>>(Y, dec_ln_g + (size_t)(l*3+1)*DM, dec_ln_b + (size_t)(l*3+1)*DM, H);
        attention(H, MEMB,
                  dec_qkv_w + (size_t)(l*2+1)*3*DM*DM, dec_qkv_b + (size_t)(l*2+1)*3*DM,
                  dec_proj_w + (size_t)(l*2+1)*DM*DM,  dec_proj_b + (size_t)(l*2+1)*DM,
                  Y, Q, K, V, SC, AO);
        // feed-forward (GELU after BOTH linears — faithful to source)
        ln_k<<<NTOK,256>>>(Y, dec_ln_g + (size_t)(l*3+2)*DM, dec_ln_b + (size_t)(l*3+2)*DM, H);
        gemm(H,  dec_ff_w1 + (size_t)l*DM*HFF, dec_ff_b1 + (size_t)l*HFF, nullptr, FF,
             NTOK, HFF, DM, DM, HFF, HFF, 0, 1);
        gemm(FF, dec_ff_w2 + (size_t)l*HFF*DM, dec_ff_b2 + (size_t)l*DM, Y, Y,
             NTOK, DM, HFF, HFF, DM, DM, 0, 1);
    }
    ln_k<<<NTOK,256>>>(Y, dec_norm_g, dec_norm_b, H);

    // ---------------- generator + log_softmax ----------------
    gemm(H, gen_w, gen_b, nullptr, out, NTOK, NV, DM, DM, NV, NV, 0, 0);
    logsoftmax_k<<<NTOK,256>>>(out);
}

// round 2
// speedup vs baseline: 2.6411x; 2.6411x over previous
#include <cuda_runtime.h>
#include <mma.h>
#include <math.h>

using namespace nvcuda;

// ---------------- problem constants ----------------
#define DM   1024
#define NHD  16
#define DH   64
#define SEQ  1024
#define NB   2
#define NTOK 2048
#define HFF  4096
#define NV   32000
#define NLE  6
#define NLD  6

// ---------------- GEMM tile config ----------------
#define BM 128
#define BN 128
#define BK 32
#define ASTR 40    // As row stride (floats): 160B rows, 32B-aligned frag ptrs
#define BSTR 136   // Bs row stride (floats): 544B rows, 32B-aligned frag ptrs
#define SMEM_FLOATS (BM*ASTR + BK*BSTR)   // 5120 + 4352 = 9472 (37.9 KB)

// ---------------- scratch ----------------
__device__ float g_X  [(size_t)NTOK*DM];
__device__ float g_Y  [(size_t)NTOK*DM];
__device__ float g_MEM[(size_t)NTOK*DM];
__device__ float g_H  [(size_t)NTOK*DM];
__device__ float g_QKV[(size_t)3*NTOK*DM];
__device__ float g_AO [(size_t)NTOK*DM];
__device__ float g_SC [(size_t)NB*NHD*SEQ*SEQ];
__device__ float g_FF [(size_t)NTOK*HFF];

// ---------------- reductions ----------------
__device__ __forceinline__ float warpSum(float v){
#pragma unroll
    for (int o=16;o>0;o>>=1) v += __shfl_xor_sync(0xffffffffu, v, o);
    return v;
}
__device__ __forceinline__ float warpMax(float v){
#pragma unroll
    for (int o=16;o>0;o>>=1) v = fmaxf(v, __shfl_xor_sync(0xffffffffu, v, o));
    return v;
}
__device__ float blockSum(float v){
    __shared__ float sh[32];
    int lane = threadIdx.x & 31, w = threadIdx.x >> 5;
    v = warpSum(v);
    if (lane==0) sh[w] = v;
    __syncthreads();
    if (w==0){
        float r = (lane < (int)(blockDim.x>>5)) ? sh[lane] : 0.f;
        r = warpSum(r);
        if (lane==0) sh[0] = r;
    }
    __syncthreads();
    float r = sh[0];
    __syncthreads();
    return r;
}
__device__ float blockMax(float v){
    __shared__ float sh[32];
    int lane = threadIdx.x & 31, w = threadIdx.x >> 5;
    v = warpMax(v);
    if (lane==0) sh[w] = v;
    __syncthreads();
    if (w==0){
        float r = (lane < (int)(blockDim.x>>5)) ? sh[lane] : -INFINITY;
        r = warpMax(r);
        if (lane==0) sh[0] = r;
    }
    __syncthreads();
    float r = sh[0];
    __syncthreads();
    return r;
}

// ---------------- TF32 tensor-core GEMM ----------------
// C[z] = act(A[z] @ op(B[z]) + bias[z]) (+ res[z])
// Requirements (all call sites satisfy): M % 128 == 0, K % 32 == 0, N % 4 == 0.
// Batch offsets: off = (z/nh)*ob + (z%nh)*oh.
__global__ void __launch_bounds__(256) gemm_tc(
    const float* __restrict__ A, const float* __restrict__ B,
    const float* __restrict__ bias, const float* __restrict__ res,
    float* __restrict__ C,
    int M, int N, int K, int lda, int ldb, int ldc,
    int transB, int doGelu,
    long aob, long aoh, long bob, long boh, long biasoh,
    long cob, long coh, int nh)
{
    int z  = blockIdx.z;
    int zb = z / nh, zh = z - zb*nh;
    A += zb*aob + zh*aoh;
    B += zb*bob + zh*boh;
    C += zb*cob + zh*coh;
    if (res)  res  += zb*cob + zh*coh;
    if (bias) bias += zh*biasoh;

    __shared__ __align__(32) float sm[SMEM_FLOATS];
    float* As = sm;
    float* Bs = sm + BM*ASTR;

    int tid = threadIdx.x;
    int wid = tid >> 5;
    int wm = wid >> 2;        // 0..1 -> 64-row half
    int wn = wid & 3;         // 0..3 -> 32-col quarter
    long row0 = (long)blockIdx.y * BM;
    long col0 = (long)blockIdx.x * BN;

    // A tile load pattern: 128 rows x 32 cols, float4
    int arow  = tid >> 3;           // 0..31 (stride 32, 4 passes)
    int acol4 = (tid & 7) * 4;      // 0..28

    float4 pa[4], pb[4];

    auto fetchA = [&](int k0){
#pragma unroll
        for (int i = 0; i < 4; i++) {
            int r = arow + i*32;
            pa[i] = *(const float4*)(A + (row0 + r)*(long)lda + k0 + acol4);
        }
    };
    auto fetchB = [&](int k0){
        if (!transB) {
#pragma unroll
            for (int i = 0; i < 4; i++) {
                int r  = (tid >> 5) + i*8;
                long gn = col0 + (tid & 31)*4;
                pb[i] = (gn < N) ? *(const float4*)(B + (long)(k0 + r)*ldb + gn)
                                 : make_float4(0.f,0.f,0.f,0.f);
            }
        } else {
#pragma unroll
            for (int i = 0; i < 4; i++) {
                long gn = col0 + (tid >> 3) + i*32;
                pb[i] = (gn < N) ? *(const float4*)(B + gn*(long)ldb + k0 + (tid & 7)*4)
                                 : make_float4(0.f,0.f,0.f,0.f);
            }
        }
    };
    auto stage = [&](){
#pragma unroll
        for (int i = 0; i < 4; i++) {
            int r = arow + i*32;
            *(float4*)(As + r*ASTR + acol4) = pa[i];
        }
        if (!transB) {
#pragma unroll
            for (int i = 0; i < 4; i++) {
                int r = (tid >> 5) + i*8;
                int c = (tid & 31)*4;
                *(float4*)(Bs + r*BSTR + c) = pb[i];
            }
        } else {
#pragma unroll
            for (int i = 0; i < 4; i++) {
                int n = (tid >> 3) + i*32;
                int k = (tid & 7)*4;
                Bs[(k+0)*BSTR + n] = pb[i].x;
                Bs[(k+1)*BSTR + n] = pb[i].y;
                Bs[(k+2)*BSTR + n] = pb[i].z;
                Bs[(k+3)*BSTR + n] = pb[i].w;
            }
        }
    };

    wmma::fragment<wmma::accumulator, 16,16,8, float> acc[4][2];
#pragma unroll
    for (int i=0;i<4;i++)
#pragma unroll
        for (int j=0;j<2;j++) wmma::fill_fragment(acc[i][j], 0.f);

    fetchA(0); fetchB(0);
    stage();
    __syncthreads();

    for (int k0 = BK; k0 <= K; k0 += BK) {
        bool more = (k0 < K);
        if (more) { fetchA(k0); fetchB(k0); }

#pragma unroll
        for (int kk = 0; kk < BK; kk += 8) {
            wmma::fragment<wmma::matrix_a, 16,16,8, wmma::precision::tf32, wmma::row_major> af[4];
            wmma::fragment<wmma::matrix_b, 16,16,8, wmma::precision::tf32, wmma::row_major> bf[2];
#pragma unroll
            for (int i=0;i<4;i++) {
                wmma::load_matrix_sync(af[i], As + (wm*64 + i*16)*ASTR + kk, ASTR);
#pragma unroll
                for (int t=0;t<af[i].num_elements;t++)
                    af[i].x[t] = wmma::__float_to_tf32(af[i].x[t]);
            }
#pragma unroll
            for (int j=0;j<2;j++) {
                wmma::load_matrix_sync(bf[j], Bs + kk*BSTR + wn*32 + j*16, BSTR);
#pragma unroll
                for (int t=0;t<bf[j].num_elements;t++)
                    bf[j].x[t] = wmma::__float_to_tf32(bf[j].x[t]);
            }
#pragma unroll
            for (int i=0;i<4;i++)
#pragma unroll
                for (int j=0;j<2;j++)
                    wmma::mma_sync(acc[i][j], af[i], bf[j], acc[i][j]);
        }
        __syncthreads();
        if (more) { stage(); __syncthreads(); }
    }

    // epilogue: two 64-row phases staged through shared (reusing sm)
    float* Cs = sm;   // 64 x 136
    for (int ph = 0; ph < 2; ph++) {
        if (wm == ph) {
#pragma unroll
            for (int i=0;i<4;i++)
#pragma unroll
                for (int j=0;j<2;j++)
                    wmma::store_matrix_sync(Cs + (i*16)*BSTR + wn*32 + j*16,
                                            acc[i][j], BSTR, wmma::mem_row_major);
        }
        __syncthreads();
#pragma unroll
        for (int it = 0; it < 8; it++) {
            int r  = (tid >> 5) + it*8;        // 0..63
            int cc = (tid & 31)*4;             // 0..124
            long gm = row0 + ph*64 + r;
            long gn = col0 + cc;
            if (gn < N) {
                float4 v = *(float4*)(Cs + r*BSTR + cc);
                float* vp = &v.x;
#pragma unroll
                for (int j=0;j<4;j++) {
                    float x = vp[j];
                    if (bias) x += bias[gn+j];
                    if (doGelu) x = 0.5f*x*(1.0f + erff(x*0.70710678118654752f));
                    if (res) x += res[gm*(long)ldc + gn + j];
                    C[gm*(long)ldc + gn + j] = x;
                }
            }
        }
        __syncthreads();
    }
}

// ---------------- embedding + positional encoding ----------------
__global__ void embed_k(const int* __restrict__ tok, const float* __restrict__ emb,
                        float* __restrict__ out)
{
    int t = blockIdx.x;
    int s = t & (SEQ-1);
    int id = tok[t];
    const float* e = emb + (long)id*DM;
    float* o = out + (long)t*DM;
    const float c = -logf(10000.0f) / (float)DM;
    for (int d = threadIdx.x; d < DM; d += blockDim.x) {
        int i2 = d & ~1;
        float ang = (float)s * expf((float)i2 * c);
        float pe = (d & 1) ? cosf(ang) : sinf(ang);
        o[d] = e[d]*32.0f + pe;
    }
}

// ---------------- LayerNorm ----------------
__global__ void ln_k(const float* __restrict__ x, const float* __restrict__ g,
                     const float* __restrict__ b, float* __restrict__ out)
{
    long t = blockIdx.x;
    const float4* xr = (const float4*)(x + t*DM);
    float4* o = (float4*)(out + t*DM);
    float4 v = xr[threadIdx.x];
    float s  = v.x+v.y+v.z+v.w;
    float ss = v.x*v.x+v.y*v.y+v.z*v.z+v.w*v.w;
    s  = blockSum(s);
    ss = blockSum(ss);
    float mean = s * (1.0f/DM);
    float var  = ss * (1.0f/DM) - mean*mean;
    float inv  = rsqrtf(var + 1e-5f);
    float4 gg = ((const float4*)g)[threadIdx.x];
    float4 bb = ((const float4*)b)[threadIdx.x];
    float4 r;
    r.x = (v.x-mean)*inv*gg.x + bb.x;
    r.y = (v.y-mean)*inv*gg.y + bb.y;
    r.z = (v.z-mean)*inv*gg.z + bb.z;
    r.w = (v.w-mean)*inv*gg.w + bb.w;
    o[threadIdx.x] = r;
}

// ---------------- softmax (row of SEQ, register resident) ----------------
__global__ void softmax_k(float* __restrict__ p)
{
    float4* r = (float4*)(p + (long)blockIdx.x * SEQ);
    float4 v = r[threadIdx.x];
    float mx = fmaxf(fmaxf(v.x,v.y), fmaxf(v.z,v.w));
    mx = blockMax(mx);
    v.x = expf(v.x-mx); v.y = expf(v.y-mx);
    v.z = expf(v.z-mx); v.w = expf(v.w-mx);
    float sum = blockSum(v.x+v.y+v.z+v.w);
    float inv = 1.f/sum;
    v.x*=inv; v.y*=inv; v.z*=inv; v.w*=inv;
    r[threadIdx.x] = v;
}

// ---------------- log_softmax over NV ----------------
__global__ void logsoftmax_k(float* __restrict__ p)
{
    float* r = p + (long)blockIdx.x * NV;
    float mx = -INFINITY;
    for (int d = threadIdx.x; d < NV; d += blockDim.x) mx = fmaxf(mx, r[d]);
    mx = blockMax(mx);
    float sum = 0.f;
    for (int d = threadIdx.x; d < NV; d += blockDim.x) sum += expf(r[d]-mx);
    sum = blockSum(sum);
    float lse = mx + logf(sum);
    for (int d = threadIdx.x; d < NV; d += blockDim.x) r[d] -= lse;
}

// ---------------- host helpers ----------------
static void gemm(const float* A, const float* B, const float* bias, const float* res,
                 float* C, int M, int N, int K, int lda, int ldb, int ldc,
                 int transB, int gelu,
                 long aob=0, long aoh=0, long bob=0, long boh=0, long biasoh=0,
                 long cob=0, long coh=0, int nh=1, int nz=1)
{
    dim3 grid((N+BN-1)/BN, M/BM, nz);
    gemm_tc<<<grid, 256>>>(A,B,bias,res,C,M,N,K,lda,ldb,ldc,transB,gelu,
                           aob,aoh,bob,boh,biasoh,cob,coh,nh);
}

static void attention(const float* Hq, const float* Hkv,
                      const float* wqkv, const float* bqkv,
                      const float* wproj, const float* bproj,
                      float* x, int sameKV,
                      float* QKV, float* Sc, float* AO)
{
    float* Q  = QKV;
    float* Kb = QKV + (size_t)NTOK*DM;
    float* Vb = QKV + (size_t)2*NTOK*DM;
    if (sameKV) {
        // fused Q,K,V: z in {0,1,2}
        gemm(Hq, wqkv, bqkv, nullptr, QKV, NTOK, DM, DM, DM, DM, DM, 0, 0,
             0, 0, 0, (long)DM*DM, DM, 0, (long)NTOK*DM, 3, 3);
    } else {
        gemm(Hq, wqkv, bqkv, nullptr, Q, NTOK, DM, DM, DM, DM, DM, 0, 0);
        // fused K,V: z in {0,1} over wqkv[1],wqkv[2]
        gemm(Hkv, wqkv + (size_t)DM*DM, bqkv + DM, nullptr, Kb,
             NTOK, DM, DM, DM, DM, DM, 0, 0,
             0, 0, 0, (long)DM*DM, DM, 0, (long)NTOK*DM, 2, 2);
    }
    // scores[b,h] = Q[b,h] @ K[b,h]^T (no scaling — faithful to reference)
    gemm(Q, Kb, nullptr, nullptr, Sc, SEQ, SEQ, DH, DM, DM, SEQ, 1, 0,
         (long)SEQ*DM, DH, (long)SEQ*DM, DH, 0,
         (long)NHD*SEQ*SEQ, (long)SEQ*SEQ, NHD, NB*NHD);
    softmax_k<<<NB*NHD*SEQ, 256>>>(Sc);
    // AO[b,h] = P @ V
    gemm(Sc, Vb, nullptr, nullptr, AO, SEQ, DH, SEQ, SEQ, DM, DM, 0, 0,
         (long)NHD*SEQ*SEQ, (long)SEQ*SEQ, (long)SEQ*DM, DH, 0,
         (long)SEQ*DM, DH, NHD, NB*NHD);
    // x = x + AO @ Wo + bo
    gemm(AO, wproj, bproj, x, x, NTOK, DM, DM, DM, DM, DM, 0, 0);
}

extern "C" void kernel_launch(void* const* d_in, const int* in_sizes, int n_in,
                              void* d_out, int out_size)
{
    const int*   src        = (const int*)  d_in[0];
    const int*   tgt        = (const int*)  d_in[1];
    const float* emb        = (const float*)d_in[5];
    const float* enc_qkv_w  = (const float*)d_in[6];
    const float* enc_qkv_b  = (const float*)d_in[7];
    const float* enc_proj_w = (const float*)d_in[8];
    const float* enc_proj_b = (const float*)d_in[9];
    const float* enc_ff_w1  = (const float*)d_in[10];
    const float* enc_ff_b1  = (const float*)d_in[11];
    const float* enc_ff_w2  = (const float*)d_in[12];
    const float* enc_ff_b2  = (const float*)d_in[13];
    const float* enc_ln_g   = (const float*)d_in[14];
    const float* enc_ln_b   = (const float*)d_in[15];
    const float* enc_norm_g = (const float*)d_in[16];
    const float* enc_norm_b = (const float*)d_in[17];
    const float* dec_qkv_w  = (const float*)d_in[18];
    const float* dec_qkv_b  = (const float*)d_in[19];
    const float* dec_proj_w = (const float*)d_in[20];
    const float* dec_proj_b = (const float*)d_in[21];
    const float* dec_ff_w1  = (const float*)d_in[22];
    const float* dec_ff_b1  = (const float*)d_in[23];
    const float* dec_ff_w2  = (const float*)d_in[24];
    const float* dec_ff_b2  = (const float*)d_in[25];
    const float* dec_ln_g   = (const float*)d_in[26];
    const float* dec_ln_b   = (const float*)d_in[27];
    const float* dec_norm_g = (const float*)d_in[28];
    const float* dec_norm_b = (const float*)d_in[29];
    const float* gen_w      = (const float*)d_in[30];
    const float* gen_b      = (const float*)d_in[31];
    float* out = (float*)d_out;

    float *X,*Y,*MEMB,*H,*QKV,*AO,*SC,*FF;
    cudaGetSymbolAddress((void**)&X,   g_X);
    cudaGetSymbolAddress((void**)&Y,   g_Y);
    cudaGetSymbolAddress((void**)&MEMB,g_MEM);
    cudaGetSymbolAddress((void**)&H,   g_H);
    cudaGetSymbolAddress((void**)&QKV, g_QKV);
    cudaGetSymbolAddress((void**)&AO,  g_AO);
    cudaGetSymbolAddress((void**)&SC,  g_SC);
    cudaGetSymbolAddress((void**)&FF,  g_FF);

    // ---------------- encoder ----------------
    embed_k<<<NTOK,256>>>(src, emb, X);
    for (int l = 0; l < NLE; l++) {
        ln_k<<<NTOK,256>>>(X, enc_ln_g + (size_t)(l*2+0)*DM, enc_ln_b + (size_t)(l*2+0)*DM, H);
        attention(H, H,
                  enc_qkv_w + (size_t)l*3*DM*DM, enc_qkv_b + (size_t)l*3*DM,
                  enc_proj_w + (size_t)l*DM*DM,  enc_proj_b + (size_t)l*DM,
                  X, 1, QKV, SC, AO);
        ln_k<<<NTOK,256>>>(X, enc_ln_g + (size_t)(l*2+1)*DM, enc_ln_b + (size_t)(l*2+1)*DM, H);
        gemm(H,  enc_ff_w1 + (size_t)l*DM*HFF, enc_ff_b1 + (size_t)l*HFF, nullptr, FF,
             NTOK, HFF, DM, DM, HFF, HFF, 0, 1);
        gemm(FF, enc_ff_w2 + (size_t)l*HFF*DM, enc_ff_b2 + (size_t)l*DM, X, X,
             NTOK, DM, HFF, HFF, DM, DM, 0, 1);
    }
    ln_k<<<NTOK,256>>>(X, enc_norm_g, enc_norm_b, MEMB);

    // ---------------- decoder ----------------
    embed_k<<<NTOK,256>>>(tgt, emb, Y);
    for (int l = 0; l < NLD; l++) {
        ln_k<<<NTOK,256>>>(Y, dec_ln_g + (size_t)(l*3+0)*DM, dec_ln_b + (size_t)(l*3+0)*DM, H);
        attention(H, H,
                  dec_qkv_w + (size_t)(l*2+0)*3*DM*DM, dec_qkv_b + (size_t)(l*2+0)*3*DM,
                  dec_proj_w + (size_t)(l*2+0)*DM*DM,  dec_proj_b + (size_t)(l*2+0)*DM,
                  Y, 1, QKV, SC, AO);
        ln_k<<<NTOK,256>>>(Y, dec_ln_g + (size_t)(l*3+1)*DM, dec_ln_b + (size_t)(l*3+1)*DM, H);
        attention(H, MEMB,
                  dec_qkv_w + (size_t)(l*2+1)*3*DM*DM, dec_qkv_b + (size_t)(l*2+1)*3*DM,
                  dec_proj_w + (size_t)(l*2+1)*DM*DM,  dec_proj_b + (size_t)(l*2+1)*DM,
                  Y, 0, QKV, SC, AO);
        ln_k<<<NTOK,256>>>(Y, dec_ln_g + (size_t)(l*3+2)*DM, dec_ln_b + (size_t)(l*3+2)*DM, H);
        gemm(H,  dec_ff_w1 + (size_t)l*DM*HFF, dec_ff_b1 + (size_t)l*HFF, nullptr, FF,
             NTOK, HFF, DM, DM, HFF, HFF, 0, 1);
        gemm(FF, dec_ff_w2 + (size_t)l*HFF*DM, dec_ff_b2 + (size_t)l*DM, Y, Y,
             NTOK, DM, HFF, HFF, DM, DM, 0, 1);
    }
    ln_k<<<NTOK,256>>>(Y, dec_norm_g, dec_norm_b, H);

    // ---------------- generator + log_softmax ----------------
    gemm(H, gen_w, gen_b, nullptr, out, NTOK, NV, DM, DM, NV, NV, 0, 0);
    logsoftmax_k<<<NTOK,256>>>(out);
}

// round 4
// speedup vs baseline: 2.8112x; 1.0644x over previous
#include <cuda_runtime.h>
#include <mma.h>
#include <math.h>

using namespace nvcuda;

// ---------------- problem constants ----------------
#define DM   1024
#define NHD  16
#define DH   64
#define SEQ  1024
#define NB   2
#define NTOK 2048
#define HFF  4096
#define NV   32000
#define NLE  6
#define NLD  6

// ---------------- GEMM tile config ----------------
#define BM 128
#define BN 128
#define BK 32
#define ASTR 40
#define BSTR 136
#define SMEM_FLOATS (BM*ASTR + BK*BSTR)

// ---------------- flash attention config ----------------
#define FA_BQ  128
#define FA_BKV 128
#define QSTR 72          // 64 + 8 pad
#define SSTR 136         // 128 + 8 pad
#define FA_SMEM ((3*FA_BQ*QSTR + FA_BQ*SSTR) * 4)   // 180224 bytes

// ---------------- scratch ----------------
__device__ float g_X  [(size_t)NTOK*DM];
__device__ float g_Y  [(size_t)NTOK*DM];
__device__ float g_MEM[(size_t)NTOK*DM];
__device__ float g_H  [(size_t)NTOK*DM];
__device__ float g_QKV[(size_t)3*NTOK*DM];
__device__ float g_AO [(size_t)NTOK*DM];
__device__ float g_FF [(size_t)NTOK*HFF];

// ---------------- reductions ----------------
__device__ __forceinline__ float warpSum(float v){
#pragma unroll
    for (int o=16;o>0;o>>=1) v += __shfl_xor_sync(0xffffffffu, v, o);
    return v;
}
__device__ __forceinline__ float warpMax(float v){
#pragma unroll
    for (int o=16;o>0;o>>=1) v = fmaxf(v, __shfl_xor_sync(0xffffffffu, v, o));
    return v;
}
__device__ float blockSum(float v){
    __shared__ float sh[32];
    int lane = threadIdx.x & 31, w = threadIdx.x >> 5;
    v = warpSum(v);
    if (lane==0) sh[w] = v;
    __syncthreads();
    if (w==0){
        float r = (lane < (int)(blockDim.x>>5)) ? sh[lane] : 0.f;
        r = warpSum(r);
        if (lane==0) sh[0] = r;
    }
    __syncthreads();
    float r = sh[0];
    __syncthreads();
    return r;
}
__device__ float blockMax(float v){
    __shared__ float sh[32];
    int lane = threadIdx.x & 31, w = threadIdx.x >> 5;
    v = warpMax(v);
    if (lane==0) sh[w] = v;
    __syncthreads();
    if (w==0){
        float r = (lane < (int)(blockDim.x>>5)) ? sh[lane] : -INFINITY;
        r = warpMax(r);
        if (lane==0) sh[0] = r;
    }
    __syncthreads();
    float r = sh[0];
    __syncthreads();
    return r;
}

// ---------------- TF32 tensor-core GEMM (B row-major only) ----------------
// C[z] = act(A[z] @ B[z] + bias[z]) (+ res[z]);  M%128==0, K%32==0, N%128==0.
__global__ void __launch_bounds__(256) gemm_tc(
    const float* __restrict__ A, const float* __restrict__ B,
    const float* __restrict__ bias, const float* __restrict__ res,
    float* __restrict__ C,
    int M, int N, int K, int lda, int ldb, int ldc,
    int doGelu,
    long aob, long aoh, long bob, long boh, long biasoh,
    long cob, long coh, int nh)
{
    int z  = blockIdx.z;
    int zb = z / nh, zh = z - zb*nh;
    A += zb*aob + zh*aoh;
    B += zb*bob + zh*boh;
    C += zb*cob + zh*coh;
    if (res)  res  += zb*cob + zh*coh;
    if (bias) bias += zh*biasoh;

    __shared__ __align__(32) float sm[SMEM_FLOATS];
    float* As = sm;
    float* Bs = sm + BM*ASTR;

    int tid = threadIdx.x;
    int wid = tid >> 5;
    int wm = wid >> 2;
    int wn = wid & 3;
    long row0 = (long)blockIdx.y * BM;
    long col0 = (long)blockIdx.x * BN;

    int arow  = tid >> 3;
    int acol4 = (tid & 7) * 4;

    float4 pa[4], pb[4];

    auto fetchA = [&](int k0){
#pragma unroll
        for (int i = 0; i < 4; i++) {
            int r = arow + i*32;
            pa[i] = *(const float4*)(A + (row0 + r)*(long)lda + k0 + acol4);
        }
    };
    auto fetchB = [&](int k0){
#pragma unroll
        for (int i = 0; i < 4; i++) {
            int r  = (tid >> 5) + i*8;
            long gn = col0 + (tid & 31)*4;
            pb[i] = *(const float4*)(B + (long)(k0 + r)*ldb + gn);
        }
    };
    auto cvt4 = [](float4 v){
        v.x = wmma::__float_to_tf32(v.x);
        v.y = wmma::__float_to_tf32(v.y);
        v.z = wmma::__float_to_tf32(v.z);
        v.w = wmma::__float_to_tf32(v.w);
        return v;
    };
    auto stage = [&](){
#pragma unroll
        for (int i = 0; i < 4; i++) {
            int r = arow + i*32;
            *(float4*)(As + r*ASTR + acol4) = cvt4(pa[i]);
        }
#pragma unroll
        for (int i = 0; i < 4; i++) {
            int r = (tid >> 5) + i*8;
            int c = (tid & 31)*4;
            *(float4*)(Bs + r*BSTR + c) = cvt4(pb[i]);
        }
    };

    wmma::fragment<wmma::accumulator, 16,16,8, float> acc[4][2];
#pragma unroll
    for (int i=0;i<4;i++)
#pragma unroll
        for (int j=0;j<2;j++) wmma::fill_fragment(acc[i][j], 0.f);

    fetchA(0); fetchB(0);
    stage();
    __syncthreads();

    for (int k0 = BK; k0 <= K; k0 += BK) {
        bool more = (k0 < K);
        if (more) { fetchA(k0); fetchB(k0); }

#pragma unroll
        for (int kk = 0; kk < BK; kk += 8) {
            wmma::fragment<wmma::matrix_a, 16,16,8, wmma::precision::tf32, wmma::row_major> af[4];
            wmma::fragment<wmma::matrix_b, 16,16,8, wmma::precision::tf32, wmma::row_major> bf[2];
#pragma unroll
            for (int i=0;i<4;i++)
                wmma::load_matrix_sync(af[i], As + (wm*64 + i*16)*ASTR + kk, ASTR);
#pragma unroll
            for (int j=0;j<2;j++)
                wmma::load_matrix_sync(bf[j], Bs + kk*BSTR + wn*32 + j*16, BSTR);
#pragma unroll
            for (int i=0;i<4;i++)
#pragma unroll
                for (int j=0;j<2;j++)
                    wmma::mma_sync(acc[i][j], af[i], bf[j], acc[i][j]);
        }
        __syncthreads();
        if (more) { stage(); __syncthreads(); }
    }

    float* Cs = sm;
    for (int ph = 0; ph < 2; ph++) {
        if (wm == ph) {
#pragma unroll
            for (int i=0;i<4;i++)
#pragma unroll
                for (int j=0;j<2;j++)
                    wmma::store_matrix_sync(Cs + (i*16)*BSTR + wn*32 + j*16,
                                            acc[i][j], BSTR, wmma::mem_row_major);
        }
        __syncthreads();
#pragma unroll
        for (int it = 0; it < 8; it++) {
            int r  = (tid >> 5) + it*8;
            int cc = (tid & 31)*4;
            long gm = row0 + ph*64 + r;
            long gn = col0 + cc;
            float4 v = *(float4*)(Cs + r*BSTR + cc);
            float* vp = &v.x;
#pragma unroll
            for (int j=0;j<4;j++) {
                float x = vp[j];
                if (bias) x += bias[gn+j];
                if (doGelu) x = 0.5f*x*(1.0f + erff(x*0.70710678118654752f));
                if (res) x += res[gm*(long)ldc + gn + j];
                C[gm*(long)ldc + gn + j] = x;
            }
        }
        __syncthreads();
    }
}

// ---------------- fused flash attention (no scale, no mask — faithful) ----
// Q,K,V,O layout: [b*SEQ + s][h*DH + d], lda = DM.
// grid = (SEQ/FA_BQ, NB*NHD), 256 threads (8 warps; warp w owns rows 16w..16w+15).
__global__ void __launch_bounds__(256) flash_k(
    const float* __restrict__ Qg, const float* __restrict__ Kg,
    const float* __restrict__ Vg, float* __restrict__ Og)
{
    extern __shared__ float sm[];
    float* sQ = sm;
    float* sK = sQ + FA_BQ*QSTR;
    float* sV = sK + FA_BKV*QSTR;
    float* sS = sV + FA_BKV*QSTR;

    int tid = threadIdx.x;
    int wid = tid >> 5;
    int bh  = blockIdx.y;
    long base = ((long)(bh >> 4) * SEQ) * DM + (bh & 15) * DH;
    int q0 = blockIdx.x * FA_BQ;

    int r  = tid >> 1;              // row 0..127 (2 threads per row)
    int hc = (tid & 1);             // half-column selector

    // load Q tile (tf32-converted)
    {
        const float4* src = (const float4*)(Qg + base + (long)(q0+r)*DM + hc*32);
        float4* dst = (float4*)(sQ + r*QSTR + hc*32);
#pragma unroll
        for (int i=0;i<8;i++){
            float4 v = src[i];
            v.x = wmma::__float_to_tf32(v.x); v.y = wmma::__float_to_tf32(v.y);
            v.z = wmma::__float_to_tf32(v.z); v.w = wmma::__float_to_tf32(v.w);
            dst[i] = v;
        }
    }

    float o[32];
#pragma unroll
    for (int i=0;i<32;i++) o[i] = 0.f;
    float mrow = -INFINITY, lrow = 0.f;

    for (int j = 0; j < SEQ/FA_BKV; j++) {
        __syncthreads();   // prev iteration fully done with sK/sV
        // load K,V tiles (tf32)
        {
            long kbase = base + (long)(j*FA_BKV + r)*DM + hc*32;
            const float4* ks = (const float4*)(Kg + kbase);
            const float4* vs = (const float4*)(Vg + kbase);
            float4* kd = (float4*)(sK + r*QSTR + hc*32);
            float4* vd = (float4*)(sV + r*QSTR + hc*32);
#pragma unroll
            for (int i=0;i<8;i++){
                float4 a = ks[i], b = vs[i];
                a.x=wmma::__float_to_tf32(a.x); a.y=wmma::__float_to_tf32(a.y);
                a.z=wmma::__float_to_tf32(a.z); a.w=wmma::__float_to_tf32(a.w);
                b.x=wmma::__float_to_tf32(b.x); b.y=wmma::__float_to_tf32(b.y);
                b.z=wmma::__float_to_tf32(b.z); b.w=wmma::__float_to_tf32(b.w);
                kd[i] = a; vd[i] = b;
            }
        }
        __syncthreads();

        // S band = Q band @ K^T   (16 x 128, K-depth 64)
        {
            wmma::fragment<wmma::accumulator,16,16,8,float> acc[8];
#pragma unroll
            for (int n=0;n<8;n++) wmma::fill_fragment(acc[n], 0.f);
#pragma unroll
            for (int kk=0; kk<DH; kk+=8) {
                wmma::fragment<wmma::matrix_a,16,16,8,wmma::precision::tf32,wmma::row_major> af;
                wmma::load_matrix_sync(af, sQ + (wid*16)*QSTR + kk, QSTR);
#pragma unroll
                for (int n=0;n<8;n++) {
                    wmma::fragment<wmma::matrix_b,16,16,8,wmma::precision::tf32,wmma::col_major> bf;
                    wmma::load_matrix_sync(bf, sK + (n*16)*QSTR + kk, QSTR);
                    wmma::mma_sync(acc[n], af, bf, acc[n]);
                }
            }
#pragma unroll
            for (int n=0;n<8;n++)
                wmma::store_matrix_sync(sS + (wid*16)*SSTR + n*16, acc[n], SSTR, wmma::mem_row_major);
        }
        __syncwarp();

        // online softmax on own row (2 threads/row, 64 cols each)
        {
            float* srow = sS + r*SSTR + hc*64;
            float tmax = -INFINITY;
#pragma unroll
            for (int c=0;c<64;c++) tmax = fmaxf(tmax, srow[c]);
            tmax = fmaxf(tmax, __shfl_xor_sync(0xffffffffu, tmax, 1));
            float mnew = fmaxf(mrow, tmax);
            float alpha = __expf(mrow - mnew);
            float tsum = 0.f;
#pragma unroll
            for (int c=0;c<64;c++) {
                float p = __expf(srow[c] - mnew);
                tsum += p;
                srow[c] = wmma::__float_to_tf32(p);
            }
            tsum += __shfl_xor_sync(0xffffffffu, tsum, 1);
            lrow = lrow*alpha + tsum;
            mrow = mnew;
#pragma unroll
            for (int i=0;i<32;i++) o[i] *= alpha;
        }
        __syncwarp();

        // O band += P band (16x128) @ V (128x64)
        {
            wmma::fragment<wmma::accumulator,16,16,8,float> acc[4];
#pragma unroll
            for (int n=0;n<4;n++) wmma::fill_fragment(acc[n], 0.f);
#pragma unroll
            for (int kk=0; kk<FA_BKV; kk+=8) {
                wmma::fragment<wmma::matrix_a,16,16,8,wmma::precision::tf32,wmma::row_major> af;
                wmma::load_matrix_sync(af, sS + (wid*16)*SSTR + kk, SSTR);
#pragma unroll
                for (int n=0;n<4;n++) {
                    wmma::fragment<wmma::matrix_b,16,16,8,wmma::precision::tf32,wmma::row_major> bf;
                    wmma::load_matrix_sync(bf, sV + kk*QSTR + n*16, QSTR);
                    wmma::mma_sync(acc[n], af, bf, acc[n]);
                }
            }
#pragma unroll
            for (int n=0;n<4;n++)
                wmma::store_matrix_sync(sS + (wid*16)*SSTR + n*16, acc[n], SSTR, wmma::mem_row_major);
        }
        __syncwarp();
        {
            float* prow = sS + r*SSTR + hc*32;
#pragma unroll
            for (int i=0;i<32;i++) o[i] += prow[i];
        }
    }

    // finalize + store
    float inv = 1.0f / lrow;
    float4* dst = (float4*)(Og + base + (long)(q0+r)*DM + hc*32);
#pragma unroll
    for (int i=0;i<8;i++) {
        float4 v;
        v.x = o[i*4+0]*inv; v.y = o[i*4+1]*inv;
        v.z = o[i*4+2]*inv; v.w = o[i*4+3]*inv;
        dst[i] = v;
    }
}

// ---------------- embedding + positional encoding ----------------
__global__ void embed_k(const int* __restrict__ tok, const float* __restrict__ emb,
                        float* __restrict__ out)
{
    int t = blockIdx.x;
    int s = t & (SEQ-1);
    int id = tok[t];
    const float* e = emb + (long)id*DM;
    float* o = out + (long)t*DM;
    const float c = -logf(10000.0f) / (float)DM;
    for (int d = threadIdx.x; d < DM; d += blockDim.x) {
        int i2 = d & ~1;
        float ang = (float)s * expf((float)i2 * c);
        float pe = (d & 1) ? cosf(ang) : sinf(ang);
        o[d] = e[d]*32.0f + pe;
    }
}

// ---------------- LayerNorm ----------------
__global__ void ln_k(const float* __restrict__ x, const float* __restrict__ g,
                     const float* __restrict__ b, float* __restrict__ out)
{
    long t = blockIdx.x;
    const float4* xr = (const float4*)(x + t*DM);
    float4* o = (float4*)(out + t*DM);
    float4 v = xr[threadIdx.x];
    float s  = v.x+v.y+v.z+v.w;
    float ss = v.x*v.x+v.y*v.y+v.z*v.z+v.w*v.w;
    s  = blockSum(s);
    ss = blockSum(ss);
    float mean = s * (1.0f/DM);
    float var  = ss * (1.0f/DM) - mean*mean;
    float inv  = rsqrtf(var + 1e-5f);
    float4 gg = ((const float4*)g)[threadIdx.x];
    float4 bb = ((const float4*)b)[threadIdx.x];
    float4 r;
    r.x = (v.x-mean)*inv*gg.x + bb.x;
    r.y = (v.y-mean)*inv*gg.y + bb.y;
    r.z = (v.z-mean)*inv*gg.z + bb.z;
    r.w = (v.w-mean)*inv*gg.w + bb.w;
    o[threadIdx.x] = r;
}

// ---------------- log_softmax over NV ----------------
__global__ void logsoftmax_k(float* __restrict__ p)
{
    float* r = p + (long)blockIdx.x * NV;
    float mx = -INFINITY;
    for (int d = threadIdx.x; d < NV; d += blockDim.x) mx = fmaxf(mx, r[d]);
    mx = blockMax(mx);
    float sum = 0.f;
    for (int d = threadIdx.x; d < NV; d += blockDim.x) sum += __expf(r[d]-mx);
    sum = blockSum(sum);
    float lse = mx + logf(sum);
    for (int d = threadIdx.x; d < NV; d += blockDim.x) r[d] -= lse;
}

// ---------------- host helpers ----------------
static void gemm(const float* A, const float* B, const float* bias, const float* res,
                 float* C, int M, int N, int K, int lda, int ldb, int ldc,
                 int gelu,
                 long aob=0, long aoh=0, long bob=0, long boh=0, long biasoh=0,
                 long cob=0, long coh=0, int nh=1, int nz=1)
{
    dim3 grid(N/BN, M/BM, nz);
    gemm_tc<<<grid, 256>>>(A,B,bias,res,C,M,N,K,lda,ldb,ldc,gelu,
                           aob,aoh,bob,boh,biasoh,cob,coh,nh);
}

static void attention(const float* Hq, const float* Hkv,
                      const float* wqkv, const float* bqkv,
                      const float* wproj, const float* bproj,
                      float* x, int sameKV,
                      float* QKV, float* AO)
{
    float* Q  = QKV;
    float* Kb = QKV + (size_t)NTOK*DM;
    float* Vb = QKV + (size_t)2*NTOK*DM;
    if (sameKV) {
        gemm(Hq, wqkv, bqkv, nullptr, QKV, NTOK, DM, DM, DM, DM, DM, 0,
             0, 0, 0, (long)DM*DM, DM, 0, (long)NTOK*DM, 3, 3);
    } else {
        gemm(Hq, wqkv, bqkv, nullptr, Q, NTOK, DM, DM, DM, DM, DM, 0);
        gemm(Hkv, wqkv + (size_t)DM*DM, bqkv + DM, nullptr, Kb,
             NTOK, DM, DM, DM, DM, DM, 0,
             0, 0, 0, (long)DM*DM, DM, 0, (long)NTOK*DM, 2, 2);
    }
    dim3 fgrid(SEQ/FA_BQ, NB*NHD);
    flash_k<<<fgrid, 256, FA_SMEM>>>(Q, Kb, Vb, AO);
    gemm(AO, wproj, bproj, x, x, NTOK, DM, DM, DM, DM, DM, 0);
}

extern "C" void kernel_launch(void* const* d_in, const int* in_sizes, int n_in,
                              void* d_out, int out_size)
{
    const int*   src        = (const int*)  d_in[0];
    const int*   tgt        = (const int*)  d_in[1];
    const float* emb        = (const float*)d_in[5];
    const float* enc_qkv_w  = (const float*)d_in[6];
    const float* enc_qkv_b  = (const float*)d_in[7];
    const float* enc_proj_w = (const float*)d_in[8];
    const float* enc_proj_b = (const float*)d_in[9];
    const float* enc_ff_w1  = (const float*)d_in[10];
    const float* enc_ff_b1  = (const float*)d_in[11];
    const float* enc_ff_w2  = (const float*)d_in[12];
    const float* enc_ff_b2  = (const float*)d_in[13];
    const float* enc_ln_g   = (const float*)d_in[14];
    const float* enc_ln_b   = (const float*)d_in[15];
    const float* enc_norm_g = (const float*)d_in[16];
    const float* enc_norm_b = (const float*)d_in[17];
    const float* dec_qkv_w  = (const float*)d_in[18];
    const float* dec_qkv_b  = (const float*)d_in[19];
    const float* dec_proj_w = (const float*)d_in[20];
    const float* dec_proj_b = (const float*)d_in[21];
    const float* dec_ff_w1  = (const float*)d_in[22];
    const float* dec_ff_b1  = (const float*)d_in[23];
    const float* dec_ff_w2  = (const float*)d_in[24];
    const float* dec_ff_b2  = (const float*)d_in[25];
    const float* dec_ln_g   = (const float*)d_in[26];
    const float* dec_ln_b   = (const float*)d_in[27];
    const float* dec_norm_g = (const float*)d_in[28];
    const float* dec_norm_b = (const float*)d_in[29];
    const float* gen_w      = (const float*)d_in[30];
    const float* gen_b      = (const float*)d_in[31];
    float* out = (float*)d_out;

    cudaFuncSetAttribute(flash_k, cudaFuncAttributeMaxDynamicSharedMemorySize, FA_SMEM);

    float *X,*Y,*MEMB,*H,*QKV,*AO,*FF;
    cudaGetSymbolAddress((void**)&X,   g_X);
    cudaGetSymbolAddress((void**)&Y,   g_Y);
    cudaGetSymbolAddress((void**)&MEMB,g_MEM);
    cudaGetSymbolAddress((void**)&H,   g_H);
    cudaGetSymbolAddress((void**)&QKV, g_QKV);
    cudaGetSymbolAddress((void**)&AO,  g_AO);
    cudaGetSymbolAddress((void**)&FF,  g_FF);

    // ---------------- encoder ----------------
    embed_k<<<NTOK,256>>>(src, emb, X);
    for (int l = 0; l < NLE; l++) {
        ln_k<<<NTOK,256>>>(X, enc_ln_g + (size_t)(l*2+0)*DM, enc_ln_b + (size_t)(l*2+0)*DM, H);
        attention(H, H,
                  enc_qkv_w + (size_t)l*3*DM*DM, enc_qkv_b + (size_t)l*3*DM,
                  enc_proj_w + (size_t)l*DM*DM,  enc_proj_b + (size_t)l*DM,
                  X, 1, QKV, AO);
        ln_k<<<NTOK,256>>>(X, enc_ln_g + (size_t)(l*2+1)*DM, enc_ln_b + (size_t)(l*2+1)*DM, H);
        gemm(H,  enc_ff_w1 + (size_t)l*DM*HFF, enc_ff_b1 + (size_t)l*HFF, nullptr, FF,
             NTOK, HFF, DM, DM, HFF, HFF, 1);
        gemm(FF, enc_ff_w2 + (size_t)l*HFF*DM, enc_ff_b2 + (size_t)l*DM, X, X,
             NTOK, DM, HFF, HFF, DM, DM, 1);
    }
    ln_k<<<NTOK,256>>>(X, enc_norm_g, enc_norm_b, MEMB);

    // ---------------- decoder ----------------
    embed_k<<<NTOK,256>>>(tgt, emb, Y);
    for (int l = 0; l < NLD; l++) {
        ln_k<<<NTOK,256>>>(Y, dec_ln_g + (size_t)(l*3+0)*DM, dec_ln_b + (size_t)(l*3+0)*DM, H);
        attention(H, H,
                  dec_qkv_w + (size_t)(l*2+0)*3*DM*DM, dec_qkv_b + (size_t)(l*2+0)*3*DM,
                  dec_proj_w + (size_t)(l*2+0)*DM*DM,  dec_proj_b + (size_t)(l*2+0)*DM,
                  Y, 1, QKV, AO);
        ln_k<<<NTOK,256>>>(Y, dec_ln_g + (size_t)(l*3+1)*DM, dec_ln_b + (size_t)(l*3+1)*DM, H);
        attention(H, MEMB,
                  dec_qkv_w + (size_t)(l*2+1)*3*DM*DM, dec_qkv_b + (size_t)(l*2+1)*3*DM,
                  dec_proj_w + (size_t)(l*2+1)*DM*DM,  dec_proj_b + (size_t)(l*2+1)*DM,
                  Y, 0, QKV, AO);
        ln_k<<<NTOK,256>>>(Y, dec_ln_g + (size_t)(l*3+2)*DM, dec_ln_b + (size_t)(l*3+2)*DM, H);
        gemm(H,  dec_ff_w1 + (size_t)l*DM*HFF, dec_ff_b1 + (size_t)l*HFF, nullptr, FF,
             NTOK, HFF, DM, DM, HFF, HFF, 1);
        gemm(FF, dec_ff_w2 + (size_t)l*HFF*DM, dec_ff_b2 + (size_t)l*DM, Y, Y,
             NTOK, DM, HFF, HFF, DM, DM, 1);
    }
    ln_k<<<NTOK,256>>>(Y, dec_norm_g, dec_norm_b, H);

    // ---------------- generator + log_softmax ----------------
    gemm(H, gen_w, gen_b, nullptr, out, NTOK, NV/BN*BN == NV ? NV : NV, DM, DM, NV, NV, 0);
    logsoftmax_k<<<NTOK,256>>>(out);
}

// round 5
// speedup vs baseline: 5.5142x; 1.9615x over previous
#include <cuda_runtime.h>
#include <cuda_bf16.h>
#include <mma.h>
#include <math.h>

using namespace nvcuda;

// ---------------- problem constants ----------------
#define DM   1024
#define NHD  16
#define DH   64
#define SEQ  1024
#define NB   2
#define NTOK 2048
#define HFF  4096
#define NV   32000
#define NLE  6
#define NLD  6

// ---------------- GEMM tile config ----------------
#define BM 128
#define BN 128
#define BK 32
#define ASTRH 40     // bf16 elems per A row (80B, 16B-mult)
#define BSTRH 136    // bf16 elems per B row (272B, 16B-mult)
#define CSTRF 136    // f32 epilogue stage stride
#define GEMM_SMEM_BYTES 37888

// ---------------- flash attention config ----------------
#define FA_BQ  128
#define FA_BKV 128
#define QSTRH 72     // bf16 (144B rows)
#define SSTR  136    // f32
#define PSTR  136    // bf16
#define FA_SMEM 196608

// ---------------- scratch ----------------
__device__ float g_X  [(size_t)NTOK*DM];
__device__ float g_Y  [(size_t)NTOK*DM];
__device__ float g_MEM[(size_t)NTOK*DM];
__device__ float g_H  [(size_t)NTOK*DM];
__device__ float g_QKV[(size_t)3*NTOK*DM];
__device__ float g_AO [(size_t)NTOK*DM];
__device__ float g_FF [(size_t)NTOK*HFF];

// ---------------- helpers ----------------
__device__ __forceinline__ void st_bf4(__nv_bfloat16* p, float4 v){
    *(__nv_bfloat162*)(p)   = __floats2bfloat162_rn(v.x, v.y);
    *(__nv_bfloat162*)(p+2) = __floats2bfloat162_rn(v.z, v.w);
}
__device__ __forceinline__ float warpSum(float v){
#pragma unroll
    for (int o=16;o>0;o>>=1) v += __shfl_xor_sync(0xffffffffu, v, o);
    return v;
}
__device__ __forceinline__ float warpMax(float v){
#pragma unroll
    for (int o=16;o>0;o>>=1) v = fmaxf(v, __shfl_xor_sync(0xffffffffu, v, o));
    return v;
}
__device__ float blockSum(float v){
    __shared__ float sh[32];
    int lane = threadIdx.x & 31, w = threadIdx.x >> 5;
    v = warpSum(v);
    if (lane==0) sh[w] = v;
    __syncthreads();
    if (w==0){
        float r = (lane < (int)(blockDim.x>>5)) ? sh[lane] : 0.f;
        r = warpSum(r);
        if (lane==0) sh[0] = r;
    }
    __syncthreads();
    float r = sh[0];
    __syncthreads();
    return r;
}
__device__ float blockMax(float v){
    __shared__ float sh[32];
    int lane = threadIdx.x & 31, w = threadIdx.x >> 5;
    v = warpMax(v);
    if (lane==0) sh[w] = v;
    __syncthreads();
    if (w==0){
        float r = (lane < (int)(blockDim.x>>5)) ? sh[lane] : -INFINITY;
        r = warpMax(r);
        if (lane==0) sh[0] = r;
    }
    __syncthreads();
    float r = sh[0];
    __syncthreads();
    return r;
}

// ---------------- bf16 tensor-core GEMM (B row-major) ----------------
__global__ void __launch_bounds__(256) gemm_bf(
    const float* __restrict__ A, const float* __restrict__ B,
    const float* __restrict__ bias, const float* __restrict__ res,
    float* __restrict__ C,
    int M, int N, int K, int lda, int ldb, int ldc,
    int doGelu,
    long aob, long aoh, long bob, long boh, long biasoh,
    long cob, long coh, int nh)
{
    int z  = blockIdx.z;
    int zb = z / nh, zh = z - zb*nh;
    A += zb*aob + zh*aoh;
    B += zb*bob + zh*boh;
    C += zb*cob + zh*coh;
    if (res)  res  += zb*cob + zh*coh;
    if (bias) bias += zh*biasoh;

    __shared__ __align__(16) unsigned char smraw[GEMM_SMEM_BYTES];
    __nv_bfloat16* As = (__nv_bfloat16*)smraw;
    __nv_bfloat16* Bs = As + 2*BM*ASTRH;
    float* Cs = (float*)smraw;

    int tid = threadIdx.x;
    int wid = tid >> 5;
    int wm = wid >> 2;
    int wn = wid & 3;
    long row0 = (long)blockIdx.y * BM;
    long col0 = (long)blockIdx.x * BN;

    int arow  = tid >> 3;
    int acol4 = (tid & 7) * 4;

    float4 pa[4], pb[4];

    auto fetchA = [&](int k0){
#pragma unroll
        for (int i = 0; i < 4; i++) {
            int r = arow + i*32;
            pa[i] = *(const float4*)(A + (row0 + r)*(long)lda + k0 + acol4);
        }
    };
    auto fetchB = [&](int k0){
#pragma unroll
        for (int i = 0; i < 4; i++) {
            int r  = (tid >> 5) + i*8;
            long gn = col0 + (tid & 31)*4;
            pb[i] = *(const float4*)(B + (long)(k0 + r)*ldb + gn);
        }
    };
    auto stage = [&](int buf){
        __nv_bfloat16* ad = As + buf*BM*ASTRH;
        __nv_bfloat16* bd = Bs + buf*BK*BSTRH;
#pragma unroll
        for (int i = 0; i < 4; i++) {
            int r = arow + i*32;
            st_bf4(ad + r*ASTRH + acol4, pa[i]);
        }
#pragma unroll
        for (int i = 0; i < 4; i++) {
            int r = (tid >> 5) + i*8;
            int c = (tid & 31)*4;
            st_bf4(bd + r*BSTRH + c, pb[i]);
        }
    };

    wmma::fragment<wmma::accumulator, 16,16,16, float> acc[4][2];
#pragma unroll
    for (int i=0;i<4;i++)
#pragma unroll
        for (int j=0;j<2;j++) wmma::fill_fragment(acc[i][j], 0.f);

    auto domma = [&](int buf){
        __nv_bfloat16* as = As + buf*BM*ASTRH;
        __nv_bfloat16* bs = Bs + buf*BK*BSTRH;
#pragma unroll
        for (int kk = 0; kk < BK; kk += 16) {
            wmma::fragment<wmma::matrix_a, 16,16,16, __nv_bfloat16, wmma::row_major> af[4];
            wmma::fragment<wmma::matrix_b, 16,16,16, __nv_bfloat16, wmma::row_major> bf[2];
#pragma unroll
            for (int i=0;i<4;i++)
                wmma::load_matrix_sync(af[i], as + (wm*64 + i*16)*ASTRH + kk, ASTRH);
#pragma unroll
            for (int j=0;j<2;j++)
                wmma::load_matrix_sync(bf[j], bs + kk*BSTRH + wn*32 + j*16, BSTRH);
#pragma unroll
            for (int i=0;i<4;i++)
#pragma unroll
                for (int j=0;j<2;j++)
                    wmma::mma_sync(acc[i][j], af[i], bf[j], acc[i][j]);
        }
    };

    int cur = 0;
    fetchA(0); fetchB(0);
    stage(cur);
    __syncthreads();

    for (int k0 = BK; k0 <= K; k0 += BK) {
        bool more = (k0 < K);
        if (more) { fetchA(k0); fetchB(k0); }
        domma(cur);
        if (more) {
            stage(cur ^ 1);
            __syncthreads();
            cur ^= 1;
        }
    }
    __syncthreads();

    for (int ph = 0; ph < 2; ph++) {
        if (wm == ph) {
#pragma unroll
            for (int i=0;i<4;i++)
#pragma unroll
                for (int j=0;j<2;j++)
                    wmma::store_matrix_sync(Cs + (i*16)*CSTRF + wn*32 + j*16,
                                            acc[i][j], CSTRF, wmma::mem_row_major);
        }
        __syncthreads();
#pragma unroll
        for (int it = 0; it < 8; it++) {
            int r  = (tid >> 5) + it*8;
            int cc = (tid & 31)*4;
            long gm = row0 + ph*64 + r;
            long gn = col0 + cc;
            float4 v = *(float4*)(Cs + r*CSTRF + cc);
            float* vp = &v.x;
#pragma unroll
            for (int j=0;j<4;j++) {
                float x = vp[j];
                if (bias) x += bias[gn+j];
                if (doGelu) x = 0.5f*x*(1.0f + erff(x*0.70710678118654752f));
                if (res) x += res[gm*(long)ldc + gn + j];
                C[gm*(long)ldc + gn + j] = x;
            }
        }
        __syncthreads();
    }
}

// ---------------- fused flash attention (bf16 MMA) ----------------
__global__ void __launch_bounds__(256) flash_k(
    const float* __restrict__ Qg, const float* __restrict__ Kg,
    const float* __restrict__ Vg, float* __restrict__ Og)
{
    extern __shared__ float smf[];
    float* sS = smf;
    __nv_bfloat16* sQ = (__nv_bfloat16*)(sS + FA_BQ*SSTR);
    __nv_bfloat16* sK = sQ + FA_BQ*QSTRH;
    __nv_bfloat16* sV = sK + 2*FA_BKV*QSTRH;
    __nv_bfloat16* sP = sV + 2*FA_BKV*QSTRH;

    int tid = threadIdx.x;
    int wid = tid >> 5;
    int bh  = blockIdx.y;
    long base = ((long)(bh >> 4) * SEQ) * DM + (bh & 15) * DH;
    int q0 = blockIdx.x * FA_BQ;

    int r  = tid >> 1;
    int hc = (tid & 1);

    float4 rr[8];

    auto fetchKV = [&](const float* G, int jj){
        long kb = base + (long)(jj*FA_BKV + r)*DM + hc*32;
        const float4* s = (const float4*)(G + kb);
#pragma unroll
        for (int i=0;i<8;i++) rr[i] = s[i];
    };
    auto stageKV = [&](__nv_bfloat16* dstbase){
        __nv_bfloat16* d = dstbase + r*QSTRH + hc*32;
#pragma unroll
        for (int i=0;i<8;i++) st_bf4(d + i*4, rr[i]);
    };

    {
        const float4* src = (const float4*)(Qg + base + (long)(q0+r)*DM + hc*32);
        __nv_bfloat16* d = sQ + r*QSTRH + hc*32;
#pragma unroll
        for (int i=0;i<8;i++) st_bf4(d + i*4, src[i]);
    }

    float o[32];
#pragma unroll
    for (int i=0;i<32;i++) o[i] = 0.f;
    float mrow = -INFINITY, lrow = 0.f;

    fetchKV(Kg, 0); stageKV(sK);
    fetchKV(Vg, 0); stageKV(sV);
    __syncthreads();

    const int NKV = SEQ/FA_BKV;
    int cur = 0;
    for (int j = 0; j < NKV; j++) {
        bool more = (j+1 < NKV);
        __nv_bfloat16* kc = sK + cur*FA_BKV*QSTRH;
        __nv_bfloat16* vc = sV + cur*FA_BKV*QSTRH;
        int nxt = cur ^ 1;

        {
            wmma::fragment<wmma::accumulator,16,16,16,float> acc[8];
#pragma unroll
            for (int n=0;n<8;n++) wmma::fill_fragment(acc[n], 0.f);
#pragma unroll
            for (int kk=0; kk<DH; kk+=16) {
                wmma::fragment<wmma::matrix_a,16,16,16,__nv_bfloat16,wmma::row_major> af;
                wmma::load_matrix_sync(af, sQ + (wid*16)*QSTRH + kk, QSTRH);
#pragma unroll
                for (int n=0;n<8;n++) {
                    wmma::fragment<wmma::matrix_b,16,16,16,__nv_bfloat16,wmma::col_major> bf;
                    wmma::load_matrix_sync(bf, kc + (n*16)*QSTRH + kk, QSTRH);
                    wmma::mma_sync(acc[n], af, bf, acc[n]);
                }
            }
#pragma unroll
            for (int n=0;n<8;n++)
                wmma::store_matrix_sync(sS + (wid*16)*SSTR + n*16, acc[n], SSTR, wmma::mem_row_major);
        }
        if (more) { fetchKV(Kg, j+1); stageKV(sK + nxt*FA_BKV*QSTRH); }
        __syncwarp();

        {
            float* srow = sS + r*SSTR + hc*64;
            __nv_bfloat16* prow = sP + r*PSTR + hc*64;
            float tmax = -INFINITY;
#pragma unroll
            for (int c=0;c<64;c++) tmax = fmaxf(tmax, srow[c]);
            tmax = fmaxf(tmax, __shfl_xor_sync(0xffffffffu, tmax, 1));
            float mnew = fmaxf(mrow, tmax);
            float alpha = __expf(mrow - mnew);
            float tsum = 0.f;
#pragma unroll
            for (int c=0;c<64;c++) {
                float p = __expf(srow[c] - mnew);
                tsum += p;
                prow[c] = __float2bfloat16(p);
            }
            tsum += __shfl_xor_sync(0xffffffffu, tsum, 1);
            lrow = lrow*alpha + tsum;
            mrow = mnew;
#pragma unroll
            for (int i=0;i<32;i++) o[i] *= alpha;
        }
        if (more) fetchKV(Vg, j+1);
        __syncwarp();

        {
            wmma::fragment<wmma::accumulator,16,16,16,float> acc[4];
#pragma unroll
            for (int n=0;n<4;n++) wmma::fill_fragment(acc[n], 0.f);
#pragma unroll
            for (int kk=0; kk<FA_BKV; kk+=16) {
                wmma::fragment<wmma::matrix_a,16,16,16,__nv_bfloat16,wmma::row_major> af;
                wmma::load_matrix_sync(af, sP + (wid*16)*PSTR + kk, PSTR);
#pragma unroll
                for (int n=0;n<4;n++) {
                    wmma::fragment<wmma::matrix_b,16,16,16,__nv_bfloat16,wmma::row_major> bf;
                    wmma::load_matrix_sync(bf, vc + kk*QSTRH + n*16, QSTRH);
                    wmma::mma_sync(acc[n], af, bf, acc[n]);
                }
            }
#pragma unroll
            for (int n=0;n<4;n++)
                wmma::store_matrix_sync(sS + (wid*16)*SSTR + n*16, acc[n], SSTR, wmma::mem_row_major);
        }
        __syncwarp();
        {
            float* orow = sS + r*SSTR + hc*32;
#pragma unroll
            for (int i=0;i<32;i++) o[i] += orow[i];
        }
        if (more) stageKV(sV + nxt*FA_BKV*QSTRH);
        __syncthreads();
        cur = nxt;
    }

    float inv = 1.0f / lrow;
    float4* dst = (float4*)(Og + base + (long)(q0+r)*DM + hc*32);
#pragma unroll
    for (int i=0;i<8;i++) {
        float4 v;
        v.x = o[i*4+0]*inv; v.y = o[i*4+1]*inv;
        v.z = o[i*4+2]*inv; v.w = o[i*4+3]*inv;
        dst[i] = v;
    }
}

// ---------------- embedding + positional encoding ----------------
__global__ void embed_k(const int* __restrict__ tok, const float* __restrict__ emb,
                        float* __restrict__ out)
{
    int t = blockIdx.x;
    int s = t & (SEQ-1);
    int id = tok[t];
    const float* e = emb + (long)id*DM;
    float* o = out + (long)t*DM;
    const float c = -logf(10000.0f) / (float)DM;
    for (int d = threadIdx.x; d < DM; d += blockDim.x) {
        int i2 = d & ~1;
        float ang = (float)s * expf((float)i2 * c);
        float pe = (d & 1) ? cosf(ang) : sinf(ang);
        o[d] = e[d]*32.0f + pe;
    }
}

// ---------------- LayerNorm ----------------
__global__ void ln_k(const float* __restrict__ x, const float* __restrict__ g,
                     const float* __restrict__ b, float* __restrict__ out)
{
    long t = blockIdx.x;
    const float4* xr = (const float4*)(x + t*DM);
    float4* o = (float4*)(out + t*DM);
    float4 v = xr[threadIdx.x];
    float s  = v.x+v.y+v.z+v.w;
    float ss = v.x*v.x+v.y*v.y+v.z*v.z+v.w*v.w;
    s  = blockSum(s);
    ss = blockSum(ss);
    float mean = s * (1.0f/DM);
    float var  = ss * (1.0f/DM) - mean*mean;
    float inv  = rsqrtf(var + 1e-5f);
    float4 gg = ((const float4*)g)[threadIdx.x];
    float4 bb = ((const float4*)b)[threadIdx.x];
    float4 rr;
    rr.x = (v.x-mean)*inv*gg.x + bb.x;
    rr.y = (v.y-mean)*inv*gg.y + bb.y;
    rr.z = (v.z-mean)*inv*gg.z + bb.z;
    rr.w = (v.w-mean)*inv*gg.w + bb.w;
    o[threadIdx.x] = rr;
}

// ---------------- log_softmax over NV ----------------
__global__ void logsoftmax_k(float* __restrict__ p)
{
    float* r = p + (long)blockIdx.x * NV;
    float mx = -INFINITY;
    for (int d = threadIdx.x; d < NV; d += blockDim.x) mx = fmaxf(mx, r[d]);
    mx = blockMax(mx);
    float sum = 0.f;
    for (int d = threadIdx.x; d < NV; d += blockDim.x) sum += __expf(r[d]-mx);
    sum = blockSum(sum);
    float lse = mx + logf(sum);
    for (int d = threadIdx.x; d < NV; d += blockDim.x) r[d] -= lse;
}

// ---------------- host helpers ----------------
static void gemm(const float* A, const float* B, const float* bias, const float* res,
                 float* C, int M, int N, int K, int lda, int ldb, int ldc,
                 int gelu,
                 long aob=0, long aoh=0, long bob=0, long boh=0, long biasoh=0,
                 long cob=0, long coh=0, int nh=1, int nz=1)
{
    dim3 grid(N/BN, M/BM, nz);
    gemm_bf<<<grid, 256>>>(A,B,bias,res,C,M,N,K,lda,ldb,ldc,gelu,
                           aob,aoh,bob,boh,biasoh,cob,coh,nh);
}

static void attention(const float* Hq, const float* Hkv,
                      const float* wqkv, const float* bqkv,
                      const float* wproj, const float* bproj,
                      float* x, int sameKV,
                      float* QKV, float* AO)
{
    float* Q  = QKV;
    float* Kb = QKV + (size_t)NTOK*DM;
    float* Vb = QKV + (size_t)2*NTOK*DM;
    if (sameKV) {
        gemm(Hq, wqkv, bqkv, nullptr, QKV, NTOK, DM, DM, DM, DM, DM, 0,
             0, 0, 0, (long)DM*DM, DM, 0, (long)NTOK*DM, 3, 3);
    } else {
        gemm(Hq, wqkv, bqkv, nullptr, Q, NTOK, DM, DM, DM, DM, DM, 0);
        gemm(Hkv, wqkv + (size_t)DM*DM, bqkv + DM, nullptr, Kb,
             NTOK, DM, DM, DM, DM, DM, 0,
             0, 0, 0, (long)DM*DM, DM, 0, (long)NTOK*DM, 2, 2);
    }
    dim3 fgrid(SEQ/FA_BQ, NB*NHD);
    flash_k<<<fgrid, 256, FA_SMEM>>>(Q, Kb, Vb, AO);
    gemm(AO, wproj, bproj, x, x, NTOK, DM, DM, DM, DM, DM, 0);
}

extern "C" void kernel_launch(void* const* d_in, const int* in_sizes, int n_in,
                              void* d_out, int out_size)
{
    const int*   src        = (const int*)  d_in[0];
    const int*   tgt        = (const int*)  d_in[1];
    const float* emb        = (const float*)d_in[5];
    const float* enc_qkv_w  = (const float*)d_in[6];
    const float* enc_qkv_b  = (const float*)d_in[7];
    const float* enc_proj_w = (const float*)d_in[8];
    const float* enc_proj_b = (const float*)d_in[9];
    const float* enc_ff_w1  = (const float*)d_in[10];
    const float* enc_ff_b1  = (const float*)d_in[11];
    const float* enc_ff_w2  = (const float*)d_in[12];
    const float* enc_ff_b2  = (const float*)d_in[13];
    const float* enc_ln_g   = (const float*)d_in[14];
    const float* enc_ln_b   = (const float*)d_in[15];
    const float* enc_norm_g = (const float*)d_in[16];
    const float* enc_norm_b = (const float*)d_in[17];
    const float* dec_qkv_w  = (const float*)d_in[18];
    const float* dec_qkv_b  = (const float*)d_in[19];
    const float* dec_proj_w = (const float*)d_in[20];
    const float* dec_proj_b = (const float*)d_in[21];
    const float* dec_ff_w1  = (const float*)d_in[22];
    const float* dec_ff_b1  = (const float*)d_in[23];
    const float* dec_ff_w2  = (const float*)d_in[24];
    const float* dec_ff_b2  = (const float*)d_in[25];
    const float* dec_ln_g   = (const float*)d_in[26];
    const float* dec_ln_b   = (const float*)d_in[27];
    const float* dec_norm_g = (const float*)d_in[28];
    const float* dec_norm_b = (const float*)d_in[29];
    const float* gen_w      = (const float*)d_in[30];
    const float* gen_b      = (const float*)d_in[31];
    float* out = (float*)d_out;

    cudaFuncSetAttribute(flash_k, cudaFuncAttributeMaxDynamicSharedMemorySize, FA_SMEM);

    float *X,*Y,*MEMB,*H,*QKV,*AO,*FF;
    cudaGetSymbolAddress((void**)&X,   g_X);
    cudaGetSymbolAddress((void**)&Y,   g_Y);
    cudaGetSymbolAddress((void**)&MEMB,g_MEM);
    cudaGetSymbolAddress((void**)&H,   g_H);
    cudaGetSymbolAddress((void**)&QKV, g_QKV);
    cudaGetSymbolAddress((void**)&AO,  g_AO);
    cudaGetSymbolAddress((void**)&FF,  g_FF);

    // ---------------- encoder ----------------
    embed_k<<<NTOK,256>>>(src, emb, X);
    for (int l = 0; l < NLE; l++) {
        ln_k<<<NTOK,256>>>(X, enc_ln_g + (size_t)(l*2+0)*DM, enc_ln_b + (size_t)(l*2+0)*DM, H);
        attention(H, H,
                  enc_qkv_w + (size_t)l*3*DM*DM, enc_qkv_b + (size_t)l*3*DM,
                  enc_proj_w + (size_t)l*DM*DM,  enc_proj_b + (size_t)l*DM,
                  X, 1, QKV, AO);
        ln_k<<<NTOK,256>>>(X, enc_ln_g + (size_t)(l*2+1)*DM, enc_ln_b + (size_t)(l*2+1)*DM, H);
        gemm(H,  enc_ff_w1 + (size_t)l*DM*HFF, enc_ff_b1 + (size_t)l*HFF, nullptr, FF,
             NTOK, HFF, DM, DM, HFF, HFF, 1);
        gemm(FF, enc_ff_w2 + (size_t)l*HFF*DM, enc_ff_b2 + (size_t)l*DM, X, X,
             NTOK, DM, HFF, HFF, DM, DM, 1);
    }
    ln_k<<<NTOK,256>>>(X, enc_norm_g, enc_norm_b, MEMB);

    // ---------------- decoder ----------------
    embed_k<<<NTOK,256>>>(tgt, emb, Y);
    for (int l = 0; l < NLD; l++) {
        ln_k<<<NTOK,256>>>(Y, dec_ln_g + (size_t)(l*3+0)*DM, dec_ln_b + (size_t)(l*3+0)*DM, H);
        attention(H, H,
                  dec_qkv_w + (size_t)(l*2+0)*3*DM*DM, dec_qkv_b + (size_t)(l*2+0)*3*DM,
                  dec_proj_w + (size_t)(l*2+0)*DM*DM,  dec_proj_b + (size_t)(l*2+0)*DM,
                  Y, 1, QKV, AO);
        ln_k<<<NTOK,256>>>(Y, dec_ln_g + (size_t)(l*3+1)*DM, dec_ln_b + (size_t)(l*3+1)*DM, H);
        attention(H, MEMB,
                  dec_qkv_w + (size_t)(l*2+1)*3*DM*DM, dec_qkv_b + (size_t)(l*2+1)*3*DM,
                  dec_proj_w + (size_t)(l*2+1)*DM*DM,  dec_proj_b + (size_t)(l*2+1)*DM,
                  Y, 0, QKV, AO);
        ln_k<<<NTOK,256>>>(Y, dec_ln_g + (size_t)(l*3+2)*DM, dec_ln_b + (size_t)(l*3+2)*DM, H);
        gemm(H,  dec_ff_w1 + (size_t)l*DM*HFF, dec_ff_b1 + (size_t)l*HFF, nullptr, FF,
             NTOK, HFF, DM, DM, HFF, HFF, 1);
        gemm(FF, dec_ff_w2 + (size_t)l*HFF*DM, dec_ff_b2 + (size_t)l*DM, Y, Y,
             NTOK, DM, HFF, HFF, DM, DM, 1);
    }
    ln_k<<<NTOK,256>>>(Y, dec_norm_g, dec_norm_b, H);

    // ---------------- generator + log_softmax ----------------
    gemm(H, gen_w, gen_b, nullptr, out, NTOK, NV, DM, DM, NV, NV, 0);
    logsoftmax_k<<<NTOK,256>>>(out);
}

// round 6
// speedup vs baseline: 6.1484x; 1.1150x over previous
#include <cuda_runtime.h>
#include <cuda_bf16.h>
#include <mma.h>
#include <math.h>

using namespace nvcuda;
typedef __nv_bfloat16 bf;

// ---------------- problem constants ----------------
#define DM   1024
#define NHD  16
#define DH   64
#define SEQ  1024
#define NB   2
#define NTOK 2048
#define HFF  4096
#define NV   32000
#define NLE  6
#define NLD  6

// ---------------- bf16 weight pool (one-time convert per replay) ----------
#define O_ENC_QKV  0L
#define O_ENC_PROJ 18874368L
#define O_ENC_FF1  25165824L
#define O_ENC_FF2  50331648L
#define O_DEC_QKV  75497472L
#define O_DEC_PROJ 113246208L
#define O_DEC_FF1  125829120L
#define O_DEC_FF2  150994944L
#define O_GEN      176160768L
#define W_TOTAL    208928768L

__device__ bf g_W[W_TOTAL];

// ---------------- scratch ----------------
__device__ float g_X [(size_t)NTOK*DM];
__device__ float g_Y [(size_t)NTOK*DM];
__device__ bf    g_Hb [(size_t)NTOK*DM];
__device__ bf    g_MEMb[(size_t)NTOK*DM];
__device__ bf    g_QKVb[(size_t)3*NTOK*DM];
__device__ bf    g_AOb [(size_t)NTOK*DM];
__device__ bf    g_FFb [(size_t)NTOK*HFF];

// ---------------- cp.async helpers ----------------
__device__ __forceinline__ void cp16(void* d, const void* s){
    unsigned sd = (unsigned)__cvta_generic_to_shared(d);
    asm volatile("cp.async.cg.shared.global [%0], [%1], 16;\n" :: "r"(sd), "l"(s));
}
__device__ __forceinline__ void cpcommit(){ asm volatile("cp.async.commit_group;\n"); }
template<int N> __device__ __forceinline__ void cpwait(){
    asm volatile("cp.async.wait_group %0;\n" :: "n"(N));
}
__device__ __forceinline__ unsigned pack_bf2(float a, float b){
    __nv_bfloat162 h = __floats2bfloat162_rn(a, b);
    return *(unsigned*)&h;
}

// ---------------- reductions ----------------
__device__ __forceinline__ float warpSum(float v){
#pragma unroll
    for (int o=16;o>0;o>>=1) v += __shfl_xor_sync(0xffffffffu, v, o);
    return v;
}
__device__ __forceinline__ float warpMax(float v){
#pragma unroll
    for (int o=16;o>0;o>>=1) v = fmaxf(v, __shfl_xor_sync(0xffffffffu, v, o));
    return v;
}
__device__ float blockSum(float v){
    __shared__ float sh[32];
    int lane = threadIdx.x & 31, w = threadIdx.x >> 5;
    v = warpSum(v);
    if (lane==0) sh[w] = v;
    __syncthreads();
    if (w==0){
        float r = (lane < (int)(blockDim.x>>5)) ? sh[lane] : 0.f;
        r = warpSum(r);
        if (lane==0) sh[0] = r;
    }
    __syncthreads();
    float r = sh[0];
    __syncthreads();
    return r;
}
__device__ float blockMax(float v){
    __shared__ float sh[32];
    int lane = threadIdx.x & 31, w = threadIdx.x >> 5;
    v = warpMax(v);
    if (lane==0) sh[w] = v;
    __syncthreads();
    if (w==0){
        float r = (lane < (int)(blockDim.x>>5)) ? sh[lane] : -INFINITY;
        r = warpMax(r);
        if (lane==0) sh[0] = r;
    }
    __syncthreads();
    float r = sh[0];
    __syncthreads();
    return r;
}

// ---------------- f32 -> bf16 converter ----------------
__global__ void cvt_k(const float* __restrict__ s, bf* __restrict__ d, long n){
    long i = ((long)blockIdx.x*blockDim.x + threadIdx.x)*4;
    if (i < n){
        float4 v = *(const float4*)(s+i);
        *(__nv_bfloat162*)(d+i)   = __floats2bfloat162_rn(v.x, v.y);
        *(__nv_bfloat162*)(d+i+2) = __floats2bfloat162_rn(v.z, v.w);
    }
}

// ---------------- bf16 GEMM: 128x128 CTA, 4 warps x 64x64, cp.async x4 ----
#define BM 128
#define BN 128
#define BK 32
#define ASTR 48
#define BSTR 136
#define NSTAGE 4
#define ATILE (BM*ASTR)
#define BTILE (BK*BSTR)
#define GEMM_SMEM ((ATILE+BTILE)*NSTAGE*2)   // 83968 bytes
#define CSTR 136

__global__ void __launch_bounds__(128) gemm_bf(
    const bf* __restrict__ A, const bf* __restrict__ B,
    const float* __restrict__ bias, const float* __restrict__ res,
    void* __restrict__ Cv,
    int M, int N, int K, int lda, int ldb, int ldc,
    int doGelu, int outBf,
    long aob, long aoh, long bob, long boh, long biasoh,
    long cob, long coh, int nh)
{
    extern __shared__ __align__(16) unsigned char smraw[];
    bf* As = (bf*)smraw;
    bf* Bs = As + NSTAGE*ATILE;
    float* Cs = (float*)smraw;

    int z = blockIdx.z, zb = z/nh, zh = z - zb*nh;
    A += zb*aob + zh*aoh;
    B += zb*bob + zh*boh;
    if (bias) bias += zh*biasoh;
    long coff = zb*cob + zh*coh;

    int tid = threadIdx.x;
    int wid = tid >> 5;
    int wm = wid >> 1, wn = wid & 1;
    long row0 = (long)blockIdx.y * BM;
    long col0 = (long)blockIdx.x * BN;

    const bf* Ag0 = A + (row0 + tid)*(long)lda;
    int brow = tid >> 2, bcol = (tid & 3)*32;
    const bf* Bg0 = B + (long)brow*ldb + col0 + bcol;

    auto issue = [&](int kt, int s){
        const bf* ag = Ag0 + kt*BK;
        bf* ad = As + s*ATILE + tid*ASTR;
#pragma unroll
        for (int i=0;i<4;i++) cp16(ad + 8*i, ag + 8*i);
        const bf* bg = Bg0 + (long)kt*BK*ldb;
        bf* bd = Bs + s*BTILE + brow*BSTR + bcol;
#pragma unroll
        for (int i=0;i<4;i++) cp16(bd + 8*i, bg + 8*i);
    };

    wmma::fragment<wmma::accumulator,16,16,16,float> acc[4][4];
#pragma unroll
    for (int i=0;i<4;i++)
#pragma unroll
        for (int j=0;j<4;j++) wmma::fill_fragment(acc[i][j], 0.f);

    int KT = K / BK;
    issue(0,0); cpcommit();
    issue(1,1); cpcommit();
    issue(2,2); cpcommit();

    for (int kt = 0; kt < KT; kt++){
        cpwait<2>();
        __syncthreads();
        if (kt+3 < KT) issue(kt+3, (kt+3)&3);
        cpcommit();
        const bf* as = As + (kt&3)*ATILE;
        const bf* bs = Bs + (kt&3)*BTILE;
#pragma unroll
        for (int kk = 0; kk < BK; kk += 16){
            wmma::fragment<wmma::matrix_a,16,16,16,bf,wmma::row_major> af[4];
#pragma unroll
            for (int i=0;i<4;i++)
                wmma::load_matrix_sync(af[i], as + (wm*64 + i*16)*ASTR + kk, ASTR);
#pragma unroll
            for (int j=0;j<4;j++){
                wmma::fragment<wmma::matrix_b,16,16,16,bf,wmma::row_major> bfr;
                wmma::load_matrix_sync(bfr, bs + kk*BSTR + wn*64 + j*16, BSTR);
#pragma unroll
                for (int i=0;i<4;i++)
                    wmma::mma_sync(acc[i][j], af[i], bfr, acc[i][j]);
            }
        }
    }
    cpwait<0>();
    __syncthreads();

    float* C  = (float*)Cv;
    bf*    Cb = (bf*)Cv;
    for (int ph = 0; ph < 2; ph++){
        if (wm == ph){
#pragma unroll
            for (int i=0;i<4;i++)
#pragma unroll
                for (int j=0;j<4;j++)
                    wmma::store_matrix_sync(Cs + (i*16)*CSTR + wn*64 + j*16,
                                            acc[i][j], CSTR, wmma::mem_row_major);
        }
        __syncthreads();
        int r = tid >> 1, hcc = (tid & 1)*64;
        long gm = row0 + ph*64 + r;
        const float* crow = Cs + r*CSTR + hcc;
        long gn0 = col0 + hcc;
        if (!outBf){
            float* co = C + coff + gm*(long)ldc + gn0;
            const float* ro = res ? res + coff + gm*(long)ldc + gn0 : nullptr;
#pragma unroll
            for (int q=0;q<16;q++){
                float4 v = *(const float4*)(crow + q*4);
                long gn = gn0 + q*4;
                if (bias){ v.x+=bias[gn]; v.y+=bias[gn+1]; v.z+=bias[gn+2]; v.w+=bias[gn+3]; }
                if (doGelu){
                    v.x = 0.5f*v.x*(1.f+erff(v.x*0.70710678f));
                    v.y = 0.5f*v.y*(1.f+erff(v.y*0.70710678f));
                    v.z = 0.5f*v.z*(1.f+erff(v.z*0.70710678f));
                    v.w = 0.5f*v.w*(1.f+erff(v.w*0.70710678f));
                }
                if (ro){
                    float4 rv = *(const float4*)(ro + q*4);
                    v.x+=rv.x; v.y+=rv.y; v.z+=rv.z; v.w+=rv.w;
                }
                *(float4*)(co + q*4) = v;
            }
        } else {
            bf* bo = Cb + coff + gm*(long)ldc + gn0;
#pragma unroll
            for (int q=0;q<16;q+=2){
                float vv[8];
                *(float4*)(vv)   = *(const float4*)(crow + q*4);
                *(float4*)(vv+4) = *(const float4*)(crow + q*4 + 4);
                long gn = gn0 + q*4;
#pragma unroll
                for (int j=0;j<8;j++){
                    float x = vv[j];
                    if (bias) x += bias[gn+j];
                    if (doGelu) x = 0.5f*x*(1.f+erff(x*0.70710678f));
                    vv[j] = x;
                }
                uint4 w;
                w.x = pack_bf2(vv[0],vv[1]); w.y = pack_bf2(vv[2],vv[3]);
                w.z = pack_bf2(vv[4],vv[5]); w.w = pack_bf2(vv[6],vv[7]);
                *(uint4*)(bo + q*4) = w;
            }
        }
        __syncthreads();
    }
}

// ---------------- flash attention: bf16 I/O, cp.async KV double buffer ----
#define FA_BQ  128
#define FA_BKV 128
#define QSTRH 72
#define SSTR  136
#define PSTR  136
#define FA_SMEM (FA_BQ*SSTR*4 + FA_BQ*QSTRH*2 + 4*FA_BKV*QSTRH*2 + FA_BQ*PSTR*2) // 196608

__global__ void __launch_bounds__(256) flash_k(
    const bf* __restrict__ Qg, const bf* __restrict__ Kg,
    const bf* __restrict__ Vg, bf* __restrict__ Og)
{
    extern __shared__ float smf[];
    float* sS = smf;
    bf* sQ = (bf*)(sS + FA_BQ*SSTR);
    bf* sK = sQ + FA_BQ*QSTRH;
    bf* sV = sK + 2*FA_BKV*QSTRH;
    bf* sP = sV + 2*FA_BKV*QSTRH;

    int tid = threadIdx.x;
    int wid = tid >> 5;
    int bh  = blockIdx.y;
    long base = ((long)(bh >> 4) * SEQ) * DM + (bh & 15) * DH;
    int q0 = blockIdx.x * FA_BQ;

    int r  = tid >> 1;
    int hc = tid & 1;

    // Q tile: direct 16B copies (already bf16)
    {
        const uint4* qs = (const uint4*)(Qg + base + (long)(q0+r)*DM + hc*32);
        uint4* qd = (uint4*)(sQ + r*QSTRH + hc*32);
#pragma unroll
        for (int i=0;i<4;i++) qd[i] = qs[i];
    }

    auto issueKV = [&](int j, int buf){
        const bf* kg = Kg + base + (long)(j*FA_BKV + r)*DM + hc*32;
        const bf* vg = Vg + base + (long)(j*FA_BKV + r)*DM + hc*32;
        bf* kd = sK + buf*FA_BKV*QSTRH + r*QSTRH + hc*32;
        bf* vd = sV + buf*FA_BKV*QSTRH + r*QSTRH + hc*32;
#pragma unroll
        for (int i=0;i<4;i++) cp16(kd + 8*i, kg + 8*i);
#pragma unroll
        for (int i=0;i<4;i++) cp16(vd + 8*i, vg + 8*i);
    };

    float o[32];
#pragma unroll
    for (int i=0;i<32;i++) o[i] = 0.f;
    float mrow = -INFINITY, lrow = 0.f;

    issueKV(0, 0); cpcommit();

    const int NKV = SEQ/FA_BKV;
    for (int j = 0; j < NKV; j++){
        int cb = j & 1;
        cpwait<0>();
        __syncthreads();                     // tile j visible to all
        if (j+1 < NKV) issueKV(j+1, cb^1);   // overwrites tile j-1 buffer (safe)
        cpcommit();

        bf* kc = sK + cb*FA_BKV*QSTRH;
        bf* vc = sV + cb*FA_BKV*QSTRH;

        // S band = Q band @ K^T
        {
            wmma::fragment<wmma::accumulator,16,16,16,float> acc[8];
#pragma unroll
            for (int n=0;n<8;n++) wmma::fill_fragment(acc[n], 0.f);
#pragma unroll
            for (int kk=0; kk<DH; kk+=16){
                wmma::fragment<wmma::matrix_a,16,16,16,bf,wmma::row_major> af;
                wmma::load_matrix_sync(af, sQ + (wid*16)*QSTRH + kk, QSTRH);
#pragma unroll
                for (int n=0;n<8;n++){
                    wmma::fragment<wmma::matrix_b,16,16,16,bf,wmma::col_major> bfr;
                    wmma::load_matrix_sync(bfr, kc + (n*16)*QSTRH + kk, QSTRH);
                    wmma::mma_sync(acc[n], af, bfr, acc[n]);
                }
            }
#pragma unroll
            for (int n=0;n<8;n++)
                wmma::store_matrix_sync(sS + (wid*16)*SSTR + n*16, acc[n], SSTR, wmma::mem_row_major);
        }
        __syncwarp();

        // online softmax; P -> bf16
        {
            float* srow = sS + r*SSTR + hc*64;
            bf* prow = sP + r*PSTR + hc*64;
            float tmax = -INFINITY;
#pragma unroll
            for (int q=0;q<16;q++){
                float4 v = *(const float4*)(srow + q*4);
                tmax = fmaxf(tmax, fmaxf(fmaxf(v.x,v.y), fmaxf(v.z,v.w)));
            }
            tmax = fmaxf(tmax, __shfl_xor_sync(0xffffffffu, tmax, 1));
            float mnew = fmaxf(mrow, tmax);
            float alpha = __expf(mrow - mnew);
            float tsum = 0.f;
#pragma unroll
            for (int q=0;q<16;q++){
                float4 v = *(const float4*)(srow + q*4);
                float e0 = __expf(v.x-mnew), e1 = __expf(v.y-mnew);
                float e2 = __expf(v.z-mnew), e3 = __expf(v.w-mnew);
                tsum += (e0+e1)+(e2+e3);
                *(unsigned*)(prow + q*4)     = pack_bf2(e0,e1);
                *(unsigned*)(prow + q*4 + 2) = pack_bf2(e2,e3);
            }
            tsum += __shfl_xor_sync(0xffffffffu, tsum, 1);
            lrow = lrow*alpha + tsum;
            mrow = mnew;
#pragma unroll
            for (int i=0;i<32;i++) o[i] *= alpha;
        }
        __syncwarp();

        // O band += P @ V
        {
            wmma::fragment<wmma::accumulator,16,16,16,float> acc[4];
#pragma unroll
            for (int n=0;n<4;n++) wmma::fill_fragment(acc[n], 0.f);
#pragma unroll
            for (int kk=0; kk<FA_BKV; kk+=16){
                wmma::fragment<wmma::matrix_a,16,16,16,bf,wmma::row_major> af;
                wmma::load_matrix_sync(af, sP + (wid*16)*PSTR + kk, PSTR);
#pragma unroll
                for (int n=0;n<4;n++){
                    wmma::fragment<wmma::matrix_b,16,16,16,bf,wmma::row_major> bfr;
                    wmma::load_matrix_sync(bfr, vc + kk*QSTRH + n*16, QSTRH);
                    wmma::mma_sync(acc[n], af, bfr, acc[n]);
                }
            }
#pragma unroll
            for (int n=0;n<4;n++)
                wmma::store_matrix_sync(sS + (wid*16)*SSTR + n*16, acc[n], SSTR, wmma::mem_row_major);
        }
        __syncwarp();
        {
            const float* orow = sS + r*SSTR + hc*32;
#pragma unroll
            for (int q=0;q<8;q++){
                float4 v = *(const float4*)(orow + q*4);
                o[q*4+0]+=v.x; o[q*4+1]+=v.y; o[q*4+2]+=v.z; o[q*4+3]+=v.w;
            }
        }
        __syncthreads();   // everyone done with buffers before next overwrite
    }

    float inv = 1.0f / lrow;
    bf* db = Og + base + (long)(q0+r)*DM + hc*32;
#pragma unroll
    for (int q=0;q<4;q++){
        uint4 w;
        w.x = pack_bf2(o[q*8+0]*inv, o[q*8+1]*inv);
        w.y = pack_bf2(o[q*8+2]*inv, o[q*8+3]*inv);
        w.z = pack_bf2(o[q*8+4]*inv, o[q*8+5]*inv);
        w.w = pack_bf2(o[q*8+6]*inv, o[q*8+7]*inv);
        *(uint4*)(db + q*8) = w;
    }
}

// ---------------- embedding + positional encoding ----------------
__global__ void embed_k(const int* __restrict__ tok, const float* __restrict__ emb,
                        float* __restrict__ out)
{
    int t = blockIdx.x;
    int s = t & (SEQ-1);
    int id = tok[t];
    const float* e = emb + (long)id*DM;
    float* o = out + (long)t*DM;
    const float c = -logf(10000.0f) / (float)DM;
    for (int d = threadIdx.x; d < DM; d += blockDim.x) {
        int i2 = d & ~1;
        float ang = (float)s * expf((float)i2 * c);
        float pe = (d & 1) ? cosf(ang) : sinf(ang);
        o[d] = e[d]*32.0f + pe;
    }
}

// ---------------- LayerNorm (f32 in -> bf16 out) ----------------
__global__ void ln_k(const float* __restrict__ x, const float* __restrict__ g,
                     const float* __restrict__ b, bf* __restrict__ out)
{
    long t = blockIdx.x;
    const float4* xr = (const float4*)(x + t*DM);
    float4 v = xr[threadIdx.x];
    float s  = v.x+v.y+v.z+v.w;
    float ss = v.x*v.x+v.y*v.y+v.z*v.z+v.w*v.w;
    s  = blockSum(s);
    ss = blockSum(ss);
    float mean = s * (1.0f/DM);
    float var  = ss * (1.0f/DM) - mean*mean;
    float inv  = rsqrtf(var + 1e-5f);
    float4 gg = ((const float4*)g)[threadIdx.x];
    float4 bb = ((const float4*)b)[threadIdx.x];
    uint2 w;
    w.x = pack_bf2((v.x-mean)*inv*gg.x + bb.x, (v.y-mean)*inv*gg.y + bb.y);
    w.y = pack_bf2((v.z-mean)*inv*gg.z + bb.z, (v.w-mean)*inv*gg.w + bb.w);
    *(uint2*)(out + t*DM + threadIdx.x*4) = w;
}

// ---------------- log_softmax over NV ----------------
__global__ void logsoftmax_k(float* __restrict__ p)
{
    float* r = p + (long)blockIdx.x * NV;
    float mx = -INFINITY;
    for (int d = threadIdx.x; d < NV; d += blockDim.x) mx = fmaxf(mx, r[d]);
    mx = blockMax(mx);
    float sum = 0.f;
    for (int d = threadIdx.x; d < NV; d += blockDim.x) sum += __expf(r[d]-mx);
    sum = blockSum(sum);
    float lse = mx + logf(sum);
    for (int d = threadIdx.x; d < NV; d += blockDim.x) r[d] -= lse;
}

// ---------------- host helpers ----------------
static void gemm(const bf* A, const bf* B, const float* bias, const float* res,
                 void* C, int M, int N, int K, int lda, int ldb, int ldc,
                 int gelu, int outBf,
                 long aob=0, long aoh=0, long bob=0, long boh=0, long biasoh=0,
                 long cob=0, long coh=0, int nh=1, int nz=1)
{
    dim3 grid(N/BN, M/BM, nz);
    gemm_bf<<<grid, 128, GEMM_SMEM>>>(A,B,bias,res,C,M,N,K,lda,ldb,ldc,gelu,outBf,
                                      aob,aoh,bob,boh,biasoh,cob,coh,nh);
}

static void cvt(const float* s, bf* d, long n){
    long blocks = (n/4 + 255)/256;
    cvt_k<<<(unsigned)blocks, 256>>>(s, d, n);
}

static void attention(const bf* Hq, const bf* Hkv,
                      const bf* wqkv, const float* bqkv,
                      const bf* wproj, const float* bproj,
                      float* x, int sameKV,
                      bf* QKV, bf* AO)
{
    bf* Q  = QKV;
    bf* Kb = QKV + (size_t)NTOK*DM;
    if (sameKV) {
        gemm(Hq, wqkv, bqkv, nullptr, QKV, NTOK, DM, DM, DM, DM, DM, 0, 1,
             0, 0, 0, (long)DM*DM, DM, 0, (long)NTOK*DM, 3, 3);
    } else {
        gemm(Hq, wqkv, bqkv, nullptr, Q, NTOK, DM, DM, DM, DM, DM, 0, 1);
        gemm(Hkv, wqkv + (size_t)DM*DM, bqkv + DM, nullptr, Kb,
             NTOK, DM, DM, DM, DM, DM, 0, 1,
             0, 0, 0, (long)DM*DM, DM, 0, (long)NTOK*DM, 2, 2);
    }
    bf* Vb = QKV + (size_t)2*NTOK*DM;
    dim3 fgrid(SEQ/FA_BQ, NB*NHD);
    flash_k<<<fgrid, 256, FA_SMEM>>>(Q, Kb, Vb, AO);
    gemm(AO, wproj, bproj, x, x, NTOK, DM, DM, DM, DM, DM, 0, 0);
}

extern "C" void kernel_launch(void* const* d_in, const int* in_sizes, int n_in,
                              void* d_out, int out_size)
{
    const int*   src        = (const int*)  d_in[0];
    const int*   tgt        = (const int*)  d_in[1];
    const float* emb        = (const float*)d_in[5];
    const float* enc_qkv_w  = (const float*)d_in[6];
    const float* enc_qkv_b  = (const float*)d_in[7];
    const float* enc_proj_w = (const float*)d_in[8];
    const float* enc_proj_b = (const float*)d_in[9];
    const float* enc_ff_w1  = (const float*)d_in[10];
    const float* enc_ff_b1  = (const float*)d_in[11];
    const float* enc_ff_w2  = (const float*)d_in[12];
    const float* enc_ff_b2  = (const float*)d_in[13];
    const float* enc_ln_g   = (const float*)d_in[14];
    const float* enc_ln_b   = (const float*)d_in[15];
    const float* enc_norm_g = (const float*)d_in[16];
    const float* enc_norm_b = (const float*)d_in[17];
    const float* dec_qkv_w  = (const float*)d_in[18];
    const float* dec_qkv_b  = (const float*)d_in[19];
    const float* dec_proj_w = (const float*)d_in[20];
    const float* dec_proj_b = (const float*)d_in[21];
    const float* dec_ff_w1  = (const float*)d_in[22];
    const float* dec_ff_b1  = (const float*)d_in[23];
    const float* dec_ff_w2  = (const float*)d_in[24];
    const float* dec_ff_b2  = (const float*)d_in[25];
    const float* dec_ln_g   = (const float*)d_in[26];
    const float* dec_ln_b   = (const float*)d_in[27];
    const float* dec_norm_g = (const float*)d_in[28];
    const float* dec_norm_b = (const float*)d_in[29];
    const float* gen_w      = (const float*)d_in[30];
    const float* gen_b      = (const float*)d_in[31];
    float* out = (float*)d_out;

    cudaFuncSetAttribute(flash_k, cudaFuncAttributeMaxDynamicSharedMemorySize, FA_SMEM);
    cudaFuncSetAttribute(gemm_bf, cudaFuncAttributeMaxDynamicSharedMemorySize, GEMM_SMEM);

    float *X,*Y;
    bf *Hb,*MEMb,*QKVb,*AOb,*FFb,*W;
    cudaGetSymbolAddress((void**)&X,    g_X);
    cudaGetSymbolAddress((void**)&Y,    g_Y);
    cudaGetSymbolAddress((void**)&Hb,   g_Hb);
    cudaGetSymbolAddress((void**)&MEMb, g_MEMb);
    cudaGetSymbolAddress((void**)&QKVb, g_QKVb);
    cudaGetSymbolAddress((void**)&AOb,  g_AOb);
    cudaGetSymbolAddress((void**)&FFb,  g_FFb);
    cudaGetSymbolAddress((void**)&W,    g_W);

    // ---- one-time (per replay) weight conversion ----
    cvt(enc_qkv_w,  W + O_ENC_QKV,  (long)NLE*3*DM*DM);
    cvt(enc_proj_w, W + O_ENC_PROJ, (long)NLE*DM*DM);
    cvt(enc_ff_w1,  W + O_ENC_FF1,  (long)NLE*DM*HFF);
    cvt(enc_ff_w2,  W + O_ENC_FF2,  (long)NLE*HFF*DM);
    cvt(dec_qkv_w,  W + O_DEC_QKV,  (long)NLD*2*3*DM*DM);
    cvt(dec_proj_w, W + O_DEC_PROJ, (long)NLD*2*DM*DM);
    cvt(dec_ff_w1,  W + O_DEC_FF1,  (long)NLD*DM*HFF);
    cvt(dec_ff_w2,  W + O_DEC_FF2,  (long)NLD*HFF*DM);
    cvt(gen_w,      W + O_GEN,      (long)DM*NV);

    // ---------------- encoder ----------------
    embed_k<<<NTOK,256>>>(src, emb, X);
    for (int l = 0; l < NLE; l++) {
        ln_k<<<NTOK,256>>>(X, enc_ln_g + (size_t)(l*2+0)*DM, enc_ln_b + (size_t)(l*2+0)*DM, Hb);
        attention(Hb, Hb,
                  W + O_ENC_QKV + (long)l*3*DM*DM, enc_qkv_b + (size_t)l*3*DM,
                  W + O_ENC_PROJ + (long)l*DM*DM,  enc_proj_b + (size_t)l*DM,
                  X, 1, QKVb, AOb);
        ln_k<<<NTOK,256>>>(X, enc_ln_g + (size_t)(l*2+1)*DM, enc_ln_b + (size_t)(l*2+1)*DM, Hb);
        gemm(Hb, W + O_ENC_FF1 + (long)l*DM*HFF, enc_ff_b1 + (size_t)l*HFF, nullptr, FFb,
             NTOK, HFF, DM, DM, HFF, HFF, 1, 1);
        gemm(FFb, W + O_ENC_FF2 + (long)l*HFF*DM, enc_ff_b2 + (size_t)l*DM, X, X,
             NTOK, DM, HFF, HFF, DM, DM, 1, 0);
    }
    ln_k<<<NTOK,256>>>(X, enc_norm_g, enc_norm_b, MEMb);

    // ---------------- decoder ----------------
    embed_k<<<NTOK,256>>>(tgt, emb, Y);
    for (int l = 0; l < NLD; l++) {
        ln_k<<<NTOK,256>>>(Y, dec_ln_g + (size_t)(l*3+0)*DM, dec_ln_b + (size_t)(l*3+0)*DM, Hb);
        attention(Hb, Hb,
                  W + O_DEC_QKV + (long)(l*2+0)*3*DM*DM, dec_qkv_b + (size_t)(l*2+0)*3*DM,
                  W + O_DEC_PROJ + (long)(l*2+0)*DM*DM,  dec_proj_b + (size_t)(l*2+0)*DM,
                  Y, 1, QKVb, AOb);
        ln_k<<<NTOK,256>>>(Y, dec_ln_g + (size_t)(l*3+1)*DM, dec_ln_b + (size_t)(l*3+1)*DM, Hb);
        attention(Hb, MEMb,
                  W + O_DEC_QKV + (long)(l*2+1)*3*DM*DM, dec_qkv_b + (size_t)(l*2+1)*3*DM,
                  W + O_DEC_PROJ + (long)(l*2+1)*DM*DM,  dec_proj_b + (size_t)(l*2+1)*DM,
                  Y, 0, QKVb, AOb);
        ln_k<<<NTOK,256>>>(Y, dec_ln_g + (size_t)(l*3+2)*DM, dec_ln_b + (size_t)(l*3+2)*DM, Hb);
        gemm(Hb, W + O_DEC_FF1 + (long)l*DM*HFF, dec_ff_b1 + (size_t)l*HFF, nullptr, FFb,
             NTOK, HFF, DM, DM, HFF, HFF, 1, 1);
        gemm(FFb, W + O_DEC_FF2 + (long)l*HFF*DM, dec_ff_b2 + (size_t)l*DM, Y, Y,
             NTOK, DM, HFF, HFF, DM, DM, 1, 0);
    }
    ln_k<<<NTOK,256>>>(Y, dec_norm_g, dec_norm_b, Hb);

    // ---------------- generator + log_softmax ----------------
    gemm(Hb, W + O_GEN, gen_b, nullptr, out, NTOK, NV, DM, DM, NV, NV, 0, 0);
    logsoftmax_k<<<NTOK,256>>>(out);
}

// round 8
// speedup vs baseline: 6.7218x; 1.0932x over previous
#include <cuda_runtime.h>
#include <cuda_bf16.h>
#include <mma.h>
#include <math.h>

using namespace nvcuda;
typedef __nv_bfloat16 bf;

// ---------------- problem constants ----------------
#define DM   1024
#define NHD  16
#define DH   64
#define SEQ  1024
#define NB   2
#define NTOK 2048
#define HFF  4096
#define NV   32000
#define NLE  6
#define NLD  6

// ---------------- bf16 weight pool (one-time convert per replay) ----------
#define O_ENC_QKV  0L
#define O_ENC_PROJ 18874368L
#define O_ENC_FF1  25165824L
#define O_ENC_FF2  50331648L
#define O_DEC_QKV  75497472L
#define O_DEC_PROJ 113246208L
#define O_DEC_FF1  125829120L
#define O_DEC_FF2  150994944L
#define O_GEN      176160768L
#define W_TOTAL    208928768L

__device__ bf g_W[W_TOTAL];

// ---------------- scratch ----------------
__device__ float g_X [(size_t)NTOK*DM];
__device__ float g_Y [(size_t)NTOK*DM];
__device__ bf    g_Hb [(size_t)NTOK*DM];
__device__ bf    g_MEMb[(size_t)NTOK*DM];
__device__ bf    g_QKVb[(size_t)3*NTOK*DM];
__device__ bf    g_AOb [(size_t)NTOK*DM];
__device__ bf    g_FFb [(size_t)NTOK*HFF];

// ---------------- low-level helpers ----------------
__device__ __forceinline__ void cp16(void* d, const void* s){
    unsigned sd = (unsigned)__cvta_generic_to_shared(d);
    asm volatile("cp.async.cg.shared.global [%0], [%1], 16;\n" :: "r"(sd), "l"(s));
}
__device__ __forceinline__ void cpcommit(){ asm volatile("cp.async.commit_group;\n"); }
template<int N> __device__ __forceinline__ void cpwait(){
    asm volatile("cp.async.wait_group %0;\n" :: "n"(N));
}
__device__ __forceinline__ unsigned pack_bf2(float a, float b){
    __nv_bfloat162 h = __floats2bfloat162_rn(a, b);
    return *(unsigned*)&h;
}
__device__ __forceinline__ void ldm4(unsigned &a0, unsigned &a1, unsigned &a2, unsigned &a3,
                                     unsigned addr){
    asm volatile("ldmatrix.sync.aligned.m8n8.x4.shared.b16 {%0,%1,%2,%3}, [%4];"
                 : "=r"(a0),"=r"(a1),"=r"(a2),"=r"(a3) : "r"(addr));
}
__device__ __forceinline__ void ldm4t(unsigned &a0, unsigned &a1, unsigned &a2, unsigned &a3,
                                      unsigned addr){
    asm volatile("ldmatrix.sync.aligned.m8n8.x4.trans.shared.b16 {%0,%1,%2,%3}, [%4];"
                 : "=r"(a0),"=r"(a1),"=r"(a2),"=r"(a3) : "r"(addr));
}
__device__ __forceinline__ void mmabf(float* c, unsigned a0, unsigned a1, unsigned a2, unsigned a3,
                                      unsigned b0, unsigned b1){
    asm volatile("mma.sync.aligned.m16n8k16.row.col.f32.bf16.bf16.f32 "
                 "{%0,%1,%2,%3}, {%4,%5,%6,%7}, {%8,%9}, {%0,%1,%2,%3};"
                 : "+f"(c[0]),"+f"(c[1]),"+f"(c[2]),"+f"(c[3])
                 : "r"(a0),"r"(a1),"r"(a2),"r"(a3),"r"(b0),"r"(b1));
}

// ---------------- reductions ----------------
__device__ __forceinline__ float warpSum(float v){
#pragma unroll
    for (int o=16;o>0;o>>=1) v += __shfl_xor_sync(0xffffffffu, v, o);
    return v;
}
__device__ __forceinline__ float warpMax(float v){
#pragma unroll
    for (int o=16;o>0;o>>=1) v = fmaxf(v, __shfl_xor_sync(0xffffffffu, v, o));
    return v;
}
__device__ float blockSum(float v){
    __shared__ float sh[32];
    int lane = threadIdx.x & 31, w = threadIdx.x >> 5;
    v = warpSum(v);
    if (lane==0) sh[w] = v;
    __syncthreads();
    if (w==0){
        float r = (lane < (int)(blockDim.x>>5)) ? sh[lane] : 0.f;
        r = warpSum(r);
        if (lane==0) sh[0] = r;
    }
    __syncthreads();
    float r = sh[0];
    __syncthreads();
    return r;
}
__device__ float blockMax(float v){
    __shared__ float sh[32];
    int lane = threadIdx.x & 31, w = threadIdx.x >> 5;
    v = warpMax(v);
    if (lane==0) sh[w] = v;
    __syncthreads();
    if (w==0){
        float r = (lane < (int)(blockDim.x>>5)) ? sh[lane] : -INFINITY;
        r = warpMax(r);
        if (lane==0) sh[0] = r;
    }
    __syncthreads();
    float r = sh[0];
    __syncthreads();
    return r;
}

// ---------------- f32 -> bf16 converter ----------------
__global__ void cvt_k(const float* __restrict__ s, bf* __restrict__ d, long n){
    long i = ((long)blockIdx.x*blockDim.x + threadIdx.x)*4;
    if (i < n){
        float4 v = *(const float4*)(s+i);
        *(__nv_bfloat162*)(d+i)   = __floats2bfloat162_rn(v.x, v.y);
        *(__nv_bfloat162*)(d+i+2) = __floats2bfloat162_rn(v.z, v.w);
    }
}

// ---------------- bf16 GEMM: 128x128 CTA, 4 warps x 64x64, cp.async x4 ----
#define BM 128
#define BN 128
#define BK 32
#define ASTR 48
#define BSTR 136
#define NSTAGE 4
#define ATILE (BM*ASTR)
#define BTILE (BK*BSTR)
#define GEMM_SMEM ((ATILE+BTILE)*NSTAGE*2)
#define CSTR 136

__global__ void __launch_bounds__(128) gemm_bf(
    const bf* __restrict__ A, const bf* __restrict__ B,
    const float* __restrict__ bias, const float* __restrict__ res,
    void* __restrict__ Cv,
    int M, int N, int K, int lda, int ldb, int ldc,
    int doGelu, int outBf,
    long aob, long aoh, long bob, long boh, long biasoh,
    long cob, long coh, int nh)
{
    extern __shared__ __align__(16) unsigned char smraw[];
    bf* As = (bf*)smraw;
    bf* Bs = As + NSTAGE*ATILE;
    float* Cs = (float*)smraw;

    int z = blockIdx.z, zb = z/nh, zh = z - zb*nh;
    A += zb*aob + zh*aoh;
    B += zb*bob + zh*boh;
    if (bias) bias += zh*biasoh;
    long coff = zb*cob + zh*coh;

    int tid = threadIdx.x;
    int wid = tid >> 5;
    int wm = wid >> 1, wn = wid & 1;
    long row0 = (long)blockIdx.y * BM;
    long col0 = (long)blockIdx.x * BN;

    const bf* Ag0 = A + (row0 + tid)*(long)lda;
    int brow = tid >> 2, bcol = (tid & 3)*32;
    const bf* Bg0 = B + (long)brow*ldb + col0 + bcol;

    auto issue = [&](int kt, int s){
        const bf* ag = Ag0 + kt*BK;
        bf* ad = As + s*ATILE + tid*ASTR;
#pragma unroll
        for (int i=0;i<4;i++) cp16(ad + 8*i, ag + 8*i);
        const bf* bg = Bg0 + (long)kt*BK*ldb;
        bf* bd = Bs + s*BTILE + brow*BSTR + bcol;
#pragma unroll
        for (int i=0;i<4;i++) cp16(bd + 8*i, bg + 8*i);
    };

    wmma::fragment<wmma::accumulator,16,16,16,float> acc[4][4];
#pragma unroll
    for (int i=0;i<4;i++)
#pragma unroll
        for (int j=0;j<4;j++) wmma::fill_fragment(acc[i][j], 0.f);

    int KT = K / BK;
    issue(0,0); cpcommit();
    issue(1,1); cpcommit();
    issue(2,2); cpcommit();

    for (int kt = 0; kt < KT; kt++){
        cpwait<2>();
        __syncthreads();
        if (kt+3 < KT) issue(kt+3, (kt+3)&3);
        cpcommit();
        const bf* as = As + (kt&3)*ATILE;
        const bf* bs = Bs + (kt&3)*BTILE;
#pragma unroll
        for (int kk = 0; kk < BK; kk += 16){
            wmma::fragment<wmma::matrix_a,16,16,16,bf,wmma::row_major> af[4];
#pragma unroll
            for (int i=0;i<4;i++)
                wmma::load_matrix_sync(af[i], as + (wm*64 + i*16)*ASTR + kk, ASTR);
#pragma unroll
            for (int j=0;j<4;j++){
                wmma::fragment<wmma::matrix_b,16,16,16,bf,wmma::row_major> bfr;
                wmma::load_matrix_sync(bfr, bs + kk*BSTR + wn*64 + j*16, BSTR);
#pragma unroll
                for (int i=0;i<4;i++)
                    wmma::mma_sync(acc[i][j], af[i], bfr, acc[i][j]);
            }
        }
    }
    cpwait<0>();
    __syncthreads();

    float* C  = (float*)Cv;
    bf*    Cb = (bf*)Cv;
    for (int ph = 0; ph < 2; ph++){
        if (wm == ph){
#pragma unroll
            for (int i=0;i<4;i++)
#pragma unroll
                for (int j=0;j<4;j++)
                    wmma::store_matrix_sync(Cs + (i*16)*CSTR + wn*64 + j*16,
                                            acc[i][j], CSTR, wmma::mem_row_major);
        }
        __syncthreads();
        int r = tid >> 1, hcc = (tid & 1)*64;
        long gm = row0 + ph*64 + r;
        const float* crow = Cs + r*CSTR + hcc;
        long gn0 = col0 + hcc;
        if (!outBf){
            float* co = C + coff + gm*(long)ldc + gn0;
            const float* ro = res ? res + coff + gm*(long)ldc + gn0 : nullptr;
#pragma unroll
            for (int q=0;q<16;q++){
                float4 v = *(const float4*)(crow + q*4);
                long gn = gn0 + q*4;
                if (bias){ v.x+=bias[gn]; v.y+=bias[gn+1]; v.z+=bias[gn+2]; v.w+=bias[gn+3]; }
                if (doGelu){
                    v.x = 0.5f*v.x*(1.f+erff(v.x*0.70710678f));
                    v.y = 0.5f*v.y*(1.f+erff(v.y*0.70710678f));
                    v.z = 0.5f*v.z*(1.f+erff(v.z*0.70710678f));
                    v.w = 0.5f*v.w*(1.f+erff(v.w*0.70710678f));
                }
                if (ro){
                    float4 rv = *(const float4*)(ro + q*4);
                    v.x+=rv.x; v.y+=rv.y; v.z+=rv.z; v.w+=rv.w;
                }
                *(float4*)(co + q*4) = v;
            }
        } else {
            bf* bo = Cb + coff + gm*(long)ldc + gn0;
#pragma unroll
            for (int q=0;q<16;q+=2){
                float vv[8];
                *(float4*)(vv)   = *(const float4*)(crow + q*4);
                *(float4*)(vv+4) = *(const float4*)(crow + q*4 + 4);
                long gn = gn0 + q*4;
#pragma unroll
                for (int j=0;j<8;j++){
                    float x = vv[j];
                    if (bias) x += bias[gn+j];
                    if (doGelu) x = 0.5f*x*(1.f+erff(x*0.70710678f));
                    vv[j] = x;
                }
                uint4 w;
                w.x = pack_bf2(vv[0],vv[1]); w.y = pack_bf2(vv[2],vv[3]);
                w.z = pack_bf2(vv[4],vv[5]); w.w = pack_bf2(vv[6],vv[7]);
                *(uint4*)(bo + q*4) = w;
            }
        }
        __syncthreads();
    }
}

// ---------------- flash attention: FA2-style, register S/P/O, mma.sync ----
// smem: Q 128x72 bf16 (18KB) + K double (36KB) + V double (36KB) = 92160B
#define FA_BQ  128
#define FA_SMEM 92160

__global__ void __launch_bounds__(256) flash_k(
    const bf* __restrict__ Qg, const bf* __restrict__ Kg,
    const bf* __restrict__ Vg, bf* __restrict__ Og)
{
    extern __shared__ char smc[];
    unsigned smem0 = (unsigned)__cvta_generic_to_shared(smc);
    unsigned smQ = smem0;
    unsigned smK = smem0 + 18432u;
    unsigned smV = smem0 + 18432u + 36864u;
    bf* gQ = (bf*)smc;
    bf* gK = (bf*)(smc + 18432);
    bf* gV = (bf*)(smc + 18432 + 36864);

    int tid = threadIdx.x;
    int wid = tid >> 5, lane = tid & 31;
    int bh = blockIdx.y;
    long base = ((long)(bh >> 4) * SEQ) * DM + (bh & 15) * DH;
    int q0 = blockIdx.x * FA_BQ;

    int r  = tid >> 1;
    int hc = tid & 1;

    // Q tile -> smem (already bf16)
    {
        const uint4* qs = (const uint4*)(Qg + base + (long)(q0+r)*DM + hc*32);
        uint4* qd = (uint4*)(gQ + r*72 + hc*32);
#pragma unroll
        for (int i=0;i<4;i++) qd[i] = qs[i];
    }

    auto issueKV = [&](int j, int buf){
        const bf* kg = Kg + base + (long)(j*128 + r)*DM + hc*32;
        const bf* vg = Vg + base + (long)(j*128 + r)*DM + hc*32;
        bf* kd = gK + buf*(128*72) + r*72 + hc*32;
        bf* vd = gV + buf*(128*72) + r*72 + hc*32;
#pragma unroll
        for (int i=0;i<4;i++) cp16(kd + 8*i, kg + 8*i);
#pragma unroll
        for (int i=0;i<4;i++) cp16(vd + 8*i, vg + 8*i);
    };

    issueKV(0, 0); cpcommit();
    __syncthreads();   // Q visible

    // preload Q a-fragments: 4 k16-slabs
    unsigned lrow = (unsigned)(lane & 15);
    unsigned lch  = ((unsigned)(lane >> 4)) << 3;
    unsigned qa[4][4];
    {
        unsigned qaddr = smQ + ((wid*16u + lrow)*72u + lch)*2u;
#pragma unroll
        for (int s=0;s<4;s++)
            ldm4(qa[s][0], qa[s][1], qa[s][2], qa[s][3], qaddr + s*32u);
    }

    float ot[8][4];
#pragma unroll
    for (int d=0;d<8;d++){ ot[d][0]=0.f; ot[d][1]=0.f; ot[d][2]=0.f; ot[d][3]=0.f; }
    float m0 = -INFINITY, m1 = -INFINITY, l0 = 0.f, l1 = 0.f;

    const int NKV = SEQ/128;
    for (int j = 0; j < NKV; j++){
        int cb = j & 1;
        cpwait<0>();
        __syncthreads();
        if (j+1 < NKV) issueKV(j+1, cb^1);
        cpcommit();

        unsigned kb = smK + (unsigned)cb*18432u;
        unsigned vb = smV + (unsigned)cb*18432u;

        // ---- S = Q @ K^T (16x128 per warp) in registers ----
        float sc[16][4];
#pragma unroll
        for (int t=0;t<16;t++){ sc[t][0]=0.f; sc[t][1]=0.f; sc[t][2]=0.f; sc[t][3]=0.f; }
#pragma unroll
        for (int g=0; g<8; g++){
            unsigned ka = kb + ((g*16u + lrow)*72u + lch)*2u;
#pragma unroll
            for (int s=0; s<4; s++){
                unsigned k0,k1,k2,k3;
                ldm4(k0,k1,k2,k3, ka + s*32u);
                mmabf(sc[2*g],   qa[s][0],qa[s][1],qa[s][2],qa[s][3], k0,k2);
                mmabf(sc[2*g+1], qa[s][0],qa[s][1],qa[s][2],qa[s][3], k1,k3);
            }
        }

        // ---- online softmax in registers (rows r0=lane>>2, r1=r0+8) ----
        float mx0 = -INFINITY, mx1 = -INFINITY;
#pragma unroll
        for (int t=0;t<16;t++){
            mx0 = fmaxf(mx0, fmaxf(sc[t][0], sc[t][1]));
            mx1 = fmaxf(mx1, fmaxf(sc[t][2], sc[t][3]));
        }
        mx0 = fmaxf(mx0, __shfl_xor_sync(0xffffffffu, mx0, 1));
        mx0 = fmaxf(mx0, __shfl_xor_sync(0xffffffffu, mx0, 2));
        mx1 = fmaxf(mx1, __shfl_xor_sync(0xffffffffu, mx1, 1));
        mx1 = fmaxf(mx1, __shfl_xor_sync(0xffffffffu, mx1, 2));
        float mn0 = fmaxf(m0, mx0), mn1 = fmaxf(m1, mx1);
        float al0 = __expf(m0 - mn0), al1 = __expf(m1 - mn1);
        float s0 = 0.f, s1 = 0.f;
        unsigned pa[8][4];
#pragma unroll
        for (int t=0;t<8;t++){
            float e00 = __expf(sc[2*t][0]-mn0),   e01 = __expf(sc[2*t][1]-mn0);
            float e10 = __expf(sc[2*t][2]-mn1),   e11 = __expf(sc[2*t][3]-mn1);
            float f00 = __expf(sc[2*t+1][0]-mn0), f01 = __expf(sc[2*t+1][1]-mn0);
            float f10 = __expf(sc[2*t+1][2]-mn1), f11 = __expf(sc[2*t+1][3]-mn1);
            s0 += (e00+e01)+(f00+f01);
            s1 += (e10+e11)+(f10+f11);
            pa[t][0] = pack_bf2(e00,e01);
            pa[t][1] = pack_bf2(e10,e11);
            pa[t][2] = pack_bf2(f00,f01);
            pa[t][3] = pack_bf2(f10,f11);
        }
        s0 += __shfl_xor_sync(0xffffffffu, s0, 1);
        s0 += __shfl_xor_sync(0xffffffffu, s0, 2);
        s1 += __shfl_xor_sync(0xffffffffu, s1, 1);
        s1 += __shfl_xor_sync(0xffffffffu, s1, 2);
        l0 = l0*al0 + s0;
        l1 = l1*al1 + s1;
        m0 = mn0; m1 = mn1;
#pragma unroll
        for (int d=0;d<8;d++){
            ot[d][0]*=al0; ot[d][1]*=al0; ot[d][2]*=al1; ot[d][3]*=al1;
        }

        // ---- O += P @ V ----
#pragma unroll
        for (int s=0; s<8; s++){
            unsigned va = vb + ((s*16u + lrow)*72u + lch)*2u;
#pragma unroll
            for (int d=0; d<4; d++){
                unsigned v0,v1,v2,v3;
                ldm4t(v0,v1,v2,v3, va + d*32u);
                mmabf(ot[2*d],   pa[s][0],pa[s][1],pa[s][2],pa[s][3], v0,v1);
                mmabf(ot[2*d+1], pa[s][0],pa[s][1],pa[s][2],pa[s][3], v2,v3);
            }
        }
    }

    // ---- finalize + store ----
    float inv0 = 1.f/l0, inv1 = 1.f/l1;
    int row0 = q0 + wid*16 + (lane >> 2);
    int row1 = row0 + 8;
    bf* o0 = Og + base + (long)row0*DM;
    bf* o1 = Og + base + (long)row1*DM;
    int cb2 = (lane & 3)*2;
#pragma unroll
    for (int d=0; d<8; d++){
        int col = d*8 + cb2;
        *(unsigned*)(o0 + col) = pack_bf2(ot[d][0]*inv0, ot[d][1]*inv0);
        *(unsigned*)(o1 + col) = pack_bf2(ot[d][2]*inv1, ot[d][3]*inv1);
    }
}

// ---------------- embedding + positional encoding ----------------
__global__ void embed_k(const int* __restrict__ tok, const float* __restrict__ emb,
                        float* __restrict__ out)
{
    int t = blockIdx.x;
    int s = t & (SEQ-1);
    int id = tok[t];
    const float* e = emb + (long)id*DM;
    float* o = out + (long)t*DM;
    const float c = -logf(10000.0f) / (float)DM;
    for (int d = threadIdx.x; d < DM; d += blockDim.x) {
        int i2 = d & ~1;
        float ang = (float)s * expf((float)i2 * c);
        float pe = (d & 1) ? cosf(ang) : sinf(ang);
        o[d] = e[d]*32.0f + pe;
    }
}

// ---------------- LayerNorm (f32 in -> bf16 out) ----------------
__global__ void ln_k(const float* __restrict__ x, const float* __restrict__ g,
                     const float* __restrict__ b, bf* __restrict__ out)
{
    long t = blockIdx.x;
    const float4* xr = (const float4*)(x + t*DM);
    float4 v = xr[threadIdx.x];
    float s  = v.x+v.y+v.z+v.w;
    float ss = v.x*v.x+v.y*v.y+v.z*v.z+v.w*v.w;
    s  = blockSum(s);
    ss = blockSum(ss);
    float mean = s * (1.0f/DM);
    float var  = ss * (1.0f/DM) - mean*mean;
    float inv  = rsqrtf(var + 1e-5f);
    float4 gg = ((const float4*)g)[threadIdx.x];
    float4 bb = ((const float4*)b)[threadIdx.x];
    uint2 w;
    w.x = pack_bf2((v.x-mean)*inv*gg.x + bb.x, (v.y-mean)*inv*gg.y + bb.y);
    w.y = pack_bf2((v.z-mean)*inv*gg.z + bb.z, (v.w-mean)*inv*gg.w + bb.w);
    *(uint2*)(out + t*DM + threadIdx.x*4) = w;
}

// ---------------- log_softmax over NV ----------------
__global__ void logsoftmax_k(float* __restrict__ p)
{
    float* r = p + (long)blockIdx.x * NV;
    float mx = -INFINITY;
    for (int d = threadIdx.x; d < NV; d += blockDim.x) mx = fmaxf(mx, r[d]);
    mx = blockMax(mx);
    float sum = 0.f;
    for (int d = threadIdx.x; d < NV; d += blockDim.x) sum += __expf(r[d]-mx);
    sum = blockSum(sum);
    float lse = mx + logf(sum);
    for (int d = threadIdx.x; d < NV; d += blockDim.x) r[d] -= lse;
}

// ---------------- host helpers ----------------
static void gemm(const bf* A, const bf* B, const float* bias, const float* res,
                 void* C, int M, int N, int K, int lda, int ldb, int ldc,
                 int gelu, int outBf,
                 long aob=0, long aoh=0, long bob=0, long boh=0, long biasoh=0,
                 long cob=0, long coh=0, int nh=1, int nz=1)
{
    dim3 grid(N/BN, M/BM, nz);
    gemm_bf<<<grid, 128, GEMM_SMEM>>>(A,B,bias,res,C,M,N,K,lda,ldb,ldc,gelu,outBf,
                                      aob,aoh,bob,boh,biasoh,cob,coh,nh);
}

static void cvt(const float* s, bf* d, long n){
    long blocks = (n/4 + 255)/256;
    cvt_k<<<(unsigned)blocks, 256>>>(s, d, n);
}

static void attention(const bf* Hq, const bf* Hkv,
                      const bf* wqkv, const float* bqkv,
                      const bf* wproj, const float* bproj,
                      float* x, int sameKV,
                      bf* QKV, bf* AO)
{
    bf* Q  = QKV;
    bf* Kb = QKV + (size_t)NTOK*DM;
    if (sameKV) {
        gemm(Hq, wqkv, bqkv, nullptr, QKV, NTOK, DM, DM, DM, DM, DM, 0, 1,
             0, 0, 0, (long)DM*DM, DM, 0, (long)NTOK*DM, 3, 3);
    } else {
        gemm(Hq, wqkv, bqkv, nullptr, Q, NTOK, DM, DM, DM, DM, DM, 0, 1);
        gemm(Hkv, wqkv + (size_t)DM*DM, bqkv + DM, nullptr, Kb,
             NTOK, DM, DM, DM, DM, DM, 0, 1,
             0, 0, 0, (long)DM*DM, DM, 0, (long)NTOK*DM, 2, 2);
    }
    bf* Vb = QKV + (size_t)2*NTOK*DM;
    dim3 fgrid(SEQ/FA_BQ, NB*NHD);
    flash_k<<<fgrid, 256, FA_SMEM>>>(Q, Kb, Vb, AO);
    gemm(AO, wproj, bproj, x, x, NTOK, DM, DM, DM, DM, DM, 0, 0);
}

extern "C" void kernel_launch(void* const* d_in, const int* in_sizes, int n_in,
                              void* d_out, int out_size)
{
    const int*   src        = (const int*)  d_in[0];
    const int*   tgt        = (const int*)  d_in[1];
    const float* emb        = (const float*)d_in[5];
    const float* enc_qkv_w  = (const float*)d_in[6];
    const float* enc_qkv_b  = (const float*)d_in[7];
    const float* enc_proj_w = (const float*)d_in[8];
    const float* enc_proj_b = (const float*)d_in[9];
    const float* enc_ff_w1  = (const float*)d_in[10];
    const float* enc_ff_b1  = (const float*)d_in[11];
    const float* enc_ff_w2  = (const float*)d_in[12];
    const float* enc_ff_b2  = (const float*)d_in[13];
    const float* enc_ln_g   = (const float*)d_in[14];
    const float* enc_ln_b   = (const float*)d_in[15];
    const float* enc_norm_g = (const float*)d_in[16];
    const float* enc_norm_b = (const float*)d_in[17];
    const float* dec_qkv_w  = (const float*)d_in[18];
    const float* dec_qkv_b  = (const float*)d_in[19];
    const float* dec_proj_w = (const float*)d_in[20];
    const float* dec_proj_b = (const float*)d_in[21];
    const float* dec_ff_w1  = (const float*)d_in[22];
    const float* dec_ff_b1  = (const float*)d_in[23];
    const float* dec_ff_w2  = (const float*)d_in[24];
    const float* dec_ff_b2  = (const float*)d_in[25];
    const float* dec_ln_g   = (const float*)d_in[26];
    const float* dec_ln_b   = (const float*)d_in[27];
    const float* dec_norm_g = (const float*)d_in[28];
    const float* dec_norm_b = (const float*)d_in[29];
    const float* gen_w      = (const float*)d_in[30];
    const float* gen_b      = (const float*)d_in[31];
    float* out = (float*)d_out;

    cudaFuncSetAttribute(flash_k, cudaFuncAttributeMaxDynamicSharedMemorySize, FA_SMEM);
    cudaFuncSetAttribute(gemm_bf, cudaFuncAttributeMaxDynamicSharedMemorySize, GEMM_SMEM);

    float *X,*Y;
    bf *Hb,*MEMb,*QKVb,*AOb,*FFb,*W;
    cudaGetSymbolAddress((void**)&X,    g_X);
    cudaGetSymbolAddress((void**)&Y,    g_Y);
    cudaGetSymbolAddress((void**)&Hb,   g_Hb);
    cudaGetSymbolAddress((void**)&MEMb, g_MEMb);
    cudaGetSymbolAddress((void**)&QKVb, g_QKVb);
    cudaGetSymbolAddress((void**)&AOb,  g_AOb);
    cudaGetSymbolAddress((void**)&FFb,  g_FFb);
    cudaGetSymbolAddress((void**)&W,    g_W);

    // ---- one-time (per replay) weight conversion ----
    cvt(enc_qkv_w,  W + O_ENC_QKV,  (long)NLE*3*DM*DM);
    cvt(enc_proj_w, W + O_ENC_PROJ, (long)NLE*DM*DM);
    cvt(enc_ff_w1,  W + O_ENC_FF1,  (long)NLE*DM*HFF);
    cvt(enc_ff_w2,  W + O_ENC_FF2,  (long)NLE*HFF*DM);
    cvt(dec_qkv_w,  W + O_DEC_QKV,  (long)NLD*2*3*DM*DM);
    cvt(dec_proj_w, W + O_DEC_PROJ, (long)NLD*2*DM*DM);
    cvt(dec_ff_w1,  W + O_DEC_FF1,  (long)NLD*DM*HFF);
    cvt(dec_ff_w2,  W + O_DEC_FF2,  (long)NLD*HFF*DM);
    cvt(gen_w,      W + O_GEN,      (long)DM*NV);

    // ---------------- encoder ----------------
    embed_k<<<NTOK,256>>>(src, emb, X);
    for (int l = 0; l < NLE; l++) {
        ln_k<<<NTOK,256>>>(X, enc_ln_g + (size_t)(l*2+0)*DM, enc_ln_b + (size_t)(l*2+0)*DM, Hb);
        attention(Hb, Hb,
                  W + O_ENC_QKV + (long)l*3*DM*DM, enc_qkv_b + (size_t)l*3*DM,
                  W + O_ENC_PROJ + (long)l*DM*DM,  enc_proj_b + (size_t)l*DM,
                  X, 1, QKVb, AOb);
        ln_k<<<NTOK,256>>>(X, enc_ln_g + (size_t)(l*2+1)*DM, enc_ln_b + (size_t)(l*2+1)*DM, Hb);
        gemm(Hb, W + O_ENC_FF1 + (long)l*DM*HFF, enc_ff_b1 + (size_t)l*HFF, nullptr, FFb,
             NTOK, HFF, DM, DM, HFF, HFF, 1, 1);
        gemm(FFb, W + O_ENC_FF2 + (long)l*HFF*DM, enc_ff_b2 + (size_t)l*DM, X, X,
             NTOK, DM, HFF, HFF, DM, DM, 1, 0);
    }
    ln_k<<<NTOK,256>>>(X, enc_norm_g, enc_norm_b, MEMb);

    // ---------------- decoder ----------------
    embed_k<<<NTOK,256>>>(tgt, emb, Y);
    for (int l = 0; l < NLD; l++) {
        ln_k<<<NTOK,256>>>(Y, dec_ln_g + (size_t)(l*3+0)*DM, dec_ln_b + (size_t)(l*3+0)*DM, Hb);
        attention(Hb, Hb,
                  W + O_DEC_QKV + (long)(l*2+0)*3*DM*DM, dec_qkv_b + (size_t)(l*2+0)*3*DM,
                  W + O_DEC_PROJ + (long)(l*2+0)*DM*DM,  dec_proj_b + (size_t)(l*2+0)*DM,
                  Y, 1, QKVb, AOb);
        ln_k<<<NTOK,256>>>(Y, dec_ln_g + (size_t)(l*3+1)*DM, dec_ln_b + (size_t)(l*3+1)*DM, Hb);
        attention(Hb, MEMb,
                  W + O_DEC_QKV + (long)(l*2+1)*3*DM*DM, dec_qkv_b + (size_t)(l*2+1)*3*DM,
                  W + O_DEC_PROJ + (long)(l*2+1)*DM*DM,  dec_proj_b + (size_t)(l*2+1)*DM,
                  Y, 0, QKVb, AOb);
        ln_k<<<NTOK,256>>>(Y, dec_ln_g + (size_t)(l*3+2)*DM, dec_ln_b + (size_t)(l*3+2)*DM, Hb);
        gemm(Hb, W + O_DEC_FF1 + (long)l*DM*HFF, dec_ff_b1 + (size_t)l*HFF, nullptr, FFb,
             NTOK, HFF, DM, DM, HFF, HFF, 1, 1);
        gemm(FFb, W + O_DEC_FF2 + (long)l*HFF*DM, dec_ff_b2 + (size_t)l*DM, Y, Y,
             NTOK, DM, HFF, HFF, DM, DM, 1, 0);
    }
    ln_k<<<NTOK,256>>>(Y, dec_norm_g, dec_norm_b, Hb);

    // ---------------- generator + log_softmax ----------------
    gemm(Hb, W + O_GEN, gen_b, nullptr, out, NTOK, NV, DM, DM, NV, NV, 0, 0);
    logsoftmax_k<<<NTOK,256>>>(out);
}

// round 9
// speedup vs baseline: 11.5018x; 1.7111x over previous
#include <cuda_runtime.h>
#include <cuda_bf16.h>
#include <math.h>

typedef __nv_bfloat16 bf;

// ---------------- problem constants ----------------
#define DM   1024
#define NHD  16
#define DH   64
#define SEQ  1024
#define NB   2
#define NTOK 2048
#define HFF  4096
#define NV   32000
#define NLE  6
#define NLD  6

// ---------------- bf16 weight pool (one-time convert per replay) ----------
#define O_ENC_QKV  0L
#define O_ENC_PROJ 18874368L
#define O_ENC_FF1  25165824L
#define O_ENC_FF2  50331648L
#define O_DEC_QKV  75497472L
#define O_DEC_PROJ 113246208L
#define O_DEC_FF1  125829120L
#define O_DEC_FF2  150994944L
#define O_GEN      176160768L
#define W_TOTAL    208928768L

__device__ bf g_W[W_TOTAL];

// ---------------- scratch ----------------
__device__ float g_X [(size_t)NTOK*DM];
__device__ float g_Y [(size_t)NTOK*DM];
__device__ bf    g_Hb [(size_t)NTOK*DM];
__device__ bf    g_MEMb[(size_t)NTOK*DM];
__device__ bf    g_QKVb[(size_t)3*NTOK*DM];
__device__ bf    g_AOb [(size_t)NTOK*DM];
__device__ bf    g_FFb [(size_t)NTOK*HFF];

// ---------------- low-level helpers ----------------
__device__ __forceinline__ void cp16(void* d, const void* s){
    unsigned sd = (unsigned)__cvta_generic_to_shared(d);
    asm volatile("cp.async.cg.shared.global [%0], [%1], 16;\n" :: "r"(sd), "l"(s));
}
__device__ __forceinline__ void cpcommit(){ asm volatile("cp.async.commit_group;\n"); }
template<int N> __device__ __forceinline__ void cpwait(){
    asm volatile("cp.async.wait_group %0;\n" :: "n"(N));
}
__device__ __forceinline__ unsigned pack_bf2(float a, float b){
    __nv_bfloat162 h = __floats2bfloat162_rn(a, b);
    return *(unsigned*)&h;
}
__device__ __forceinline__ void ldm4(unsigned &a0, unsigned &a1, unsigned &a2, unsigned &a3,
                                     unsigned addr){
    asm volatile("ldmatrix.sync.aligned.m8n8.x4.shared.b16 {%0,%1,%2,%3}, [%4];"
                 : "=r"(a0),"=r"(a1),"=r"(a2),"=r"(a3) : "r"(addr));
}
__device__ __forceinline__ void ldm4t(unsigned &a0, unsigned &a1, unsigned &a2, unsigned &a3,
                                      unsigned addr){
    asm volatile("ldmatrix.sync.aligned.m8n8.x4.trans.shared.b16 {%0,%1,%2,%3}, [%4];"
                 : "=r"(a0),"=r"(a1),"=r"(a2),"=r"(a3) : "r"(addr));
}
__device__ __forceinline__ void mmabf(float* c, unsigned a0, unsigned a1, unsigned a2, unsigned a3,
                                      unsigned b0, unsigned b1){
    asm volatile("mma.sync.aligned.m16n8k16.row.col.f32.bf16.bf16.f32 "
                 "{%0,%1,%2,%3}, {%4,%5,%6,%7}, {%8,%9}, {%0,%1,%2,%3};"
                 : "+f"(c[0]),"+f"(c[1]),"+f"(c[2]),"+f"(c[3])
                 : "r"(a0),"r"(a1),"r"(a2),"r"(a3),"r"(b0),"r"(b1));
}
__device__ __forceinline__ float gelu1(float x){
    return 0.5f*x*(1.f+erff(x*0.70710678f));
}

// ---------------- reductions ----------------
__device__ __forceinline__ float warpSum(float v){
#pragma unroll
    for (int o=16;o>0;o>>=1) v += __shfl_xor_sync(0xffffffffu, v, o);
    return v;
}
__device__ __forceinline__ float warpMax(float v){
#pragma unroll
    for (int o=16;o>0;o>>=1) v = fmaxf(v, __shfl_xor_sync(0xffffffffu, v, o));
    return v;
}
__device__ float blockSum(float v){
    __shared__ float sh[32];
    int lane = threadIdx.x & 31, w = threadIdx.x >> 5;
    v = warpSum(v);
    if (lane==0) sh[w] = v;
    __syncthreads();
    if (w==0){
        float r = (lane < (int)(blockDim.x>>5)) ? sh[lane] : 0.f;
        r = warpSum(r);
        if (lane==0) sh[0] = r;
    }
    __syncthreads();
    float r = sh[0];
    __syncthreads();
    return r;
}
__device__ float blockMax(float v){
    __shared__ float sh[32];
    int lane = threadIdx.x & 31, w = threadIdx.x >> 5;
    v = warpMax(v);
    if (lane==0) sh[w] = v;
    __syncthreads();
    if (w==0){
        float r = (lane < (int)(blockDim.x>>5)) ? sh[lane] : -INFINITY;
        r = warpMax(r);
        if (lane==0) sh[0] = r;
    }
    __syncthreads();
    float r = sh[0];
    __syncthreads();
    return r;
}

// ---------------- f32 -> bf16 converter ----------------
__global__ void cvt_k(const float* __restrict__ s, bf* __restrict__ d, long n){
    long i = ((long)blockIdx.x*blockDim.x + threadIdx.x)*4;
    if (i < n){
        float4 v = *(const float4*)(s+i);
        *(__nv_bfloat162*)(d+i)   = __floats2bfloat162_rn(v.x, v.y);
        *(__nv_bfloat162*)(d+i+2) = __floats2bfloat162_rn(v.z, v.w);
    }
}

// ---------------- bf16 GEMM: mma.sync, 128x128 CTA, 8 warps x 64x32 ------
// High-occupancy design: <=128 regs/thread, 2 CTAs/SM -> 16 warps/SM.
#define BM 128
#define BN 128
#define BK 32
#define ASTR 40      // bf16 elems per A row (80B)
#define BSTR 136     // bf16 elems per B row (272B)
#define NSTAGE 4
#define ATILE (BM*ASTR)   // 5120
#define BTILE (BK*BSTR)   // 4352
#define GEMM_SMEM ((ATILE+BTILE)*NSTAGE*2)   // 75776 bytes

__global__ void __launch_bounds__(256, 2) gemm_ms(
    const bf* __restrict__ A, const bf* __restrict__ B,
    const float* __restrict__ bias, const float* __restrict__ res,
    void* __restrict__ Cv,
    int M, int N, int K, int lda, int ldb, int ldc,
    int doGelu, int outBf,
    long aob, long aoh, long bob, long boh, long biasoh,
    long cob, long coh, int nh)
{
    extern __shared__ __align__(16) unsigned char smraw[];
    bf* As = (bf*)smraw;
    bf* Bs = As + NSTAGE*ATILE;
    unsigned smA = (unsigned)__cvta_generic_to_shared(As);
    unsigned smB = (unsigned)__cvta_generic_to_shared(Bs);

    int z = blockIdx.z, zb = z/nh, zh = z - zb*nh;
    A += zb*aob + zh*aoh;
    B += zb*bob + zh*boh;
    if (bias) bias += zh*biasoh;
    long coff = zb*cob + zh*coh;

    int tid = threadIdx.x;
    int wid = tid >> 5, lane = tid & 31;
    int wm = wid >> 2;          // 0..1: 64-row band
    int wn = wid & 3;           // 0..3: 32-col band
    long row0 = (long)blockIdx.y * BM;
    long col0 = (long)blockIdx.x * BN;

    // cp.async source pointers
    const bf* Ag0 = A + (row0 + (tid>>1))*(long)lda + (tid&1)*16;
    const bf* Bg0 = B + (long)(tid>>3)*ldb + col0 + (tid&7)*16;
    bf* Ad0 = As + (tid>>1)*ASTR + (tid&1)*16;
    bf* Bd0 = Bs + (tid>>3)*BSTR + (tid&7)*16;

    auto issue = [&](int kt, int s){
        const bf* ag = Ag0 + kt*BK;
        bf* ad = Ad0 + s*ATILE;
        cp16(ad,     ag);
        cp16(ad + 8, ag + 8);
        const bf* bg = Bg0 + (long)kt*BK*ldb;
        bf* bd = Bd0 + s*BTILE;
        cp16(bd,     bg);
        cp16(bd + 8, bg + 8);
    };

    float acc[4][4][4];
#pragma unroll
    for (int i=0;i<4;i++)
#pragma unroll
        for (int j=0;j<4;j++)
#pragma unroll
            for (int q=0;q<4;q++) acc[i][j][q] = 0.f;

    unsigned lrow = (unsigned)(lane & 15);
    unsigned lch  = ((unsigned)(lane >> 4)) << 3;

    int KT = K / BK;
    issue(0,0); cpcommit();
    issue(1,1); cpcommit();
    issue(2,2); cpcommit();

    for (int kt = 0; kt < KT; kt++){
        cpwait<2>();
        __syncthreads();
        if (kt+3 < KT) issue(kt+3, (kt+3)&3);
        cpcommit();
        unsigned sa = smA + (unsigned)(kt&3)*ATILE*2u;
        unsigned sb = smB + (unsigned)(kt&3)*BTILE*2u;
#pragma unroll
        for (int kk = 0; kk < BK; kk += 16){
            // A fragments: 4 x m16k16
            unsigned af[4][4];
#pragma unroll
            for (int mi=0;mi<4;mi++){
                unsigned aaddr = sa + ((wm*64u + mi*16u + lrow)*ASTR + kk + lch)*2u;
                ldm4(af[mi][0], af[mi][1], af[mi][2], af[mi][3], aaddr);
            }
            // B fragments + MMAs: 2 x (k16 x n16) -> 4 n8 tiles
#pragma unroll
            for (int ni=0;ni<2;ni++){
                unsigned b0,b1,b2,b3;
                unsigned baddr = sb + ((kk + lrow)*BSTR + wn*32u + ni*16u + lch)*2u;
                ldm4t(b0,b1,b2,b3, baddr);
#pragma unroll
                for (int mi=0;mi<4;mi++){
                    mmabf(acc[mi][2*ni],   af[mi][0],af[mi][1],af[mi][2],af[mi][3], b0,b1);
                    mmabf(acc[mi][2*ni+1], af[mi][0],af[mi][1],af[mi][2],af[mi][3], b2,b3);
                }
            }
        }
    }
    cpwait<0>();

    // ---- epilogue: direct from accumulators ----
    float* C  = (float*)Cv;
    bf*    Cb = (bf*)Cv;
    int rbase = (int)(wm*64) + (lane >> 2);
    int cbase = (int)(wn*32) + (lane & 3)*2;
#pragma unroll
    for (int mi=0;mi<4;mi++){
        long r0 = row0 + rbase + mi*16;
        long r1 = r0 + 8;
#pragma unroll
        for (int nj=0;nj<4;nj++){
            long gn = col0 + cbase + nj*8;
            float v0 = acc[mi][nj][0], v1 = acc[mi][nj][1];
            float v2 = acc[mi][nj][2], v3 = acc[mi][nj][3];
            if (bias){
                float b0 = bias[gn], b1 = bias[gn+1];
                v0 += b0; v1 += b1; v2 += b0; v3 += b1;
            }
            if (doGelu){
                v0 = gelu1(v0); v1 = gelu1(v1); v2 = gelu1(v2); v3 = gelu1(v3);
            }
            if (!outBf){
                if (res){
                    const float2 q0 = *(const float2*)(res + coff + r0*(long)ldc + gn);
                    const float2 q1 = *(const float2*)(res + coff + r1*(long)ldc + gn);
                    v0 += q0.x; v1 += q0.y; v2 += q1.x; v3 += q1.y;
                }
                *(float2*)(C + coff + r0*(long)ldc + gn) = make_float2(v0, v1);
                *(float2*)(C + coff + r1*(long)ldc + gn) = make_float2(v2, v3);
            } else {
                *(unsigned*)(Cb + coff + r0*(long)ldc + gn) = pack_bf2(v0, v1);
                *(unsigned*)(Cb + coff + r1*(long)ldc + gn) = pack_bf2(v2, v3);
            }
        }
    }
}

// ---------------- flash attention: FA2-style, register S/P/O, mma.sync ----
#define FA_BQ  128
#define FA_SMEM 92160

__global__ void __launch_bounds__(256) flash_k(
    const bf* __restrict__ Qg, const bf* __restrict__ Kg,
    const bf* __restrict__ Vg, bf* __restrict__ Og)
{
    extern __shared__ char smc[];
    unsigned smem0 = (unsigned)__cvta_generic_to_shared(smc);
    unsigned smQ = smem0;
    unsigned smK = smem0 + 18432u;
    unsigned smV = smem0 + 18432u + 36864u;
    bf* gQ = (bf*)smc;
    bf* gK = (bf*)(smc + 18432);
    bf* gV = (bf*)(smc + 18432 + 36864);

    int tid = threadIdx.x;
    int wid = tid >> 5, lane = tid & 31;
    int bh = blockIdx.y;
    long base = ((long)(bh >> 4) * SEQ) * DM + (bh & 15) * DH;
    int q0 = blockIdx.x * FA_BQ;

    int r  = tid >> 1;
    int hc = tid & 1;

    {
        const uint4* qs = (const uint4*)(Qg + base + (long)(q0+r)*DM + hc*32);
        uint4* qd = (uint4*)(gQ + r*72 + hc*32);
#pragma unroll
        for (int i=0;i<4;i++) qd[i] = qs[i];
    }

    auto issueKV = [&](int j, int buf){
        const bf* kg = Kg + base + (long)(j*128 + r)*DM + hc*32;
        const bf* vg = Vg + base + (long)(j*128 + r)*DM + hc*32;
        bf* kd = gK + buf*(128*72) + r*72 + hc*32;
        bf* vd = gV + buf*(128*72) + r*72 + hc*32;
#pragma unroll
        for (int i=0;i<4;i++) cp16(kd + 8*i, kg + 8*i);
#pragma unroll
        for (int i=0;i<4;i++) cp16(vd + 8*i, vg + 8*i);
    };

    issueKV(0, 0); cpcommit();
    __syncthreads();

    unsigned lrow = (unsigned)(lane & 15);
    unsigned lch  = ((unsigned)(lane >> 4)) << 3;
    unsigned qa[4][4];
    {
        unsigned qaddr = smQ + ((wid*16u + lrow)*72u + lch)*2u;
#pragma unroll
        for (int s=0;s<4;s++)
            ldm4(qa[s][0], qa[s][1], qa[s][2], qa[s][3], qaddr + s*32u);
    }

    float ot[8][4];
#pragma unroll
    for (int d=0;d<8;d++){ ot[d][0]=0.f; ot[d][1]=0.f; ot[d][2]=0.f; ot[d][3]=0.f; }
    float m0 = -INFINITY, m1 = -INFINITY, l0 = 0.f, l1 = 0.f;

    const int NKV = SEQ/128;
    for (int j = 0; j < NKV; j++){
        int cb = j & 1;
        cpwait<0>();
        __syncthreads();
        if (j+1 < NKV) issueKV(j+1, cb^1);
        cpcommit();

        unsigned kb = smK + (unsigned)cb*18432u;
        unsigned vb = smV + (unsigned)cb*18432u;

        float sc[16][4];
#pragma unroll
        for (int t=0;t<16;t++){ sc[t][0]=0.f; sc[t][1]=0.f; sc[t][2]=0.f; sc[t][3]=0.f; }
#pragma unroll
        for (int g=0; g<8; g++){
            unsigned ka = kb + ((g*16u + lrow)*72u + lch)*2u;
#pragma unroll
            for (int s=0; s<4; s++){
                unsigned k0,k1,k2,k3;
                ldm4(k0,k1,k2,k3, ka + s*32u);
                mmabf(sc[2*g],   qa[s][0],qa[s][1],qa[s][2],qa[s][3], k0,k2);
                mmabf(sc[2*g+1], qa[s][0],qa[s][1],qa[s][2],qa[s][3], k1,k3);
            }
        }

        float mx0 = -INFINITY, mx1 = -INFINITY;
#pragma unroll
        for (int t=0;t<16;t++){
            mx0 = fmaxf(mx0, fmaxf(sc[t][0], sc[t][1]));
            mx1 = fmaxf(mx1, fmaxf(sc[t][2], sc[t][3]));
        }
        mx0 = fmaxf(mx0, __shfl_xor_sync(0xffffffffu, mx0, 1));
        mx0 = fmaxf(mx0, __shfl_xor_sync(0xffffffffu, mx0, 2));
        mx1 = fmaxf(mx1, __shfl_xor_sync(0xffffffffu, mx1, 1));
        mx1 = fmaxf(mx1, __shfl_xor_sync(0xffffffffu, mx1, 2));
        float mn0 = fmaxf(m0, mx0), mn1 = fmaxf(m1, mx1);
        float al0 = __expf(m0 - mn0), al1 = __expf(m1 - mn1);
        float s0 = 0.f, s1 = 0.f;
        unsigned pa[8][4];
#pragma unroll
        for (int t=0;t<8;t++){
            float e00 = __expf(sc[2*t][0]-mn0),   e01 = __expf(sc[2*t][1]-mn0);
            float e10 = __expf(sc[2*t][2]-mn1),   e11 = __expf(sc[2*t][3]-mn1);
            float f00 = __expf(sc[2*t+1][0]-mn0), f01 = __expf(sc[2*t+1][1]-mn0);
            float f10 = __expf(sc[2*t+1][2]-mn1), f11 = __expf(sc[2*t+1][3]-mn1);
            s0 += (e00+e01)+(f00+f01);
            s1 += (e10+e11)+(f10+f11);
            pa[t][0] = pack_bf2(e00,e01);
            pa[t][1] = pack_bf2(e10,e11);
            pa[t][2] = pack_bf2(f00,f01);
            pa[t][3] = pack_bf2(f10,f11);
        }
        s0 += __shfl_xor_sync(0xffffffffu, s0, 1);
        s0 += __shfl_xor_sync(0xffffffffu, s0, 2);
        s1 += __shfl_xor_sync(0xffffffffu, s1, 1);
        s1 += __shfl_xor_sync(0xffffffffu, s1, 2);
        l0 = l0*al0 + s0;
        l1 = l1*al1 + s1;
        m0 = mn0; m1 = mn1;
#pragma unroll
        for (int d=0;d<8;d++){
            ot[d][0]*=al0; ot[d][1]*=al0; ot[d][2]*=al1; ot[d][3]*=al1;
        }

#pragma unroll
        for (int s=0; s<8; s++){
            unsigned va = vb + ((s*16u + lrow)*72u + lch)*2u;
#pragma unroll
            for (int d=0; d<4; d++){
                unsigned v0,v1,v2,v3;
                ldm4t(v0,v1,v2,v3, va + d*32u);
                mmabf(ot[2*d],   pa[s][0],pa[s][1],pa[s][2],pa[s][3], v0,v1);
                mmabf(ot[2*d+1], pa[s][0],pa[s][1],pa[s][2],pa[s][3], v2,v3);
            }
        }
    }

    float inv0 = 1.f/l0, inv1 = 1.f/l1;
    int row0 = q0 + wid*16 + (lane >> 2);
    int row1 = row0 + 8;
    bf* o0 = Og + base + (long)row0*DM;
    bf* o1 = Og + base + (long)row1*DM;
    int cb2 = (lane & 3)*2;
#pragma unroll
    for (int d=0; d<8; d++){
        int col = d*8 + cb2;
        *(unsigned*)(o0 + col) = pack_bf2(ot[d][0]*inv0, ot[d][1]*inv0);
        *(unsigned*)(o1 + col) = pack_bf2(ot[d][2]*inv1, ot[d][3]*inv1);
    }
}

// ---------------- embedding + positional encoding ----------------
__global__ void embed_k(const int* __restrict__ tok, const float* __restrict__ emb,
                        float* __restrict__ out)
{
    int t = blockIdx.x;
    int s = t & (SEQ-1);
    int id = tok[t];
    const float* e = emb + (long)id*DM;
    float* o = out + (long)t*DM;
    const float c = -logf(10000.0f) / (float)DM;
    for (int d = threadIdx.x; d < DM; d += blockDim.x) {
        int i2 = d & ~1;
        float ang = (float)s * expf((float)i2 * c);
        float pe = (d & 1) ? cosf(ang) : sinf(ang);
        o[d] = e[d]*32.0f + pe;
    }
}

// ---------------- LayerNorm (f32 in -> bf16 out) ----------------
__global__ void ln_k(const float* __restrict__ x, const float* __restrict__ g,
                     const float* __restrict__ b, bf* __restrict__ out)
{
    long t = blockIdx.x;
    const float4* xr = (const float4*)(x + t*DM);
    float4 v = xr[threadIdx.x];
    float s  = v.x+v.y+v.z+v.w;
    float ss = v.x*v.x+v.y*v.y+v.z*v.z+v.w*v.w;
    s  = blockSum(s);
    ss = blockSum(ss);
    float mean = s * (1.0f/DM);
    float var  = ss * (1.0f/DM) - mean*mean;
    float inv  = rsqrtf(var + 1e-5f);
    float4 gg = ((const float4*)g)[threadIdx.x];
    float4 bb = ((const float4*)b)[threadIdx.x];
    uint2 w;
    w.x = pack_bf2((v.x-mean)*inv*gg.x + bb.x, (v.y-mean)*inv*gg.y + bb.y);
    w.y = pack_bf2((v.z-mean)*inv*gg.z + bb.z, (v.w-mean)*inv*gg.w + bb.w);
    *(uint2*)(out + t*DM + threadIdx.x*4) = w;
}

// ---------------- log_softmax over NV ----------------
__global__ void logsoftmax_k(float* __restrict__ p)
{
    float* r = p + (long)blockIdx.x * NV;
    float mx = -INFINITY;
    for (int d = threadIdx.x; d < NV; d += blockDim.x) mx = fmaxf(mx, r[d]);
    mx = blockMax(mx);
    float sum = 0.f;
    for (int d = threadIdx.x; d < NV; d += blockDim.x) sum += __expf(r[d]-mx);
    sum = blockSum(sum);
    float lse = mx + logf(sum);
    for (int d = threadIdx.x; d < NV; d += blockDim.x) r[d] -= lse;
}

// ---------------- host helpers ----------------
static void gemm(const bf* A, const bf* B, const float* bias, const float* res,
                 void* C, int M, int N, int K, int lda, int ldb, int ldc,
                 int gelu, int outBf,
                 long aob=0, long aoh=0, long bob=0, long boh=0, long biasoh=0,
                 long cob=0, long coh=0, int nh=1, int nz=1)
{
    dim3 grid(N/BN, M/BM, nz);
    gemm_ms<<<grid, 256, GEMM_SMEM>>>(A,B,bias,res,C,M,N,K,lda,ldb,ldc,gelu,outBf,
                                      aob,aoh,bob,boh,biasoh,cob,coh,nh);
}

static void cvt(const float* s, bf* d, long n){
    long blocks = (n/4 + 255)/256;
    cvt_k<<<(unsigned)blocks, 256>>>(s, d, n);
}

static void attention(const bf* Hq, const bf* Hkv,
                      const bf* wqkv, const float* bqkv,
                      const bf* wproj, const float* bproj,
                      float* x, int sameKV,
                      bf* QKV, bf* AO)
{
    bf* Q  = QKV;
    bf* Kb = QKV + (size_t)NTOK*DM;
    if (sameKV) {
        gemm(Hq, wqkv, bqkv, nullptr, QKV, NTOK, DM, DM, DM, DM, DM, 0, 1,
             0, 0, 0, (long)DM*DM, DM, 0, (long)NTOK*DM, 3, 3);
    } else {
        gemm(Hq, wqkv, bqkv, nullptr, Q, NTOK, DM, DM, DM, DM, DM, 0, 1);
        gemm(Hkv, wqkv + (size_t)DM*DM, bqkv + DM, nullptr, Kb,
             NTOK, DM, DM, DM, DM, DM, 0, 1,
             0, 0, 0, (long)DM*DM, DM, 0, (long)NTOK*DM, 2, 2);
    }
    bf* Vb = QKV + (size_t)2*NTOK*DM;
    dim3 fgrid(SEQ/FA_BQ, NB*NHD);
    flash_k<<<fgrid, 256, FA_SMEM>>>(Q, Kb, Vb, AO);
    gemm(AO, wproj, bproj, x, x, NTOK, DM, DM, DM, DM, DM, 0, 0);
}

extern "C" void kernel_launch(void* const* d_in, const int* in_sizes, int n_in,
                              void* d_out, int out_size)
{
    const int*   src        = (const int*)  d_in[0];
    const int*   tgt        = (const int*)  d_in[1];
    const float* emb        = (const float*)d_in[5];
    const float* enc_qkv_w  = (const float*)d_in[6];
    const float* enc_qkv_b  = (const float*)d_in[7];
    const float* enc_proj_w = (const float*)d_in[8];
    const float* enc_proj_b = (const float*)d_in[9];
    const float* enc_ff_w1  = (const float*)d_in[10];
    const float* enc_ff_b1  = (const float*)d_in[11];
    const float* enc_ff_w2  = (const float*)d_in[12];
    const float* enc_ff_b2  = (const float*)d_in[13];
    const float* enc_ln_g   = (const float*)d_in[14];
    const float* enc_ln_b   = (const float*)d_in[15];
    const float* enc_norm_g = (const float*)d_in[16];
    const float* enc_norm_b = (const float*)d_in[17];
    const float* dec_qkv_w  = (const float*)d_in[18];
    const float* dec_qkv_b  = (const float*)d_in[19];
    const float* dec_proj_w = (const float*)d_in[20];
    const float* dec_proj_b = (const float*)d_in[21];
    const float* dec_ff_w1  = (const float*)d_in[22];
    const float* dec_ff_b1  = (const float*)d_in[23];
    const float* dec_ff_w2  = (const float*)d_in[24];
    const float* dec_ff_b2  = (const float*)d_in[25];
    const float* dec_ln_g   = (const float*)d_in[26];
    const float* dec_ln_b   = (const float*)d_in[27];
    const float* dec_norm_g = (const float*)d_in[28];
    const float* dec_norm_b = (const float*)d_in[29];
    const float* gen_w      = (const float*)d_in[30];
    const float* gen_b      = (const float*)d_in[31];
    float* out = (float*)d_out;

    cudaFuncSetAttribute(flash_k, cudaFuncAttributeMaxDynamicSharedMemorySize, FA_SMEM);
    cudaFuncSetAttribute(gemm_ms, cudaFuncAttributeMaxDynamicSharedMemorySize, GEMM_SMEM);

    float *X,*Y;
    bf *Hb,*MEMb,*QKVb,*AOb,*FFb,*W;
    cudaGetSymbolAddress((void**)&X,    g_X);
    cudaGetSymbolAddress((void**)&Y,    g_Y);
    cudaGetSymbolAddress((void**)&Hb,   g_Hb);
    cudaGetSymbolAddress((void**)&MEMb, g_MEMb);
    cudaGetSymbolAddress((void**)&QKVb, g_QKVb);
    cudaGetSymbolAddress((void**)&AOb,  g_AOb);
    cudaGetSymbolAddress((void**)&FFb,  g_FFb);
    cudaGetSymbolAddress((void**)&W,    g_W);

    // ---- one-time (per replay) weight conversion ----
    cvt(enc_qkv_w,  W + O_ENC_QKV,  (long)NLE*3*DM*DM);
    cvt(enc_proj_w, W + O_ENC_PROJ, (long)NLE*DM*DM);
    cvt(enc_ff_w1,  W + O_ENC_FF1,  (long)NLE*DM*HFF);
    cvt(enc_ff_w2,  W + O_ENC_FF2,  (long)NLE*HFF*DM);
    cvt(dec_qkv_w,  W + O_DEC_QKV,  (long)NLD*2*3*DM*DM);
    cvt(dec_proj_w, W + O_DEC_PROJ, (long)NLD*2*DM*DM);
    cvt(dec_ff_w1,  W + O_DEC_FF1,  (long)NLD*DM*HFF);
    cvt(dec_ff_w2,  W + O_DEC_FF2,  (long)NLD*HFF*DM);
    cvt(gen_w,      W + O_GEN,      (long)DM*NV);

    // ---------------- encoder ----------------
    embed_k<<<NTOK,256>>>(src, emb, X);
    for (int l = 0; l < NLE; l++) {
        ln_k<<<NTOK,256>>>(X, enc_ln_g + (size_t)(l*2+0)*DM, enc_ln_b + (size_t)(l*2+0)*DM, Hb);
        attention(Hb, Hb,
                  W + O_ENC_QKV + (long)l*3*DM*DM, enc_qkv_b + (size_t)l*3*DM,
                  W + O_ENC_PROJ + (long)l*DM*DM,  enc_proj_b + (size_t)l*DM,
                  X, 1, QKVb, AOb);
        ln_k<<<NTOK,256>>>(X, enc_ln_g + (size_t)(l*2+1)*DM, enc_ln_b + (size_t)(l*2+1)*DM, Hb);
        gemm(Hb, W + O_ENC_FF1 + (long)l*DM*HFF, enc_ff_b1 + (size_t)l*HFF, nullptr, FFb,
             NTOK, HFF, DM, DM, HFF, HFF, 1, 1);
        gemm(FFb, W + O_ENC_FF2 + (long)l*HFF*DM, enc_ff_b2 + (size_t)l*DM, X, X,
             NTOK, DM, HFF, HFF, DM, DM, 1, 0);
    }
    ln_k<<<NTOK,256>>>(X, enc_norm_g, enc_norm_b, MEMb);

    // ---------------- decoder ----------------
    embed_k<<<NTOK,256>>>(tgt, emb, Y);
    for (int l = 0; l < NLD; l++) {
        ln_k<<<NTOK,256>>>(Y, dec_ln_g + (size_t)(l*3+0)*DM, dec_ln_b + (size_t)(l*3+0)*DM, Hb);
        attention(Hb, Hb,
                  W + O_DEC_QKV + (long)(l*2+0)*3*DM*DM, dec_qkv_b + (size_t)(l*2+0)*3*DM,
                  W + O_DEC_PROJ + (long)(l*2+0)*DM*DM,  dec_proj_b + (size_t)(l*2+0)*DM,
                  Y, 1, QKVb, AOb);
        ln_k<<<NTOK,256>>>(Y, dec_ln_g + (size_t)(l*3+1)*DM, dec_ln_b + (size_t)(l*3+1)*DM, Hb);
        attention(Hb, MEMb,
                  W + O_DEC_QKV + (long)(l*2+1)*3*DM*DM, dec_qkv_b + (size_t)(l*2+1)*3*DM,
                  W + O_DEC_PROJ + (long)(l*2+1)*DM*DM,  dec_proj_b + (size_t)(l*2+1)*DM,
                  Y, 0, QKVb, AOb);
        ln_k<<<NTOK,256>>>(Y, dec_ln_g + (size_t)(l*3+2)*DM, dec_ln_b + (size_t)(l*3+2)*DM, Hb);
        gemm(Hb, W + O_DEC_FF1 + (long)l*DM*HFF, dec_ff_b1 + (size_t)l*HFF, nullptr, FFb,
             NTOK, HFF, DM, DM, HFF, HFF, 1, 1);
        gemm(FFb, W + O_DEC_FF2 + (long)l*HFF*DM, dec_ff_b2 + (size_t)l*DM, Y, Y,
             NTOK, DM, HFF, HFF, DM, DM, 1, 0);
    }
    ln_k<<<NTOK,256>>>(Y, dec_norm_g, dec_norm_b, Hb);

    // ---------------- generator + log_softmax ----------------
    gemm(Hb, W + O_GEN, gen_b, nullptr, out, NTOK, NV, DM, DM, NV, NV, 0, 0);
    logsoftmax_k<<<NTOK,256>>>(out);
}

// round 12
// speedup vs baseline: 11.5044x; 1.0002x over previous
#include <cuda_runtime.h>
#include <cuda_bf16.h>
#include <math.h>

typedef __nv_bfloat16 bf;

// ---------------- problem constants ----------------
#define DM   1024
#define NHD  16
#define DH   64
#define SEQ  1024
#define NB   2
#define NTOK 2048
#define HFF  4096
#define NV   32000
#define NLE  6
#define NLD  6

// ---------------- bf16 weight pool (one-time convert per replay) ----------
#define O_ENC_QKV  0L
#define O_ENC_PROJ 18874368L
#define O_ENC_FF1  25165824L
#define O_ENC_FF2  50331648L
#define O_DEC_QKV  75497472L
#define O_DEC_PROJ 113246208L
#define O_DEC_FF1  125829120L
#define O_DEC_FF2  150994944L
#define O_GEN      176160768L
#define W_TOTAL    208928768L

__device__ bf g_W[W_TOTAL];

// ---------------- scratch ----------------
__device__ float g_X [(size_t)NTOK*DM];
__device__ float g_Y [(size_t)NTOK*DM];
__device__ bf    g_Hb [(size_t)NTOK*DM];
__device__ bf    g_MEMb[(size_t)NTOK*DM];
__device__ bf    g_QKVb[(size_t)3*NTOK*DM];
__device__ bf    g_AOb [(size_t)NTOK*DM];
__device__ bf    g_FFb [(size_t)NTOK*HFF];

// ---------------- low-level helpers ----------------
__device__ __forceinline__ void cp16(void* d, const void* s){
    unsigned sd = (unsigned)__cvta_generic_to_shared(d);
    asm volatile("cp.async.cg.shared.global [%0], [%1], 16;\n" :: "r"(sd), "l"(s));
}
__device__ __forceinline__ void cpcommit(){ asm volatile("cp.async.commit_group;\n"); }
template<int N> __device__ __forceinline__ void cpwait(){
    asm volatile("cp.async.wait_group %0;\n" :: "n"(N));
}
__device__ __forceinline__ unsigned pack_bf2(float a, float b){
    __nv_bfloat162 h = __floats2bfloat162_rn(a, b);
    return *(unsigned*)&h;
}
__device__ __forceinline__ void ldm4(unsigned &a0, unsigned &a1, unsigned &a2, unsigned &a3,
                                     unsigned addr){
    asm volatile("ldmatrix.sync.aligned.m8n8.x4.shared.b16 {%0,%1,%2,%3}, [%4];"
                 : "=r"(a0),"=r"(a1),"=r"(a2),"=r"(a3) : "r"(addr));
}
__device__ __forceinline__ void ldm4t(unsigned &a0, unsigned &a1, unsigned &a2, unsigned &a3,
                                      unsigned addr){
    asm volatile("ldmatrix.sync.aligned.m8n8.x4.trans.shared.b16 {%0,%1,%2,%3}, [%4];"
                 : "=r"(a0),"=r"(a1),"=r"(a2),"=r"(a3) : "r"(addr));
}
__device__ __forceinline__ void mmabf(float* c, unsigned a0, unsigned a1, unsigned a2, unsigned a3,
                                      unsigned b0, unsigned b1){
    asm volatile("mma.sync.aligned.m16n8k16.row.col.f32.bf16.bf16.f32 "
                 "{%0,%1,%2,%3}, {%4,%5,%6,%7}, {%8,%9}, {%0,%1,%2,%3};"
                 : "+f"(c[0]),"+f"(c[1]),"+f"(c[2]),"+f"(c[3])
                 : "r"(a0),"r"(a1),"r"(a2),"r"(a3),"r"(b0),"r"(b1));
}
__device__ __forceinline__ float gelu1(float x){
    return 0.5f*x*(1.f+erff(x*0.70710678f));
}

// ---------------- reductions ----------------
__device__ __forceinline__ float warpSum(float v){
#pragma unroll
    for (int o=16;o>0;o>>=1) v += __shfl_xor_sync(0xffffffffu, v, o);
    return v;
}
__device__ float blockSum(float v){
    __shared__ float sh[32];
    int lane = threadIdx.x & 31, w = threadIdx.x >> 5;
    v = warpSum(v);
    if (lane==0) sh[w] = v;
    __syncthreads();
    if (w==0){
        float r = (lane < (int)(blockDim.x>>5)) ? sh[lane] : 0.f;
        r = warpSum(r);
        if (lane==0) sh[0] = r;
    }
    __syncthreads();
    float r = sh[0];
    __syncthreads();
    return r;
}

// ---------------- f32 -> bf16 converter ----------------
__global__ void cvt_k(const float* __restrict__ s, bf* __restrict__ d, long n){
    long i = ((long)blockIdx.x*blockDim.x + threadIdx.x)*4;
    if (i < n){
        float4 v = *(const float4*)(s+i);
        *(__nv_bfloat162*)(d+i)   = __floats2bfloat162_rn(v.x, v.y);
        *(__nv_bfloat162*)(d+i+2) = __floats2bfloat162_rn(v.z, v.w);
    }
}

// ---------------- bf16 GEMM: mma.sync, templated CTA M-tile ----------------
// BMT=128: 8 warps x (64x32); BMT=64: 8 warps x (32x32). Both: BN=128, 2 CTA/SM.
#define BN 128
#define BK 32
#define ASTR 40
#define BSTR 136
#define NSTAGE 4
#define BTILE (BK*BSTR)

template<int BMT>
__global__ void __launch_bounds__(256, 2) gemm_ms(
    const bf* __restrict__ A, const bf* __restrict__ B,
    const float* __restrict__ bias, const float* __restrict__ res,
    void* __restrict__ Cv,
    int M, int N, int K, int lda, int ldb, int ldc,
    int doGelu, int outBf,
    long aob, long aoh, long bob, long boh, long biasoh,
    long cob, long coh, int nh)
{
    constexpr int RB = BMT/2;          // rows per warp band
    constexpr int MI = RB/16;          // m16 tiles per warp
    constexpr int ATILE = BMT*ASTR;

    extern __shared__ __align__(16) unsigned char smraw[];
    bf* As = (bf*)smraw;
    bf* Bs = As + NSTAGE*ATILE;
    unsigned smA = (unsigned)__cvta_generic_to_shared(As);
    unsigned smB = (unsigned)__cvta_generic_to_shared(Bs);

    int z = blockIdx.z, zb = z/nh, zh = z - zb*nh;
    A += zb*aob + zh*aoh;
    B += zb*bob + zh*boh;
    if (bias) bias += zh*biasoh;
    long coff = zb*cob + zh*coh;

    int tid = threadIdx.x;
    int wid = tid >> 5, lane = tid & 31;
    int wm = wid >> 2;
    int wn = wid & 3;
    long row0 = (long)blockIdx.y * BMT;
    long col0 = (long)blockIdx.x * BN;

    // A loader mapping
    const bf* Ag0; bf* Ad0;
    if (BMT == 128){
        Ag0 = A + (row0 + (tid>>1))*(long)lda + (tid&1)*16;
        Ad0 = As + (tid>>1)*ASTR + (tid&1)*16;
    } else {
        Ag0 = A + (row0 + (tid>>2))*(long)lda + (tid&3)*8;
        Ad0 = As + (tid>>2)*ASTR + (tid&3)*8;
    }
    const bf* Bg0 = B + (long)(tid>>3)*ldb + col0 + (tid&7)*16;
    bf* Bd0 = Bs + (tid>>3)*BSTR + (tid&7)*16;

    auto issue = [&](int kt, int s){
        const bf* ag = Ag0 + kt*BK;
        bf* ad = Ad0 + s*ATILE;
        if (BMT == 128){
            cp16(ad,     ag);
            cp16(ad + 8, ag + 8);
        } else {
            cp16(ad, ag);
        }
        const bf* bg = Bg0 + (long)kt*BK*ldb;
        bf* bd = Bd0 + s*BTILE;
        cp16(bd,     bg);
        cp16(bd + 8, bg + 8);
    };

    float acc[MI][4][4];
#pragma unroll
    for (int i=0;i<MI;i++)
#pragma unroll
        for (int j=0;j<4;j++)
#pragma unroll
            for (int q=0;q<4;q++) acc[i][j][q] = 0.f;

    unsigned lrow = (unsigned)(lane & 15);
    unsigned lch  = ((unsigned)(lane >> 4)) << 3;

    int KT = K / BK;
    issue(0,0); cpcommit();
    issue(1,1); cpcommit();
    issue(2,2); cpcommit();

    for (int kt = 0; kt < KT; kt++){
        cpwait<2>();
        __syncthreads();
        if (kt+3 < KT) issue(kt+3, (kt+3)&3);
        cpcommit();
        unsigned sa = smA + (unsigned)(kt&3)*ATILE*2u;
        unsigned sb = smB + (unsigned)(kt&3)*BTILE*2u;
#pragma unroll
        for (int kk = 0; kk < BK; kk += 16){
            unsigned af[MI][4];
#pragma unroll
            for (int mi=0;mi<MI;mi++){
                unsigned aaddr = sa + (((unsigned)(wm*RB) + mi*16u + lrow)*ASTR + kk + lch)*2u;
                ldm4(af[mi][0], af[mi][1], af[mi][2], af[mi][3], aaddr);
            }
#pragma unroll
            for (int ni=0;ni<2;ni++){
                unsigned b0,b1,b2,b3;
                unsigned baddr = sb + ((kk + lrow)*BSTR + wn*32u + ni*16u + lch)*2u;
                ldm4t(b0,b1,b2,b3, baddr);
#pragma unroll
                for (int mi=0;mi<MI;mi++){
                    mmabf(acc[mi][2*ni],   af[mi][0],af[mi][1],af[mi][2],af[mi][3], b0,b1);
                    mmabf(acc[mi][2*ni+1], af[mi][0],af[mi][1],af[mi][2],af[mi][3], b2,b3);
                }
            }
        }
    }
    cpwait<0>();

    // ---- epilogue: direct from accumulators ----
    float* C  = (float*)Cv;
    bf*    Cb = (bf*)Cv;
    int rbase = wm*RB + (lane >> 2);
    int cbase = wn*32 + (lane & 3)*2;
#pragma unroll
    for (int mi=0;mi<MI;mi++){
        long r0 = row0 + rbase + mi*16;
        long r1 = r0 + 8;
#pragma unroll
        for (int nj=0;nj<4;nj++){
            long gn = col0 + cbase + nj*8;
            float v0 = acc[mi][nj][0], v1 = acc[mi][nj][1];
            float v2 = acc[mi][nj][2], v3 = acc[mi][nj][3];
            if (bias){
                float b0 = bias[gn], b1 = bias[gn+1];
                v0 += b0; v1 += b1; v2 += b0; v3 += b1;
            }
            if (doGelu){
                v0 = gelu1(v0); v1 = gelu1(v1); v2 = gelu1(v2); v3 = gelu1(v3);
            }
            if (!outBf){
                if (res){
                    const float2 q0 = *(const float2*)(res + coff + r0*(long)ldc + gn);
                    const float2 q1 = *(const float2*)(res + coff + r1*(long)ldc + gn);
                    v0 += q0.x; v1 += q0.y; v2 += q1.x; v3 += q1.y;
                }
                *(float2*)(C + coff + r0*(long)ldc + gn) = make_float2(v0, v1);
                *(float2*)(C + coff + r1*(long)ldc + gn) = make_float2(v2, v3);
            } else {
                *(unsigned*)(Cb + coff + r0*(long)ldc + gn) = pack_bf2(v0, v1);
                *(unsigned*)(Cb + coff + r1*(long)ldc + gn) = pack_bf2(v2, v3);
            }
        }
    }
}

#define GEMM_SMEM128 ((128*ASTR+BTILE)*NSTAGE*2)
#define GEMM_SMEM64  ((64*ASTR+BTILE)*NSTAGE*2)

// ---------------- flash attention: FA2-style, register S/P/O, mma.sync ----
#define FA_BQ  128
#define FA_SMEM 92160

__global__ void __launch_bounds__(256) flash_k(
    const bf* __restrict__ Qg, const bf* __restrict__ Kg,
    const bf* __restrict__ Vg, bf* __restrict__ Og)
{
    extern __shared__ char smc[];
    unsigned smem0 = (unsigned)__cvta_generic_to_shared(smc);
    unsigned smQ = smem0;
    unsigned smK = smem0 + 18432u;
    unsigned smV = smem0 + 18432u + 36864u;
    bf* gQ = (bf*)smc;
    bf* gK = (bf*)(smc + 18432);
    bf* gV = (bf*)(smc + 18432 + 36864);

    int tid = threadIdx.x;
    int wid = tid >> 5, lane = tid & 31;
    int bh = blockIdx.y;
    long base = ((long)(bh >> 4) * SEQ) * DM + (bh & 15) * DH;
    int q0 = blockIdx.x * FA_BQ;

    int r  = tid >> 1;
    int hc = tid & 1;

    {
        const uint4* qs = (const uint4*)(Qg + base + (long)(q0+r)*DM + hc*32);
        uint4* qd = (uint4*)(gQ + r*72 + hc*32);
#pragma unroll
        for (int i=0;i<4;i++) qd[i] = qs[i];
    }

    auto issueKV = [&](int j, int buf){
        const bf* kg = Kg + base + (long)(j*128 + r)*DM + hc*32;
        const bf* vg = Vg + base + (long)(j*128 + r)*DM + hc*32;
        bf* kd = gK + buf*(128*72) + r*72 + hc*32;
        bf* vd = gV + buf*(128*72) + r*72 + hc*32;
#pragma unroll
        for (int i=0;i<4;i++) cp16(kd + 8*i, kg + 8*i);
#pragma unroll
        for (int i=0;i<4;i++) cp16(vd + 8*i, vg + 8*i);
    };

    issueKV(0, 0); cpcommit();
    __syncthreads();

    unsigned lrow = (unsigned)(lane & 15);
    unsigned lch  = ((unsigned)(lane >> 4)) << 3;
    unsigned qa[4][4];
    {
        unsigned qaddr = smQ + ((wid*16u + lrow)*72u + lch)*2u;
#pragma unroll
        for (int s=0;s<4;s++)
            ldm4(qa[s][0], qa[s][1], qa[s][2], qa[s][3], qaddr + s*32u);
    }

    float ot[8][4];
#pragma unroll
    for (int d=0;d<8;d++){ ot[d][0]=0.f; ot[d][1]=0.f; ot[d][2]=0.f; ot[d][3]=0.f; }
    float m0 = -INFINITY, m1 = -INFINITY, l0 = 0.f, l1 = 0.f;

    const int NKV = SEQ/128;
    for (int j = 0; j < NKV; j++){
        int cb = j & 1;
        cpwait<0>();
        __syncthreads();
        if (j+1 < NKV) issueKV(j+1, cb^1);
        cpcommit();

        unsigned kb = smK + (unsigned)cb*18432u;
        unsigned vb = smV + (unsigned)cb*18432u;

        float sc[16][4];
#pragma unroll
        for (int t=0;t<16;t++){ sc[t][0]=0.f; sc[t][1]=0.f; sc[t][2]=0.f; sc[t][3]=0.f; }
#pragma unroll
        for (int g=0; g<8; g++){
            unsigned ka = kb + ((g*16u + lrow)*72u + lch)*2u;
#pragma unroll
            for (int s=0; s<4; s++){
                unsigned k0,k1,k2,k3;
                ldm4(k0,k1,k2,k3, ka + s*32u);
                mmabf(sc[2*g],   qa[s][0],qa[s][1],qa[s][2],qa[s][3], k0,k2);
                mmabf(sc[2*g+1], qa[s][0],qa[s][1],qa[s][2],qa[s][3], k1,k3);
            }
        }

        float mx0 = -INFINITY, mx1 = -INFINITY;
#pragma unroll
        for (int t=0;t<16;t++){
            mx0 = fmaxf(mx0, fmaxf(sc[t][0], sc[t][1]));
            mx1 = fmaxf(mx1, fmaxf(sc[t][2], sc[t][3]));
        }
        mx0 = fmaxf(mx0, __shfl_xor_sync(0xffffffffu, mx0, 1));
        mx0 = fmaxf(mx0, __shfl_xor_sync(0xffffffffu, mx0, 2));
        mx1 = fmaxf(mx1, __shfl_xor_sync(0xffffffffu, mx1, 1));
        mx1 = fmaxf(mx1, __shfl_xor_sync(0xffffffffu, mx1, 2));
        float mn0 = fmaxf(m0, mx0), mn1 = fmaxf(m1, mx1);
        float al0 = __expf(m0 - mn0), al1 = __expf(m1 - mn1);
        float s0 = 0.f, s1 = 0.f;
        unsigned pa[8][4];
#pragma unroll
        for (int t=0;t<8;t++){
            float e00 = __expf(sc[2*t][0]-mn0),   e01 = __expf(sc[2*t][1]-mn0);
            float e10 = __expf(sc[2*t][2]-mn1),   e11 = __expf(sc[2*t][3]-mn1);
            float f00 = __expf(sc[2*t+1][0]-mn0), f01 = __expf(sc[2*t+1][1]-mn0);
            float f10 = __expf(sc[2*t+1][2]-mn1), f11 = __expf(sc[2*t+1][3]-mn1);
            s0 += (e00+e01)+(f00+f01);
            s1 += (e10+e11)+(f10+f11);
            pa[t][0] = pack_bf2(e00,e01);
            pa[t][1] = pack_bf2(e10,e11);
            pa[t][2] = pack_bf2(f00,f01);
            pa[t][3] = pack_bf2(f10,f11);
        }
        s0 += __shfl_xor_sync(0xffffffffu, s0, 1);
        s0 += __shfl_xor_sync(0xffffffffu, s0, 2);
        s1 += __shfl_xor_sync(0xffffffffu, s1, 1);
        s1 += __shfl_xor_sync(0xffffffffu, s1, 2);
        l0 = l0*al0 + s0;
        l1 = l1*al1 + s1;
        m0 = mn0; m1 = mn1;
#pragma unroll
        for (int d=0;d<8;d++){
            ot[d][0]*=al0; ot[d][1]*=al0; ot[d][2]*=al1; ot[d][3]*=al1;
        }

#pragma unroll
        for (int s=0; s<8; s++){
            unsigned va = vb + ((s*16u + lrow)*72u + lch)*2u;
#pragma unroll
            for (int d=0; d<4; d++){
                unsigned v0,v1,v2,v3;
                ldm4t(v0,v1,v2,v3, va + d*32u);
                mmabf(ot[2*d],   pa[s][0],pa[s][1],pa[s][2],pa[s][3], v0,v1);
                mmabf(ot[2*d+1], pa[s][0],pa[s][1],pa[s][2],pa[s][3], v2,v3);
            }
        }
    }

    float inv0 = 1.f/l0, inv1 = 1.f/l1;
    int row0 = q0 + wid*16 + (lane >> 2);
    int row1 = row0 + 8;
    bf* o0 = Og + base + (long)row0*DM;
    bf* o1 = Og + base + (long)row1*DM;
    int cb2 = (lane & 3)*2;
#pragma unroll
    for (int d=0; d<8; d++){
        int col = d*8 + cb2;
        *(unsigned*)(o0 + col) = pack_bf2(ot[d][0]*inv0, ot[d][1]*inv0);
        *(unsigned*)(o1 + col) = pack_bf2(ot[d][2]*inv1, ot[d][3]*inv1);
    }
}

// ---------------- embedding + positional encoding ----------------
__global__ void embed_k(const int* __restrict__ tok, const float* __restrict__ emb,
                        float* __restrict__ out)
{
    int t = blockIdx.x;
    int s = t & (SEQ-1);
    int id = tok[t];
    const float* e = emb + (long)id*DM;
    float* o = out + (long)t*DM;
    const float c = -logf(10000.0f) / (float)DM;
    for (int d = threadIdx.x; d < DM; d += blockDim.x) {
        int i2 = d & ~1;
        float ang = (float)s * expf((float)i2 * c);
        float pe = (d & 1) ? cosf(ang) : sinf(ang);
        o[d] = e[d]*32.0f + pe;
    }
}

// ---------------- LayerNorm (f32 in -> bf16 out) ----------------
__global__ void ln_k(const float* __restrict__ x, const float* __restrict__ g,
                     const float* __restrict__ b, bf* __restrict__ out)
{
    long t = blockIdx.x;
    const float4* xr = (const float4*)(x + t*DM);
    float4 v = xr[threadIdx.x];
    float s  = v.x+v.y+v.z+v.w;
    float ss = v.x*v.x+v.y*v.y+v.z*v.z+v.w*v.w;
    s  = blockSum(s);
    ss = blockSum(ss);
    float mean = s * (1.0f/DM);
    float var  = ss * (1.0f/DM) - mean*mean;
    float inv  = rsqrtf(var + 1e-5f);
    float4 gg = ((const float4*)g)[threadIdx.x];
    float4 bb = ((const float4*)b)[threadIdx.x];
    uint2 w;
    w.x = pack_bf2((v.x-mean)*inv*gg.x + bb.x, (v.y-mean)*inv*gg.y + bb.y);
    w.y = pack_bf2((v.z-mean)*inv*gg.z + bb.z, (v.w-mean)*inv*gg.w + bb.w);
    *(uint2*)(out + t*DM + threadIdx.x*4) = w;
}

// ---------------- log_softmax over NV (online, finite sentinel) ----------
__global__ void logsoftmax_k(float* __restrict__ p)
{
    __shared__ float shm[32], shs[32];
    float* r = p + (long)blockIdx.x * NV;
    int tid = threadIdx.x, lane = tid & 31, w = tid >> 5;

    float m = -3.0e38f, s = 0.f;
    for (int d = tid; d < NV; d += blockDim.x){
        float x = r[d];
        float mn = fmaxf(m, x);
        s = s*__expf(m - mn) + __expf(x - mn);
        m = mn;
    }
#pragma unroll
    for (int o=16;o>0;o>>=1){
        float m2 = __shfl_xor_sync(0xffffffffu, m, o);
        float s2 = __shfl_xor_sync(0xffffffffu, s, o);
        float mn = fmaxf(m, m2);
        s = s*__expf(m-mn) + s2*__expf(m2-mn);
        m = mn;
    }
    if (lane==0){ shm[w] = m; shs[w] = s; }
    __syncthreads();
    if (w==0){
        float mm = (lane < (int)(blockDim.x>>5)) ? shm[lane] : -3.0e38f;
        float ss2 = (lane < (int)(blockDim.x>>5)) ? shs[lane] : 0.f;
#pragma unroll
        for (int o=16;o>0;o>>=1){
            float m2 = __shfl_xor_sync(0xffffffffu, mm, o);
            float s2 = __shfl_xor_sync(0xffffffffu, ss2, o);
            float mn = fmaxf(mm, m2);
            ss2 = ss2*__expf(mm-mn) + s2*__expf(m2-mn);
            mm = mn;
        }
        if (lane==0){ shm[0] = mm; shs[0] = ss2; }
    }
    __syncthreads();
    float lse = shm[0] + logf(shs[0]);
    for (int d = tid; d < NV; d += blockDim.x) r[d] -= lse;
}

// ---------------- host helpers ----------------
static void gemm(const bf* A, const bf* B, const float* bias, const float* res,
                 void* C, int M, int N, int K, int lda, int ldb, int ldc,
                 int gelu, int outBf,
                 long aob=0, long aoh=0, long bob=0, long boh=0, long biasoh=0,
                 long cob=0, long coh=0, int nh=1, int nz=1)
{
    long ctas128 = (long)(N/BN) * (M/128) * nz;
    if (ctas128 < 296){
        dim3 grid(N/BN, M/64, nz);
        gemm_ms<64><<<grid, 256, GEMM_SMEM64>>>(A,B,bias,res,C,M,N,K,lda,ldb,ldc,gelu,outBf,
                                                aob,aoh,bob,boh,biasoh,cob,coh,nh);
    } else {
        dim3 grid(N/BN, M/128, nz);
        gemm_ms<128><<<grid, 256, GEMM_SMEM128>>>(A,B,bias,res,C,M,N,K,lda,ldb,ldc,gelu,outBf,
                                                  aob,aoh,bob,boh,biasoh,cob,coh,nh);
    }
}

static void cvt(const float* s, bf* d, long n){
    long blocks = (n/4 + 255)/256;
    cvt_k<<<(unsigned)blocks, 256>>>(s, d, n);
}

static void attention(const bf* Hq, const bf* Hkv,
                      const bf* wqkv, const float* bqkv,
                      const bf* wproj, const float* bproj,
                      float* x, int sameKV,
                      bf* QKV, bf* AO)
{
    bf* Q  = QKV;
    bf* Kb = QKV + (size_t)NTOK*DM;
    if (sameKV) {
        gemm(Hq, wqkv, bqkv, nullptr, QKV, NTOK, DM, DM, DM, DM, DM, 0, 1,
             0, 0, 0, (long)DM*DM, DM, 0, (long)NTOK*DM, 3, 3);
    } else {
        gemm(Hq, wqkv, bqkv, nullptr, Q, NTOK, DM, DM, DM, DM, DM, 0, 1);
        gemm(Hkv, wqkv + (size_t)DM*DM, bqkv + DM, nullptr, Kb,
             NTOK, DM, DM, DM, DM, DM, 0, 1,
             0, 0, 0, (long)DM*DM, DM, 0, (long)NTOK*DM, 2, 2);
    }
    bf* Vb = QKV + (size_t)2*NTOK*DM;
    dim3 fgrid(SEQ/FA_BQ, NB*NHD);
    flash_k<<<fgrid, 256, FA_SMEM>>>(Q, Kb, Vb, AO);
    gemm(AO, wproj, bproj, x, x, NTOK, DM, DM, DM, DM, DM, 0, 0);
}

extern "C" void kernel_launch(void* const* d_in, const int* in_sizes, int n_in,
                              void* d_out, int out_size)
{
    const int*   src        = (const int*)  d_in[0];
    const int*   tgt        = (const int*)  d_in[1];
    const float* emb        = (const float*)d_in[5];
    const float* enc_qkv_w  = (const float*)d_in[6];
    const float* enc_qkv_b  = (const float*)d_in[7];
    const float* enc_proj_w = (const float*)d_in[8];
    const float* enc_proj_b = (const float*)d_in[9];
    const float* enc_ff_w1  = (const float*)d_in[10];
    const float* enc_ff_b1  = (const float*)d_in[11];
    const float* enc_ff_w2  = (const float*)d_in[12];
    const float* enc_ff_b2  = (const float*)d_in[13];
    const float* enc_ln_g   = (const float*)d_in[14];
    const float* enc_ln_b   = (const float*)d_in[15];
    const float* enc_norm_g = (const float*)d_in[16];
    const float* enc_norm_b = (const float*)d_in[17];
    const float* dec_qkv_w  = (const float*)d_in[18];
    const float* dec_qkv_b  = (const float*)d_in[19];
    const float* dec_proj_w = (const float*)d_in[20];
    const float* dec_proj_b = (const float*)d_in[21];
    const float* dec_ff_w1  = (const float*)d_in[22];
    const float* dec_ff_b1  = (const float*)d_in[23];
    const float* dec_ff_w2  = (const float*)d_in[24];
    const float* dec_ff_b2  = (const float*)d_in[25];
    const float* dec_ln_g   = (const float*)d_in[26];
    const float* dec_ln_b   = (const float*)d_in[27];
    const float* dec_norm_g = (const float*)d_in[28];
    const float* dec_norm_b = (const float*)d_in[29];
    const float* gen_w      = (const float*)d_in[30];
    const float* gen_b      = (const float*)d_in[31];
    float* out = (float*)d_out;

    cudaFuncSetAttribute(flash_k, cudaFuncAttributeMaxDynamicSharedMemorySize, FA_SMEM);
    cudaFuncSetAttribute(gemm_ms<128>, cudaFuncAttributeMaxDynamicSharedMemorySize, GEMM_SMEM128);
    cudaFuncSetAttribute(gemm_ms<64>,  cudaFuncAttributeMaxDynamicSharedMemorySize, GEMM_SMEM64);

    float *X,*Y;
    bf *Hb,*MEMb,*QKVb,*AOb,*FFb,*W;
    cudaGetSymbolAddress((void**)&X,    g_X);
    cudaGetSymbolAddress((void**)&Y,    g_Y);
    cudaGetSymbolAddress((void**)&Hb,   g_Hb);
    cudaGetSymbolAddress((void**)&MEMb, g_MEMb);
    cudaGetSymbolAddress((void**)&QKVb, g_QKVb);
    cudaGetSymbolAddress((void**)&AOb,  g_AOb);
    cudaGetSymbolAddress((void**)&FFb,  g_FFb);
    cudaGetSymbolAddress((void**)&W,    g_W);

    // ---- one-time (per replay) weight conversion ----
    cvt(enc_qkv_w,  W + O_ENC_QKV,  (long)NLE*3*DM*DM);
    cvt(enc_proj_w, W + O_ENC_PROJ, (long)NLE*DM*DM);
    cvt(enc_ff_w1,  W + O_ENC_FF1,  (long)NLE*DM*HFF);
    cvt(enc_ff_w2,  W + O_ENC_FF2,  (long)NLE*HFF*DM);
    cvt(dec_qkv_w,  W + O_DEC_QKV,  (long)NLD*2*3*DM*DM);
    cvt(dec_proj_w, W + O_DEC_PROJ, (long)NLD*2*DM*DM);
    cvt(dec_ff_w1,  W + O_DEC_FF1,  (long)NLD*DM*HFF);
    cvt(dec_ff_w2,  W + O_DEC_FF2,  (long)NLD*HFF*DM);
    cvt(gen_w,      W + O_GEN,      (long)DM*NV);

    // ---------------- encoder ----------------
    embed_k<<<NTOK,256>>>(src, emb, X);
    for (int l = 0; l < NLE; l++) {
        ln_k<<<NTOK,256>>>(X, enc_ln_g + (size_t)(l*2+0)*DM, enc_ln_b + (size_t)(l*2+0)*DM, Hb);
        attention(Hb, Hb,
                  W + O_ENC_QKV + (long)l*3*DM*DM, enc_qkv_b + (size_t)l*3*DM,
                  W + O_ENC_PROJ + (long)l*DM*DM,  enc_proj_b + (size_t)l*DM,
                  X, 1, QKVb, AOb);
        ln_k<<<NTOK,256>>>(X, enc_ln_g + (size_t)(l*2+1)*DM, enc_ln_b + (size_t)(l*2+1)*DM, Hb);
        gemm(Hb, W + O_ENC_FF1 + (long)l*DM*HFF, enc_ff_b1 + (size_t)l*HFF, nullptr, FFb,
             NTOK, HFF, DM, DM, HFF, HFF, 1, 1);
        gemm(FFb, W + O_ENC_FF2 + (long)l*HFF*DM, enc_ff_b2 + (size_t)l*DM, X, X,
             NTOK, DM, HFF, HFF, DM, DM, 1, 0);
    }
    ln_k<<<NTOK,256>>>(X, enc_norm_g, enc_norm_b, MEMb);

    // ---------------- decoder ----------------
    embed_k<<<NTOK,256>>>(tgt, emb, Y);
    for (int l = 0; l < NLD; l++) {
        ln_k<<<NTOK,256>>>(Y, dec_ln_g + (size_t)(l*3+0)*DM, dec_ln_b + (size_t)(l*3+0)*DM, Hb);
        attention(Hb, Hb,
                  W + O_DEC_QKV + (long)(l*2+0)*3*DM*DM, dec_qkv_b + (size_t)(l*2+0)*3*DM,
                  W + O_DEC_PROJ + (long)(l*2+0)*DM*DM,  dec_proj_b + (size_t)(l*2+0)*DM,
                  Y, 1, QKVb, AOb);
        ln_k<<<NTOK,256>>>(Y, dec_ln_g + (size_t)(l*3+1)*DM, dec_ln_b + (size_t)(l*3+1)*DM, Hb);
        attention(Hb, MEMb,
                  W + O_DEC_QKV + (long)(l*2+1)*3*DM*DM, dec_qkv_b + (size_t)(l*2+1)*3*DM,
                  W + O_DEC_PROJ + (long)(l*2+1)*DM*DM,  dec_proj_b + (size_t)(l*2+1)*DM,
                  Y, 0, QKVb, AOb);
        ln_k<<<NTOK,256>>>(Y, dec_ln_g + (size_t)(l*3+2)*DM, dec_ln_b + (size_t)(l*3+2)*DM, Hb);
        gemm(Hb, W + O_DEC_FF1 + (long)l*DM*HFF, dec_ff_b1 + (size_t)l*HFF, nullptr, FFb,
             NTOK, HFF, DM, DM, HFF, HFF, 1, 1);
        gemm(FFb, W + O_DEC_FF2 + (long)l*HFF*DM, dec_ff_b2 + (size_t)l*DM, Y, Y,
             NTOK, DM, HFF, HFF, DM, DM, 1, 0);
    }
    ln_k<<<NTOK,256>>>(Y, dec_norm_g, dec_norm_b, Hb);

    // ---------------- generator + log_softmax ----------------
    gemm(Hb, W + O_GEN, gen_b, nullptr, out, NTOK, NV, DM, DM, NV, NV, 0, 0);
    logsoftmax_k<<<NTOK,256>>>(out);
}

// round 13
// speedup vs baseline: 11.9773x; 1.0411x over previous
#include <cuda_runtime.h>
#include <cuda_bf16.h>
#include <math.h>

typedef __nv_bfloat16 bf;

// ---------------- problem constants ----------------
#define DM   1024
#define NHD  16
#define DH   64
#define SEQ  1024
#define NB   2
#define NTOK 2048
#define HFF  4096
#define NV   32000
#define NLE  6
#define NLD  6

// ---------------- bf16 weight pool (one-time convert per replay) ----------
#define O_ENC_QKV  0L
#define O_ENC_PROJ 18874368L
#define O_ENC_FF1  25165824L
#define O_ENC_FF2  50331648L
#define O_DEC_QKV  75497472L
#define O_DEC_PROJ 113246208L
#define O_DEC_FF1  125829120L
#define O_DEC_FF2  150994944L
#define O_GEN      176160768L
#define W_TOTAL    208928768L

__device__ bf g_W[W_TOTAL];

// ---------------- scratch ----------------
__device__ float g_X [(size_t)NTOK*DM];
__device__ float g_Y [(size_t)NTOK*DM];
__device__ bf    g_Hb [(size_t)NTOK*DM];
__device__ bf    g_MEMb[(size_t)NTOK*DM];
__device__ bf    g_QKVb[(size_t)3*NTOK*DM];
__device__ bf    g_AOb [(size_t)NTOK*DM];
__device__ bf    g_FFb [(size_t)NTOK*HFF];

// ---------------- low-level helpers ----------------
__device__ __forceinline__ void cp16(void* d, const void* s){
    unsigned sd = (unsigned)__cvta_generic_to_shared(d);
    asm volatile("cp.async.cg.shared.global [%0], [%1], 16;\n" :: "r"(sd), "l"(s));
}
__device__ __forceinline__ void cpcommit(){ asm volatile("cp.async.commit_group;\n"); }
template<int N> __device__ __forceinline__ void cpwait(){
    asm volatile("cp.async.wait_group %0;\n" :: "n"(N));
}
__device__ __forceinline__ unsigned pack_bf2(float a, float b){
    __nv_bfloat162 h = __floats2bfloat162_rn(a, b);
    return *(unsigned*)&h;
}
__device__ __forceinline__ void ldm4(unsigned &a0, unsigned &a1, unsigned &a2, unsigned &a3,
                                     unsigned addr){
    asm volatile("ldmatrix.sync.aligned.m8n8.x4.shared.b16 {%0,%1,%2,%3}, [%4];"
                 : "=r"(a0),"=r"(a1),"=r"(a2),"=r"(a3) : "r"(addr));
}
__device__ __forceinline__ void ldm4t(unsigned &a0, unsigned &a1, unsigned &a2, unsigned &a3,
                                      unsigned addr){
    asm volatile("ldmatrix.sync.aligned.m8n8.x4.trans.shared.b16 {%0,%1,%2,%3}, [%4];"
                 : "=r"(a0),"=r"(a1),"=r"(a2),"=r"(a3) : "r"(addr));
}
__device__ __forceinline__ void mmabf(float* c, unsigned a0, unsigned a1, unsigned a2, unsigned a3,
                                      unsigned b0, unsigned b1){
    asm volatile("mma.sync.aligned.m16n8k16.row.col.f32.bf16.bf16.f32 "
                 "{%0,%1,%2,%3}, {%4,%5,%6,%7}, {%8,%9}, {%0,%1,%2,%3};"
                 : "+f"(c[0]),"+f"(c[1]),"+f"(c[2]),"+f"(c[3])
                 : "r"(a0),"r"(a1),"r"(a2),"r"(a3),"r"(b0),"r"(b1));
}
__device__ __forceinline__ float gelu1(float x){
    return 0.5f*x*(1.f+erff(x*0.70710678f));
}

// ---------------- reductions ----------------
__device__ __forceinline__ float warpSum(float v){
#pragma unroll
    for (int o=16;o>0;o>>=1) v += __shfl_xor_sync(0xffffffffu, v, o);
    return v;
}

// ---------------- f32 -> bf16 converter ----------------
__global__ void cvt_k(const float* __restrict__ s, bf* __restrict__ d, long n){
    long i = ((long)blockIdx.x*blockDim.x + threadIdx.x)*4;
    if (i < n){
        float4 v = *(const float4*)(s+i);
        *(__nv_bfloat162*)(d+i)   = __floats2bfloat162_rn(v.x, v.y);
        *(__nv_bfloat162*)(d+i+2) = __floats2bfloat162_rn(v.z, v.w);
    }
}

// ---------------- bf16 GEMM: mma.sync, templated CTA M-tile ----------------
#define BN 128
#define BK 32
#define ASTR 40
#define BSTR 136
#define NSTAGE 4
#define BTILE (BK*BSTR)

template<int BMT>
__global__ void __launch_bounds__(256, 2) gemm_ms(
    const bf* __restrict__ A, const bf* __restrict__ B,
    const float* __restrict__ bias, const float* __restrict__ res,
    void* __restrict__ Cv,
    int M, int N, int K, int lda, int ldb, int ldc,
    int doGelu, int outBf,
    long aob, long aoh, long bob, long boh, long biasoh,
    long cob, long coh, int nh)
{
    constexpr int RB = BMT/2;
    constexpr int MI = RB/16;
    constexpr int ATILE = BMT*ASTR;

    extern __shared__ __align__(16) unsigned char smraw[];
    bf* As = (bf*)smraw;
    bf* Bs = As + NSTAGE*ATILE;
    unsigned smA = (unsigned)__cvta_generic_to_shared(As);
    unsigned smB = (unsigned)__cvta_generic_to_shared(Bs);

    int z = blockIdx.z, zb = z/nh, zh = z - zb*nh;
    A += zb*aob + zh*aoh;
    B += zb*bob + zh*boh;
    if (bias) bias += zh*biasoh;
    long coff = zb*cob + zh*coh;

    int tid = threadIdx.x;
    int wid = tid >> 5, lane = tid & 31;
    int wm = wid >> 2;
    int wn = wid & 3;
    long row0 = (long)blockIdx.y * BMT;
    long col0 = (long)blockIdx.x * BN;

    const bf* Ag0; bf* Ad0;
    if (BMT == 128){
        Ag0 = A + (row0 + (tid>>1))*(long)lda + (tid&1)*16;
        Ad0 = As + (tid>>1)*ASTR + (tid&1)*16;
    } else {
        Ag0 = A + (row0 + (tid>>2))*(long)lda + (tid&3)*8;
        Ad0 = As + (tid>>2)*ASTR + (tid&3)*8;
    }
    const bf* Bg0 = B + (long)(tid>>3)*ldb + col0 + (tid&7)*16;
    bf* Bd0 = Bs + (tid>>3)*BSTR + (tid&7)*16;

    auto issue = [&](int kt, int s){
        const bf* ag = Ag0 + kt*BK;
        bf* ad = Ad0 + s*ATILE;
        if (BMT == 128){
            cp16(ad,     ag);
            cp16(ad + 8, ag + 8);
        } else {
            cp16(ad, ag);
        }
        const bf* bg = Bg0 + (long)kt*BK*ldb;
        bf* bd = Bd0 + s*BTILE;
        cp16(bd,     bg);
        cp16(bd + 8, bg + 8);
    };

    float acc[MI][4][4];
#pragma unroll
    for (int i=0;i<MI;i++)
#pragma unroll
        for (int j=0;j<4;j++)
#pragma unroll
            for (int q=0;q<4;q++) acc[i][j][q] = 0.f;

    unsigned lrow = (unsigned)(lane & 15);
    unsigned lch  = ((unsigned)(lane >> 4)) << 3;

    int KT = K / BK;
    issue(0,0); cpcommit();
    issue(1,1); cpcommit();
    issue(2,2); cpcommit();

    for (int kt = 0; kt < KT; kt++){
        cpwait<2>();
        __syncthreads();
        if (kt+3 < KT) issue(kt+3, (kt+3)&3);
        cpcommit();
        unsigned sa = smA + (unsigned)(kt&3)*ATILE*2u;
        unsigned sb = smB + (unsigned)(kt&3)*BTILE*2u;
#pragma unroll
        for (int kk = 0; kk < BK; kk += 16){
            unsigned af[MI][4];
#pragma unroll
            for (int mi=0;mi<MI;mi++){
                unsigned aaddr = sa + (((unsigned)(wm*RB) + mi*16u + lrow)*ASTR + kk + lch)*2u;
                ldm4(af[mi][0], af[mi][1], af[mi][2], af[mi][3], aaddr);
            }
#pragma unroll
            for (int ni=0;ni<2;ni++){
                unsigned b0,b1,b2,b3;
                unsigned baddr = sb + ((kk + lrow)*BSTR + wn*32u + ni*16u + lch)*2u;
                ldm4t(b0,b1,b2,b3, baddr);
#pragma unroll
                for (int mi=0;mi<MI;mi++){
                    mmabf(acc[mi][2*ni],   af[mi][0],af[mi][1],af[mi][2],af[mi][3], b0,b1);
                    mmabf(acc[mi][2*ni+1], af[mi][0],af[mi][1],af[mi][2],af[mi][3], b2,b3);
                }
            }
        }
    }
    cpwait<0>();

    float* C  = (float*)Cv;
    bf*    Cb = (bf*)Cv;
    int rbase = wm*RB + (lane >> 2);
    int cbase = wn*32 + (lane & 3)*2;
#pragma unroll
    for (int mi=0;mi<MI;mi++){
        long r0 = row0 + rbase + mi*16;
        long r1 = r0 + 8;
#pragma unroll
        for (int nj=0;nj<4;nj++){
            long gn = col0 + cbase + nj*8;
            float v0 = acc[mi][nj][0], v1 = acc[mi][nj][1];
            float v2 = acc[mi][nj][2], v3 = acc[mi][nj][3];
            if (bias){
                float b0 = bias[gn], b1 = bias[gn+1];
                v0 += b0; v1 += b1; v2 += b0; v3 += b1;
            }
            if (doGelu){
                v0 = gelu1(v0); v1 = gelu1(v1); v2 = gelu1(v2); v3 = gelu1(v3);
            }
            if (!outBf){
                if (res){
                    const float2 q0 = *(const float2*)(res + coff + r0*(long)ldc + gn);
                    const float2 q1 = *(const float2*)(res + coff + r1*(long)ldc + gn);
                    v0 += q0.x; v1 += q0.y; v2 += q1.x; v3 += q1.y;
                }
                *(float2*)(C + coff + r0*(long)ldc + gn) = make_float2(v0, v1);
                *(float2*)(C + coff + r1*(long)ldc + gn) = make_float2(v2, v3);
            } else {
                *(unsigned*)(Cb + coff + r0*(long)ldc + gn) = pack_bf2(v0, v1);
                *(unsigned*)(Cb + coff + r1*(long)ldc + gn) = pack_bf2(v2, v3);
            }
        }
    }
}

#define GEMM_SMEM128 ((128*ASTR+BTILE)*NSTAGE*2)
#define GEMM_SMEM64  ((64*ASTR+BTILE)*NSTAGE*2)

// ---------------- flash attention: 64-row KV tiles, 2 CTAs/SM ------------
// smem: Q 128x72 (18432B) + K dbl 2x64x72 (18432B) + V dbl (18432B) = 55296B
#define FA_BQ  128
#define FA_SMEM 55296

__global__ void __launch_bounds__(256, 2) flash_k(
    const bf* __restrict__ Qg, const bf* __restrict__ Kg,
    const bf* __restrict__ Vg, bf* __restrict__ Og)
{
    extern __shared__ char smc[];
    unsigned smem0 = (unsigned)__cvta_generic_to_shared(smc);
    unsigned smQ = smem0;
    unsigned smK = smem0 + 18432u;
    unsigned smV = smem0 + 18432u + 18432u;
    bf* gQ = (bf*)smc;
    bf* gK = (bf*)(smc + 18432);
    bf* gV = (bf*)(smc + 18432 + 18432);

    int tid = threadIdx.x;
    int wid = tid >> 5, lane = tid & 31;
    int bh = blockIdx.y;
    long base = ((long)(bh >> 4) * SEQ) * DM + (bh & 15) * DH;
    int q0 = blockIdx.x * FA_BQ;

    // Q loader: 128 rows, 2 threads/row
    {
        int r  = tid >> 1;
        int hc = tid & 1;
        const uint4* qs = (const uint4*)(Qg + base + (long)(q0+r)*DM + hc*32);
        uint4* qd = (uint4*)(gQ + r*72 + hc*32);
#pragma unroll
        for (int i=0;i<4;i++) qd[i] = qs[i];
    }

    // KV loader: 64 rows x 64 cols, 4 threads/row, 1 cp16 each per K and V
    int kr = tid >> 2;
    int kc = (tid & 3)*16;
    auto issueKV = [&](int j, int buf){
        long goff = base + (long)(j*64 + kr)*DM + kc;
        bf* kd = gK + buf*(64*72) + kr*72 + kc;
        bf* vd = gV + buf*(64*72) + kr*72 + kc;
        cp16(kd,     Kg + goff);
        cp16(kd + 8, Kg + goff + 8);
        cp16(vd,     Vg + goff);
        cp16(vd + 8, Vg + goff + 8);
    };

    issueKV(0, 0); cpcommit();
    __syncthreads();

    unsigned lrow = (unsigned)(lane & 15);
    unsigned lch  = ((unsigned)(lane >> 4)) << 3;
    unsigned qa[4][4];
    {
        unsigned qaddr = smQ + ((wid*16u + lrow)*72u + lch)*2u;
#pragma unroll
        for (int s=0;s<4;s++)
            ldm4(qa[s][0], qa[s][1], qa[s][2], qa[s][3], qaddr + s*32u);
    }

    float ot[8][4];
#pragma unroll
    for (int d=0;d<8;d++){ ot[d][0]=0.f; ot[d][1]=0.f; ot[d][2]=0.f; ot[d][3]=0.f; }
    float m0 = -INFINITY, m1 = -INFINITY, l0 = 0.f, l1 = 0.f;

    const int NKV = SEQ/64;
    for (int j = 0; j < NKV; j++){
        int cb = j & 1;
        cpwait<0>();
        __syncthreads();
        if (j+1 < NKV) issueKV(j+1, cb^1);
        cpcommit();

        unsigned kb = smK + (unsigned)cb*9216u;
        unsigned vb = smV + (unsigned)cb*9216u;

        // ---- S = Q(16x64) @ K^T(64x64) per warp, in registers ----
        float sc[8][4];
#pragma unroll
        for (int t=0;t<8;t++){ sc[t][0]=0.f; sc[t][1]=0.f; sc[t][2]=0.f; sc[t][3]=0.f; }
#pragma unroll
        for (int g=0; g<4; g++){
            unsigned ka = kb + ((g*16u + lrow)*72u + lch)*2u;
#pragma unroll
            for (int s=0; s<4; s++){
                unsigned k0,k1,k2,k3;
                ldm4(k0,k1,k2,k3, ka + s*32u);
                mmabf(sc[2*g],   qa[s][0],qa[s][1],qa[s][2],qa[s][3], k0,k2);
                mmabf(sc[2*g+1], qa[s][0],qa[s][1],qa[s][2],qa[s][3], k1,k3);
            }
        }

        // ---- online softmax ----
        float mx0 = -INFINITY, mx1 = -INFINITY;
#pragma unroll
        for (int t=0;t<8;t++){
            mx0 = fmaxf(mx0, fmaxf(sc[t][0], sc[t][1]));
            mx1 = fmaxf(mx1, fmaxf(sc[t][2], sc[t][3]));
        }
        mx0 = fmaxf(mx0, __shfl_xor_sync(0xffffffffu, mx0, 1));
        mx0 = fmaxf(mx0, __shfl_xor_sync(0xffffffffu, mx0, 2));
        mx1 = fmaxf(mx1, __shfl_xor_sync(0xffffffffu, mx1, 1));
        mx1 = fmaxf(mx1, __shfl_xor_sync(0xffffffffu, mx1, 2));
        float mn0 = fmaxf(m0, mx0), mn1 = fmaxf(m1, mx1);
        float al0 = __expf(m0 - mn0), al1 = __expf(m1 - mn1);
        float s0 = 0.f, s1 = 0.f;
        unsigned pa[4][4];
#pragma unroll
        for (int t=0;t<4;t++){
            float e00 = __expf(sc[2*t][0]-mn0),   e01 = __expf(sc[2*t][1]-mn0);
            float e10 = __expf(sc[2*t][2]-mn1),   e11 = __expf(sc[2*t][3]-mn1);
            float f00 = __expf(sc[2*t+1][0]-mn0), f01 = __expf(sc[2*t+1][1]-mn0);
            float f10 = __expf(sc[2*t+1][2]-mn1), f11 = __expf(sc[2*t+1][3]-mn1);
            s0 += (e00+e01)+(f00+f01);
            s1 += (e10+e11)+(f10+f11);
            pa[t][0] = pack_bf2(e00,e01);
            pa[t][1] = pack_bf2(e10,e11);
            pa[t][2] = pack_bf2(f00,f01);
            pa[t][3] = pack_bf2(f10,f11);
        }
        s0 += __shfl_xor_sync(0xffffffffu, s0, 1);
        s0 += __shfl_xor_sync(0xffffffffu, s0, 2);
        s1 += __shfl_xor_sync(0xffffffffu, s1, 1);
        s1 += __shfl_xor_sync(0xffffffffu, s1, 2);
        l0 = l0*al0 + s0;
        l1 = l1*al1 + s1;
        m0 = mn0; m1 = mn1;
#pragma unroll
        for (int d=0;d<8;d++){
            ot[d][0]*=al0; ot[d][1]*=al0; ot[d][2]*=al1; ot[d][3]*=al1;
        }

        // ---- O += P(16x64) @ V(64x64) ----
#pragma unroll
        for (int s=0; s<4; s++){
            unsigned va = vb + ((s*16u + lrow)*72u + lch)*2u;
#pragma unroll
            for (int d=0; d<4; d++){
                unsigned v0,v1,v2,v3;
                ldm4t(v0,v1,v2,v3, va + d*32u);
                mmabf(ot[2*d],   pa[s][0],pa[s][1],pa[s][2],pa[s][3], v0,v1);
                mmabf(ot[2*d+1], pa[s][0],pa[s][1],pa[s][2],pa[s][3], v2,v3);
            }
        }
    }

    float inv0 = 1.f/l0, inv1 = 1.f/l1;
    int row0 = q0 + wid*16 + (lane >> 2);
    int row1 = row0 + 8;
    bf* o0 = Og + base + (long)row0*DM;
    bf* o1 = Og + base + (long)row1*DM;
    int cb2 = (lane & 3)*2;
#pragma unroll
    for (int d=0; d<8; d++){
        int col = d*8 + cb2;
        *(unsigned*)(o0 + col) = pack_bf2(ot[d][0]*inv0, ot[d][1]*inv0);
        *(unsigned*)(o1 + col) = pack_bf2(ot[d][2]*inv1, ot[d][3]*inv1);
    }
}

// ---------------- embedding + positional encoding ----------------
__global__ void embed_k(const int* __restrict__ tok, const float* __restrict__ emb,
                        float* __restrict__ out)
{
    int t = blockIdx.x;
    int s = t & (SEQ-1);
    int id = tok[t];
    const float* e = emb + (long)id*DM;
    float* o = out + (long)t*DM;
    const float c = -logf(10000.0f) / (float)DM;
    for (int d = threadIdx.x; d < DM; d += blockDim.x) {
        int i2 = d & ~1;
        float ang = (float)s * expf((float)i2 * c);
        float pe = (d & 1) ? cosf(ang) : sinf(ang);
        o[d] = e[d]*32.0f + pe;
    }
}

// ---------------- LayerNorm: warp-per-token (f32 in -> bf16 out) ----------
__global__ void ln_k(const float* __restrict__ x, const float* __restrict__ g,
                     const float* __restrict__ b, bf* __restrict__ out)
{
    int lane = threadIdx.x & 31, w = threadIdx.x >> 5;
    long t = (long)blockIdx.x*8 + w;
    const float4* xr = (const float4*)(x + t*DM);
    float4 v[8];
    float s = 0.f, ss = 0.f;
#pragma unroll
    for (int i=0;i<8;i++){
        v[i] = xr[lane + i*32];
        s  += v[i].x+v[i].y+v[i].z+v[i].w;
        ss += v[i].x*v[i].x+v[i].y*v[i].y+v[i].z*v[i].z+v[i].w*v[i].w;
    }
    s  = warpSum(s);
    ss = warpSum(ss);
    float mean = s * (1.0f/DM);
    float var  = ss * (1.0f/DM) - mean*mean;
    float inv  = rsqrtf(var + 1e-5f);
    uint2* o = (uint2*)(out + t*DM);
#pragma unroll
    for (int i=0;i<8;i++){
        float4 gg = ((const float4*)g)[lane + i*32];
        float4 bb = ((const float4*)b)[lane + i*32];
        uint2 wv;
        wv.x = pack_bf2((v[i].x-mean)*inv*gg.x + bb.x, (v[i].y-mean)*inv*gg.y + bb.y);
        wv.y = pack_bf2((v[i].z-mean)*inv*gg.z + bb.z, (v[i].w-mean)*inv*gg.w + bb.w);
        o[lane + i*32] = wv;
    }
}

// ---------------- log_softmax over NV (online, finite sentinel) ----------
__global__ void logsoftmax_k(float* __restrict__ p)
{
    __shared__ float shm[32], shs[32];
    float* r = p + (long)blockIdx.x * NV;
    int tid = threadIdx.x, lane = tid & 31, w = tid >> 5;

    float m = -3.0e38f, s = 0.f;
    for (int d = tid; d < NV; d += blockDim.x){
        float x = r[d];
        float mn = fmaxf(m, x);
        s = s*__expf(m - mn) + __expf(x - mn);
        m = mn;
    }
#pragma unroll
    for (int o=16;o>0;o>>=1){
        float m2 = __shfl_xor_sync(0xffffffffu, m, o);
        float s2 = __shfl_xor_sync(0xffffffffu, s, o);
        float mn = fmaxf(m, m2);
        s = s*__expf(m-mn) + s2*__expf(m2-mn);
        m = mn;
    }
    if (lane==0){ shm[w] = m; shs[w] = s; }
    __syncthreads();
    if (w==0){
        float mm = (lane < (int)(blockDim.x>>5)) ? shm[lane] : -3.0e38f;
        float ss2 = (lane < (int)(blockDim.x>>5)) ? shs[lane] : 0.f;
#pragma unroll
        for (int o=16;o>0;o>>=1){
            float m2 = __shfl_xor_sync(0xffffffffu, mm, o);
            float s2 = __shfl_xor_sync(0xffffffffu, ss2, o);
            float mn = fmaxf(mm, m2);
            ss2 = ss2*__expf(mm-mn) + s2*__expf(m2-mn);
            mm = mn;
        }
        if (lane==0){ shm[0] = mm; shs[0] = ss2; }
    }
    __syncthreads();
    float lse = shm[0] + logf(shs[0]);
    for (int d = tid; d < NV; d += blockDim.x) r[d] -= lse;
}

// ---------------- host helpers ----------------
static void gemm(const bf* A, const bf* B, const float* bias, const float* res,
                 void* C, int M, int N, int K, int lda, int ldb, int ldc,
                 int gelu, int outBf,
                 long aob=0, long aoh=0, long bob=0, long boh=0, long biasoh=0,
                 long cob=0, long coh=0, int nh=1, int nz=1)
{
    dim3 grid(N/BN, M/128, nz);
    gemm_ms<128><<<grid, 256, GEMM_SMEM128>>>(A,B,bias,res,C,M,N,K,lda,ldb,ldc,gelu,outBf,
                                              aob,aoh,bob,boh,biasoh,cob,coh,nh);
}

static void cvt(const float* s, bf* d, long n){
    long blocks = (n/4 + 255)/256;
    cvt_k<<<(unsigned)blocks, 256>>>(s, d, n);
}

static void attention(const bf* Hq, const bf* Hkv,
                      const bf* wqkv, const float* bqkv,
                      const bf* wproj, const float* bproj,
                      float* x, int sameKV,
                      bf* QKV, bf* AO)
{
    bf* Q  = QKV;
    bf* Kb = QKV + (size_t)NTOK*DM;
    if (sameKV) {
        gemm(Hq, wqkv, bqkv, nullptr, QKV, NTOK, DM, DM, DM, DM, DM, 0, 1,
             0, 0, 0, (long)DM*DM, DM, 0, (long)NTOK*DM, 3, 3);
    } else {
        gemm(Hq, wqkv, bqkv, nullptr, Q, NTOK, DM, DM, DM, DM, DM, 0, 1);
        gemm(Hkv, wqkv + (size_t)DM*DM, bqkv + DM, nullptr, Kb,
             NTOK, DM, DM, DM, DM, DM, 0, 1,
             0, 0, 0, (long)DM*DM, DM, 0, (long)NTOK*DM, 2, 2);
    }
    bf* Vb = QKV + (size_t)2*NTOK*DM;
    dim3 fgrid(SEQ/FA_BQ, NB*NHD);
    flash_k<<<fgrid, 256, FA_SMEM>>>(Q, Kb, Vb, AO);
    gemm(AO, wproj, bproj, x, x, NTOK, DM, DM, DM, DM, DM, 0, 0);
}

extern "C" void kernel_launch(void* const* d_in, const int* in_sizes, int n_in,
                              void* d_out, int out_size)
{
    const int*   src        = (const int*)  d_in[0];
    const int*   tgt        = (const int*)  d_in[1];
    const float* emb        = (const float*)d_in[5];
    const float* enc_qkv_w  = (const float*)d_in[6];
    const float* enc_qkv_b  = (const float*)d_in[7];
    const float* enc_proj_w = (const float*)d_in[8];
    const float* enc_proj_b = (const float*)d_in[9];
    const float* enc_ff_w1  = (const float*)d_in[10];
    const float* enc_ff_b1  = (const float*)d_in[11];
    const float* enc_ff_w2  = (const float*)d_in[12];
    const float* enc_ff_b2  = (const float*)d_in[13];
    const float* enc_ln_g   = (const float*)d_in[14];
    const float* enc_ln_b   = (const float*)d_in[15];
    const float* enc_norm_g = (const float*)d_in[16];
    const float* enc_norm_b = (const float*)d_in[17];
    const float* dec_qkv_w  = (const float*)d_in[18];
    const float* dec_qkv_b  = (const float*)d_in[19];
    const float* dec_proj_w = (const float*)d_in[20];
    const float* dec_proj_b = (const float*)d_in[21];
    const float* dec_ff_w1  = (const float*)d_in[22];
    const float* dec_ff_b1  = (const float*)d_in[23];
    const float* dec_ff_w2  = (const float*)d_in[24];
    const float* dec_ff_b2  = (const float*)d_in[25];
    const float* dec_ln_g   = (const float*)d_in[26];
    const float* dec_ln_b   = (const float*)d_in[27];
    const float* dec_norm_g = (const float*)d_in[28];
    const float* dec_norm_b = (const float*)d_in[29];
    const float* gen_w      = (const float*)d_in[30];
    const float* gen_b      = (const float*)d_in[31];
    float* out = (float*)d_out;

    cudaFuncSetAttribute(flash_k, cudaFuncAttributeMaxDynamicSharedMemorySize, FA_SMEM);
    cudaFuncSetAttribute(gemm_ms<128>, cudaFuncAttributeMaxDynamicSharedMemorySize, GEMM_SMEM128);

    float *X,*Y;
    bf *Hb,*MEMb,*QKVb,*AOb,*FFb,*W;
    cudaGetSymbolAddress((void**)&X,    g_X);
    cudaGetSymbolAddress((void**)&Y,    g_Y);
    cudaGetSymbolAddress((void**)&Hb,   g_Hb);
    cudaGetSymbolAddress((void**)&MEMb, g_MEMb);
    cudaGetSymbolAddress((void**)&QKVb, g_QKVb);
    cudaGetSymbolAddress((void**)&AOb,  g_AOb);
    cudaGetSymbolAddress((void**)&FFb,  g_FFb);
    cudaGetSymbolAddress((void**)&W,    g_W);

    // ---- one-time (per replay) weight conversion ----
    cvt(enc_qkv_w,  W + O_ENC_QKV,  (long)NLE*3*DM*DM);
    cvt(enc_proj_w, W + O_ENC_PROJ, (long)NLE*DM*DM);
    cvt(enc_ff_w1,  W + O_ENC_FF1,  (long)NLE*DM*HFF);
    cvt(enc_ff_w2,  W + O_ENC_FF2,  (long)NLE*HFF*DM);
    cvt(dec_qkv_w,  W + O_DEC_QKV,  (long)NLD*2*3*DM*DM);
    cvt(dec_proj_w, W + O_DEC_PROJ, (long)NLD*2*DM*DM);
    cvt(dec_ff_w1,  W + O_DEC_FF1,  (long)NLD*DM*HFF);
    cvt(dec_ff_w2,  W + O_DEC_FF2,  (long)NLD*HFF*DM);
    cvt(gen_w,      W + O_GEN,      (long)DM*NV);

    // ---------------- encoder ----------------
    embed_k<<<NTOK,256>>>(src, emb, X);
    for (int l = 0; l < NLE; l++) {
        ln_k<<<NTOK/8,256>>>(X, enc_ln_g + (size_t)(l*2+0)*DM, enc_ln_b + (size_t)(l*2+0)*DM, Hb);
        attention(Hb, Hb,
                  W + O_ENC_QKV + (long)l*3*DM*DM, enc_qkv_b + (size_t)l*3*DM,
                  W + O_ENC_PROJ + (long)l*DM*DM,  enc_proj_b + (size_t)l*DM,
                  X, 1, QKVb, AOb);
        ln_k<<<NTOK/8,256>>>(X, enc_ln_g + (size_t)(l*2+1)*DM, enc_ln_b + (size_t)(l*2+1)*DM, Hb);
        gemm(Hb, W + O_ENC_FF1 + (long)l*DM*HFF, enc_ff_b1 + (size_t)l*HFF, nullptr, FFb,
             NTOK, HFF, DM, DM, HFF, HFF, 1, 1);
        gemm(FFb, W + O_ENC_FF2 + (long)l*HFF*DM, enc_ff_b2 + (size_t)l*DM, X, X,
             NTOK, DM, HFF, HFF, DM, DM, 1, 0);
    }
    ln_k<<<NTOK/8,256>>>(X, enc_norm_g, enc_norm_b, MEMb);

    // ---------------- decoder ----------------
    embed_k<<<NTOK,256>>>(tgt, emb, Y);
    for (int l = 0; l < NLD; l++) {
        ln_k<<<NTOK/8,256>>>(Y, dec_ln_g + (size_t)(l*3+0)*DM, dec_ln_b + (size_t)(l*3+0)*DM, Hb);
        attention(Hb, Hb,
                  W + O_DEC_QKV + (long)(l*2+0)*3*DM*DM, dec_qkv_b + (size_t)(l*2+0)*3*DM,
                  W + O_DEC_PROJ + (long)(l*2+0)*DM*DM,  dec_proj_b + (size_t)(l*2+0)*DM,
                  Y, 1, QKVb, AOb);
        ln_k<<<NTOK/8,256>>>(Y, dec_ln_g + (size_t)(l*3+1)*DM, dec_ln_b + (size_t)(l*3+1)*DM, Hb);
        attention(Hb, MEMb,
                  W + O_DEC_QKV + (long)(l*2+1)*3*DM*DM, dec_qkv_b + (size_t)(l*2+1)*3*DM,
                  W + O_DEC_PROJ + (long)(l*2+1)*DM*DM,  dec_proj_b + (size_t)(l*2+1)*DM,
                  Y, 0, QKVb, AOb);
        ln_k<<<NTOK/8,256>>>(Y, dec_ln_g + (size_t)(l*3+2)*DM, dec_ln_b + (size_t)(l*3+2)*DM, Hb);
        gemm(Hb, W + O_DEC_FF1 + (long)l*DM*HFF, dec_ff_b1 + (size_t)l*HFF, nullptr, FFb,
             NTOK, HFF, DM, DM, HFF, HFF, 1, 1);
        gemm(FFb, W + O_DEC_FF2 + (long)l*HFF*DM, dec_ff_b2 + (size_t)l*DM, Y, Y,
             NTOK, DM, HFF, HFF, DM, DM, 1, 0);
    }
    ln_k<<<NTOK/8,256>>>(Y, dec_norm_g, dec_norm_b, Hb);

    // ---------------- generator + log_softmax ----------------
    gemm(Hb, W + O_GEN, gen_b, nullptr, out, NTOK, NV, DM, DM, NV, NV, 0, 0);
    logsoftmax_k<<<NTOK,256>>>(out);
}

// round 14
// speedup vs baseline: 12.1525x; 1.0146x over previous
#include <cuda_runtime.h>
#include <cuda_bf16.h>
#include <math.h>

typedef __nv_bfloat16 bf;

// ---------------- problem constants ----------------
#define DM   1024
#define NHD  16
#define DH   64
#define SEQ  1024
#define NB   2
#define NTOK 2048
#define HFF  4096
#define NV   32000
#define NLE  6
#define NLD  6

// ---------------- bf16 weight pool ----------------
#define O_ENC_QKV  0L
#define O_ENC_PROJ 18874368L
#define O_ENC_FF1  25165824L
#define O_ENC_FF2  50331648L
#define O_DEC_QKV  75497472L
#define O_DEC_PROJ 113246208L
#define O_DEC_FF1  125829120L
#define O_DEC_FF2  150994944L
#define O_GEN      176160768L
#define W_TOTAL    208928768L

__device__ bf g_W[W_TOTAL];

// ---------------- scratch ----------------
__device__ float g_X [(size_t)NTOK*DM];
__device__ float g_Y [(size_t)NTOK*DM];
__device__ bf    g_Hb [(size_t)NTOK*DM];
__device__ bf    g_MEMb[(size_t)NTOK*DM];
__device__ bf    g_QKVb[(size_t)3*NTOK*DM];
__device__ bf    g_AOb [(size_t)NTOK*DM];
__device__ bf    g_FFb [(size_t)NTOK*HFF];

// ---------------- low-level helpers ----------------
__device__ __forceinline__ void cp16(void* d, const void* s){
    unsigned sd = (unsigned)__cvta_generic_to_shared(d);
    asm volatile("cp.async.cg.shared.global [%0], [%1], 16;\n" :: "r"(sd), "l"(s));
}
__device__ __forceinline__ void cpcommit(){ asm volatile("cp.async.commit_group;\n"); }
template<int N> __device__ __forceinline__ void cpwait(){
    asm volatile("cp.async.wait_group %0;\n" :: "n"(N));
}
__device__ __forceinline__ unsigned pack_bf2(float a, float b){
    __nv_bfloat162 h = __floats2bfloat162_rn(a, b);
    return *(unsigned*)&h;
}
__device__ __forceinline__ void ldm4(unsigned &a0, unsigned &a1, unsigned &a2, unsigned &a3,
                                     unsigned addr){
    asm volatile("ldmatrix.sync.aligned.m8n8.x4.shared.b16 {%0,%1,%2,%3}, [%4];"
                 : "=r"(a0),"=r"(a1),"=r"(a2),"=r"(a3) : "r"(addr));
}
__device__ __forceinline__ void ldm4t(unsigned &a0, unsigned &a1, unsigned &a2, unsigned &a3,
                                      unsigned addr){
    asm volatile("ldmatrix.sync.aligned.m8n8.x4.trans.shared.b16 {%0,%1,%2,%3}, [%4];"
                 : "=r"(a0),"=r"(a1),"=r"(a2),"=r"(a3) : "r"(addr));
}
__device__ __forceinline__ void mmabf(float* c, unsigned a0, unsigned a1, unsigned a2, unsigned a3,
                                      unsigned b0, unsigned b1){
    asm volatile("mma.sync.aligned.m16n8k16.row.col.f32.bf16.bf16.f32 "
                 "{%0,%1,%2,%3}, {%4,%5,%6,%7}, {%8,%9}, {%0,%1,%2,%3};"
                 : "+f"(c[0]),"+f"(c[1]),"+f"(c[2]),"+f"(c[3])
                 : "r"(a0),"r"(a1),"r"(a2),"r"(a3),"r"(b0),"r"(b1));
}
__device__ __forceinline__ float gelu1(float x){
    return 0.5f*x*(1.f+erff(x*0.70710678f));
}

// ---------------- reductions ----------------
__device__ __forceinline__ float warpSum(float v){
#pragma unroll
    for (int o=16;o>0;o>>=1) v += __shfl_xor_sync(0xffffffffu, v, o);
    return v;
}

// ---------------- f32 -> bf16 converter ----------------
__global__ void cvt_k(const float* __restrict__ s, bf* __restrict__ d, long n){
    long i = ((long)blockIdx.x*blockDim.x + threadIdx.x)*4;
    if (i < n){
        float4 v = *(const float4*)(s+i);
        *(__nv_bfloat162*)(d+i)   = __floats2bfloat162_rn(v.x, v.y);
        *(__nv_bfloat162*)(d+i+2) = __floats2bfloat162_rn(v.z, v.w);
    }
}

// ---------------- GEMM config ----------------
#define BN 128
#define BK 32
#define ASTR 40
#define BSTR 136
#define NSTAGE 4
#define BTILE (BK*BSTR)
#define ATILE128 (128*ASTR)
#define GEMM_SMEM128 ((ATILE128+BTILE)*NSTAGE*2)

// -------- epilogue helper (shared between variants) --------
__device__ __forceinline__ void epilogue_tile(
    float* acc4, long r0, long r1, long gn, long coff, int ldc,
    const float* bias, const float* res, int doGelu, int outBf,
    float* C, bf* Cb)
{
    float v0 = acc4[0], v1 = acc4[1], v2 = acc4[2], v3 = acc4[3];
    if (bias){
        float b0 = bias[gn], b1 = bias[gn+1];
        v0 += b0; v1 += b1; v2 += b0; v3 += b1;
    }
    if (doGelu){
        v0 = gelu1(v0); v1 = gelu1(v1); v2 = gelu1(v2); v3 = gelu1(v3);
    }
    if (!outBf){
        if (res){
            const float2 q0 = *(const float2*)(res + coff + r0*(long)ldc + gn);
            const float2 q1 = *(const float2*)(res + coff + r1*(long)ldc + gn);
            v0 += q0.x; v1 += q0.y; v2 += q1.x; v3 += q1.y;
        }
        *(float2*)(C + coff + r0*(long)ldc + gn) = make_float2(v0, v1);
        *(float2*)(C + coff + r1*(long)ldc + gn) = make_float2(v2, v3);
    } else {
        *(unsigned*)(Cb + coff + r0*(long)ldc + gn) = pack_bf2(v0, v1);
        *(unsigned*)(Cb + coff + r1*(long)ldc + gn) = pack_bf2(v2, v3);
    }
}

// ---------------- 256-thread variant: 8 warps x 64x32 ----------------
__global__ void __launch_bounds__(256, 2) gemm_ms(
    const bf* __restrict__ A, const bf* __restrict__ B,
    const float* __restrict__ bias, const float* __restrict__ res,
    void* __restrict__ Cv,
    int M, int N, int K, int lda, int ldb, int ldc,
    int doGelu, int outBf,
    long aob, long aoh, long bob, long boh, long biasoh,
    long cob, long coh, int nh)
{
    extern __shared__ __align__(16) unsigned char smraw[];
    bf* As = (bf*)smraw;
    bf* Bs = As + NSTAGE*ATILE128;
    unsigned smA = (unsigned)__cvta_generic_to_shared(As);
    unsigned smB = (unsigned)__cvta_generic_to_shared(Bs);

    int z = blockIdx.z, zb = z/nh, zh = z - zb*nh;
    A += zb*aob + zh*aoh;
    B += zb*bob + zh*boh;
    if (bias) bias += zh*biasoh;
    long coff = zb*cob + zh*coh;

    int tid = threadIdx.x;
    int wid = tid >> 5, lane = tid & 31;
    int wm = wid >> 2, wn = wid & 3;
    long row0 = (long)blockIdx.y * 128;
    long col0 = (long)blockIdx.x * BN;

    const bf* Ag0 = A + (row0 + (tid>>1))*(long)lda + (tid&1)*16;
    bf* Ad0 = As + (tid>>1)*ASTR + (tid&1)*16;
    const bf* Bg0 = B + (long)(tid>>3)*ldb + col0 + (tid&7)*16;
    bf* Bd0 = Bs + (tid>>3)*BSTR + (tid&7)*16;

    auto issue = [&](int kt, int s){
        const bf* ag = Ag0 + kt*BK;
        bf* ad = Ad0 + s*ATILE128;
        cp16(ad,     ag);
        cp16(ad + 8, ag + 8);
        const bf* bg = Bg0 + (long)kt*BK*ldb;
        bf* bd = Bd0 + s*BTILE;
        cp16(bd,     bg);
        cp16(bd + 8, bg + 8);
    };

    float acc[4][4][4];
#pragma unroll
    for (int i=0;i<4;i++)
#pragma unroll
        for (int j=0;j<4;j++)
#pragma unroll
            for (int q=0;q<4;q++) acc[i][j][q] = 0.f;

    unsigned lrow = (unsigned)(lane & 15);
    unsigned lch  = ((unsigned)(lane >> 4)) << 3;

    int KT = K / BK;
    issue(0,0); cpcommit();
    issue(1,1); cpcommit();
    issue(2,2); cpcommit();

    for (int kt = 0; kt < KT; kt++){
        cpwait<2>();
        __syncthreads();
        if (kt+3 < KT) issue(kt+3, (kt+3)&3);
        cpcommit();
        unsigned sa = smA + (unsigned)(kt&3)*ATILE128*2u;
        unsigned sb = smB + (unsigned)(kt&3)*BTILE*2u;
#pragma unroll
        for (int kk = 0; kk < BK; kk += 16){
            unsigned af[4][4];
#pragma unroll
            for (int mi=0;mi<4;mi++){
                unsigned aaddr = sa + (((unsigned)(wm*64) + mi*16u + lrow)*ASTR + kk + lch)*2u;
                ldm4(af[mi][0], af[mi][1], af[mi][2], af[mi][3], aaddr);
            }
#pragma unroll
            for (int ni=0;ni<2;ni++){
                unsigned b0,b1,b2,b3;
                unsigned baddr = sb + ((kk + lrow)*BSTR + wn*32u + ni*16u + lch)*2u;
                ldm4t(b0,b1,b2,b3, baddr);
#pragma unroll
                for (int mi=0;mi<4;mi++){
                    mmabf(acc[mi][2*ni],   af[mi][0],af[mi][1],af[mi][2],af[mi][3], b0,b1);
                    mmabf(acc[mi][2*ni+1], af[mi][0],af[mi][1],af[mi][2],af[mi][3], b2,b3);
                }
            }
        }
    }
    cpwait<0>();

    float* C  = (float*)Cv;
    bf*    Cb = (bf*)Cv;
    int rbase = wm*64 + (lane >> 2);
    int cbase = wn*32 + (lane & 3)*2;
#pragma unroll
    for (int mi=0;mi<4;mi++){
        long r0 = row0 + rbase + mi*16;
        long r1 = r0 + 8;
#pragma unroll
        for (int nj=0;nj<4;nj++){
            long gn = col0 + cbase + nj*8;
            epilogue_tile(acc[mi][nj], r0, r1, gn, coff, ldc, bias, res, doGelu, outBf, C, Cb);
        }
    }
}

// ---------------- 512-thread variant: 16 warps x 32x32 (for small grids) --
__global__ void __launch_bounds__(512, 1) gemm_ms512(
    const bf* __restrict__ A, const bf* __restrict__ B,
    const float* __restrict__ bias, const float* __restrict__ res,
    void* __restrict__ Cv,
    int M, int N, int K, int lda, int ldb, int ldc,
    int doGelu, int outBf,
    long aob, long aoh, long bob, long boh, long biasoh,
    long cob, long coh, int nh)
{
    extern __shared__ __align__(16) unsigned char smraw[];
    bf* As = (bf*)smraw;
    bf* Bs = As + NSTAGE*ATILE128;
    unsigned smA = (unsigned)__cvta_generic_to_shared(As);
    unsigned smB = (unsigned)__cvta_generic_to_shared(Bs);

    int z = blockIdx.z, zb = z/nh, zh = z - zb*nh;
    A += zb*aob + zh*aoh;
    B += zb*bob + zh*boh;
    if (bias) bias += zh*biasoh;
    long coff = zb*cob + zh*coh;

    int tid = threadIdx.x;
    int wid = tid >> 5, lane = tid & 31;
    int wm = wid >> 2, wn = wid & 3;   // 4x4 warp grid, 32x32 tiles
    long row0 = (long)blockIdx.y * 128;
    long col0 = (long)blockIdx.x * BN;

    // loaders: 512 threads, 1 cp16 each for A (128x32) and B (32x128)
    const bf* Ag0 = A + (row0 + (tid>>2))*(long)lda + (tid&3)*8;
    bf* Ad0 = As + (tid>>2)*ASTR + (tid&3)*8;
    const bf* Bg0 = B + (long)(tid>>4)*ldb + col0 + (tid&15)*8;
    bf* Bd0 = Bs + (tid>>4)*BSTR + (tid&15)*8;

    auto issue = [&](int kt, int s){
        cp16(Ad0 + s*ATILE128, Ag0 + kt*BK);
        cp16(Bd0 + s*BTILE, Bg0 + (long)kt*BK*ldb);
    };

    float acc[2][4][4];
#pragma unroll
    for (int i=0;i<2;i++)
#pragma unroll
        for (int j=0;j<4;j++)
#pragma unroll
            for (int q=0;q<4;q++) acc[i][j][q] = 0.f;

    unsigned lrow = (unsigned)(lane & 15);
    unsigned lch  = ((unsigned)(lane >> 4)) << 3;

    int KT = K / BK;
    issue(0,0); cpcommit();
    issue(1,1); cpcommit();
    issue(2,2); cpcommit();

    for (int kt = 0; kt < KT; kt++){
        cpwait<2>();
        __syncthreads();
        if (kt+3 < KT) issue(kt+3, (kt+3)&3);
        cpcommit();
        unsigned sa = smA + (unsigned)(kt&3)*ATILE128*2u;
        unsigned sb = smB + (unsigned)(kt&3)*BTILE*2u;
#pragma unroll
        for (int kk = 0; kk < BK; kk += 16){
            unsigned af[2][4];
#pragma unroll
            for (int mi=0;mi<2;mi++){
                unsigned aaddr = sa + (((unsigned)(wm*32) + mi*16u + lrow)*ASTR + kk + lch)*2u;
                ldm4(af[mi][0], af[mi][1], af[mi][2], af[mi][3], aaddr);
            }
#pragma unroll
            for (int ni=0;ni<2;ni++){
                unsigned b0,b1,b2,b3;
                unsigned baddr = sb + ((kk + lrow)*BSTR + wn*32u + ni*16u + lch)*2u;
                ldm4t(b0,b1,b2,b3, baddr);
#pragma unroll
                for (int mi=0;mi<2;mi++){
                    mmabf(acc[mi][2*ni],   af[mi][0],af[mi][1],af[mi][2],af[mi][3], b0,b1);
                    mmabf(acc[mi][2*ni+1], af[mi][0],af[mi][1],af[mi][2],af[mi][3], b2,b3);
                }
            }
        }
    }
    cpwait<0>();

    float* C  = (float*)Cv;
    bf*    Cb = (bf*)Cv;
    int rbase = wm*32 + (lane >> 2);
    int cbase = wn*32 + (lane & 3)*2;
#pragma unroll
    for (int mi=0;mi<2;mi++){
        long r0 = row0 + rbase + mi*16;
        long r1 = r0 + 8;
#pragma unroll
        for (int nj=0;nj<4;nj++){
            long gn = col0 + cbase + nj*8;
            epilogue_tile(acc[mi][nj], r0, r1, gn, coff, ldc, bias, res, doGelu, outBf, C, Cb);
        }
    }
}

// ---------------- flash attention: 64-row KV tiles, 2 CTAs/SM ------------
#define FA_BQ  128
#define FA_SMEM 55296

__global__ void __launch_bounds__(256, 2) flash_k(
    const bf* __restrict__ Qg, const bf* __restrict__ Kg,
    const bf* __restrict__ Vg, bf* __restrict__ Og)
{
    extern __shared__ char smc[];
    unsigned smem0 = (unsigned)__cvta_generic_to_shared(smc);
    unsigned smQ = smem0;
    unsigned smK = smem0 + 18432u;
    unsigned smV = smem0 + 18432u + 18432u;
    bf* gQ = (bf*)smc;
    bf* gK = (bf*)(smc + 18432);
    bf* gV = (bf*)(smc + 18432 + 18432);

    int tid = threadIdx.x;
    int wid = tid >> 5, lane = tid & 31;
    int bh = blockIdx.y;
    long base = ((long)(bh >> 4) * SEQ) * DM + (bh & 15) * DH;
    int q0 = blockIdx.x * FA_BQ;

    {
        int r  = tid >> 1;
        int hc = tid & 1;
        const uint4* qs = (const uint4*)(Qg + base + (long)(q0+r)*DM + hc*32);
        uint4* qd = (uint4*)(gQ + r*72 + hc*32);
#pragma unroll
        for (int i=0;i<4;i++) qd[i] = qs[i];
    }

    int kr = tid >> 2;
    int kc = (tid & 3)*16;
    auto issueKV = [&](int j, int buf){
        long goff = base + (long)(j*64 + kr)*DM + kc;
        bf* kd = gK + buf*(64*72) + kr*72 + kc;
        bf* vd = gV + buf*(64*72) + kr*72 + kc;
        cp16(kd,     Kg + goff);
        cp16(kd + 8, Kg + goff + 8);
        cp16(vd,     Vg + goff);
        cp16(vd + 8, Vg + goff + 8);
    };

    issueKV(0, 0); cpcommit();
    __syncthreads();

    unsigned lrow = (unsigned)(lane & 15);
    unsigned lch  = ((unsigned)(lane >> 4)) << 3;
    unsigned qa[4][4];
    {
        unsigned qaddr = smQ + ((wid*16u + lrow)*72u + lch)*2u;
#pragma unroll
        for (int s=0;s<4;s++)
            ldm4(qa[s][0], qa[s][1], qa[s][2], qa[s][3], qaddr + s*32u);
    }

    float ot[8][4];
#pragma unroll
    for (int d=0;d<8;d++){ ot[d][0]=0.f; ot[d][1]=0.f; ot[d][2]=0.f; ot[d][3]=0.f; }
    float m0 = -INFINITY, m1 = -INFINITY, l0 = 0.f, l1 = 0.f;

    const int NKV = SEQ/64;
    for (int j = 0; j < NKV; j++){
        int cb = j & 1;
        cpwait<0>();
        __syncthreads();
        if (j+1 < NKV) issueKV(j+1, cb^1);
        cpcommit();

        unsigned kb = smK + (unsigned)cb*9216u;
        unsigned vb = smV + (unsigned)cb*9216u;

        float sc[8][4];
#pragma unroll
        for (int t=0;t<8;t++){ sc[t][0]=0.f; sc[t][1]=0.f; sc[t][2]=0.f; sc[t][3]=0.f; }
#pragma unroll
        for (int g=0; g<4; g++){
            unsigned ka = kb + ((g*16u + lrow)*72u + lch)*2u;
#pragma unroll
            for (int s=0; s<4; s++){
                unsigned k0,k1,k2,k3;
                ldm4(k0,k1,k2,k3, ka + s*32u);
                mmabf(sc[2*g],   qa[s][0],qa[s][1],qa[s][2],qa[s][3], k0,k2);
                mmabf(sc[2*g+1], qa[s][0],qa[s][1],qa[s][2],qa[s][3], k1,k3);
            }
        }

        float mx0 = -INFINITY, mx1 = -INFINITY;
#pragma unroll
        for (int t=0;t<8;t++){
            mx0 = fmaxf(mx0, fmaxf(sc[t][0], sc[t][1]));
            mx1 = fmaxf(mx1, fmaxf(sc[t][2], sc[t][3]));
        }
        mx0 = fmaxf(mx0, __shfl_xor_sync(0xffffffffu, mx0, 1));
        mx0 = fmaxf(mx0, __shfl_xor_sync(0xffffffffu, mx0, 2));
        mx1 = fmaxf(mx1, __shfl_xor_sync(0xffffffffu, mx1, 1));
        mx1 = fmaxf(mx1, __shfl_xor_sync(0xffffffffu, mx1, 2));
        float mn0 = fmaxf(m0, mx0), mn1 = fmaxf(m1, mx1);
        float al0 = __expf(m0 - mn0), al1 = __expf(m1 - mn1);
        float s0 = 0.f, s1 = 0.f;
        unsigned pa[4][4];
#pragma unroll
        for (int t=0;t<4;t++){
            float e00 = __expf(sc[2*t][0]-mn0),   e01 = __expf(sc[2*t][1]-mn0);
            float e10 = __expf(sc[2*t][2]-mn1),   e11 = __expf(sc[2*t][3]-mn1);
            float f00 = __expf(sc[2*t+1][0]-mn0), f01 = __expf(sc[2*t+1][1]-mn0);
            float f10 = __expf(sc[2*t+1][2]-mn1), f11 = __expf(sc[2*t+1][3]-mn1);
            s0 += (e00+e01)+(f00+f01);
            s1 += (e10+e11)+(f10+f11);
            pa[t][0] = pack_bf2(e00,e01);
            pa[t][1] = pack_bf2(e10,e11);
            pa[t][2] = pack_bf2(f00,f01);
            pa[t][3] = pack_bf2(f10,f11);
        }
        s0 += __shfl_xor_sync(0xffffffffu, s0, 1);
        s0 += __shfl_xor_sync(0xffffffffu, s0, 2);
        s1 += __shfl_xor_sync(0xffffffffu, s1, 1);
        s1 += __shfl_xor_sync(0xffffffffu, s1, 2);
        l0 = l0*al0 + s0;
        l1 = l1*al1 + s1;
        m0 = mn0; m1 = mn1;
#pragma unroll
        for (int d=0;d<8;d++){
            ot[d][0]*=al0; ot[d][1]*=al0; ot[d][2]*=al1; ot[d][3]*=al1;
        }

#pragma unroll
        for (int s=0; s<4; s++){
            unsigned va = vb + ((s*16u + lrow)*72u + lch)*2u;
#pragma unroll
            for (int d=0; d<4; d++){
                unsigned v0,v1,v2,v3;
                ldm4t(v0,v1,v2,v3, va + d*32u);
                mmabf(ot[2*d],   pa[s][0],pa[s][1],pa[s][2],pa[s][3], v0,v1);
                mmabf(ot[2*d+1], pa[s][0],pa[s][1],pa[s][2],pa[s][3], v2,v3);
            }
        }
    }

    float inv0 = 1.f/l0, inv1 = 1.f/l1;
    int row0 = q0 + wid*16 + (lane >> 2);
    int row1 = row0 + 8;
    bf* o0 = Og + base + (long)row0*DM;
    bf* o1 = Og + base + (long)row1*DM;
    int cb2 = (lane & 3)*2;
#pragma unroll
    for (int d=0; d<8; d++){
        int col = d*8 + cb2;
        *(unsigned*)(o0 + col) = pack_bf2(ot[d][0]*inv0, ot[d][1]*inv0);
        *(unsigned*)(o1 + col) = pack_bf2(ot[d][2]*inv1, ot[d][3]*inv1);
    }
}

// ---------------- embedding + positional encoding ----------------
__global__ void embed_k(const int* __restrict__ tok, const float* __restrict__ emb,
                        float* __restrict__ out)
{
    int t = blockIdx.x;
    int s = t & (SEQ-1);
    int id = tok[t];
    const float* e = emb + (long)id*DM;
    float* o = out + (long)t*DM;
    const float c = -logf(10000.0f) / (float)DM;
    for (int d = threadIdx.x; d < DM; d += blockDim.x) {
        int i2 = d & ~1;
        float ang = (float)s * expf((float)i2 * c);
        float pe = (d & 1) ? cosf(ang) : sinf(ang);
        o[d] = e[d]*32.0f + pe;
    }
}

// ---------------- LayerNorm: warp-per-token ----------------
__global__ void ln_k(const float* __restrict__ x, const float* __restrict__ g,
                     const float* __restrict__ b, bf* __restrict__ out)
{
    int lane = threadIdx.x & 31, w = threadIdx.x >> 5;
    long t = (long)blockIdx.x*8 + w;
    const float4* xr = (const float4*)(x + t*DM);
    float4 v[8];
    float s = 0.f, ss = 0.f;
#pragma unroll
    for (int i=0;i<8;i++){
        v[i] = xr[lane + i*32];
        s  += v[i].x+v[i].y+v[i].z+v[i].w;
        ss += v[i].x*v[i].x+v[i].y*v[i].y+v[i].z*v[i].z+v[i].w*v[i].w;
    }
    s  = warpSum(s);
    ss = warpSum(ss);
    float mean = s * (1.0f/DM);
    float var  = ss * (1.0f/DM) - mean*mean;
    float inv  = rsqrtf(var + 1e-5f);
    uint2* o = (uint2*)(out + t*DM);
#pragma unroll
    for (int i=0;i<8;i++){
        float4 gg = ((const float4*)g)[lane + i*32];
        float4 bb = ((const float4*)b)[lane + i*32];
        uint2 wv;
        wv.x = pack_bf2((v[i].x-mean)*inv*gg.x + bb.x, (v[i].y-mean)*inv*gg.y + bb.y);
        wv.y = pack_bf2((v[i].z-mean)*inv*gg.z + bb.z, (v[i].w-mean)*inv*gg.w + bb.w);
        o[lane + i*32] = wv;
    }
}

// ---------------- log_softmax over NV ----------------
__global__ void logsoftmax_k(float* __restrict__ p)
{
    __shared__ float shm[32], shs[32];
    float* r = p + (long)blockIdx.x * NV;
    int tid = threadIdx.x, lane = tid & 31, w = tid >> 5;

    float m = -3.0e38f, s = 0.f;
    for (int d = tid; d < NV; d += blockDim.x){
        float x = r[d];
        float mn = fmaxf(m, x);
        s = s*__expf(m - mn) + __expf(x - mn);
        m = mn;
    }
#pragma unroll
    for (int o=16;o>0;o>>=1){
        float m2 = __shfl_xor_sync(0xffffffffu, m, o);
        float s2 = __shfl_xor_sync(0xffffffffu, s, o);
        float mn = fmaxf(m, m2);
        s = s*__expf(m-mn) + s2*__expf(m2-mn);
        m = mn;
    }
    if (lane==0){ shm[w] = m; shs[w] = s; }
    __syncthreads();
    if (w==0){
        float mm = (lane < (int)(blockDim.x>>5)) ? shm[lane] : -3.0e38f;
        float ss2 = (lane < (int)(blockDim.x>>5)) ? shs[lane] : 0.f;
#pragma unroll
        for (int o=16;o>0;o>>=1){
            float m2 = __shfl_xor_sync(0xffffffffu, mm, o);
            float s2 = __shfl_xor_sync(0xffffffffu, ss2, o);
            float mn = fmaxf(mm, m2);
            ss2 = ss2*__expf(mm-mn) + s2*__expf(m2-mn);
            mm = mn;
        }
        if (lane==0){ shm[0] = mm; shs[0] = ss2; }
    }
    __syncthreads();
    float lse = shm[0] + logf(shs[0]);
    for (int d = tid; d < NV; d += blockDim.x) r[d] -= lse;
}

// ---------------- host helpers ----------------
static void gemm(const bf* A, const bf* B, const float* bias, const float* res,
                 void* C, int M, int N, int K, int lda, int ldb, int ldc,
                 int gelu, int outBf,
                 long aob=0, long aoh=0, long bob=0, long boh=0, long biasoh=0,
                 long cob=0, long coh=0, int nh=1, int nz=1)
{
    dim3 grid(N/BN, M/128, nz);
    long ctas = (long)grid.x*grid.y*grid.z;
    if (ctas <= 148){
        gemm_ms512<<<grid, 512, GEMM_SMEM128>>>(A,B,bias,res,C,M,N,K,lda,ldb,ldc,gelu,outBf,
                                                aob,aoh,bob,boh,biasoh,cob,coh,nh);
    } else {
        gemm_ms<<<grid, 256, GEMM_SMEM128>>>(A,B,bias,res,C,M,N,K,lda,ldb,ldc,gelu,outBf,
                                             aob,aoh,bob,boh,biasoh,cob,coh,nh);
    }
}

static void cvt(const float* s, bf* d, long n){
    long blocks = (n/4 + 255)/256;
    cvt_k<<<(unsigned)blocks, 256>>>(s, d, n);
}

static void attention(const bf* Hq, const bf* Hkv,
                      const bf* wqkv, const float* bqkv,
                      const bf* wproj, const float* bproj,
                      float* x, int sameKV,
                      bf* QKV, bf* AO)
{
    bf* Q  = QKV;
    bf* Kb = QKV + (size_t)NTOK*DM;
    if (sameKV) {
        gemm(Hq, wqkv, bqkv, nullptr, QKV, NTOK, DM, DM, DM, DM, DM, 0, 1,
             0, 0, 0, (long)DM*DM, DM, 0, (long)NTOK*DM, 3, 3);
    } else {
        gemm(Hq, wqkv, bqkv, nullptr, Q, NTOK, DM, DM, DM, DM, DM, 0, 1);
        gemm(Hkv, wqkv + (size_t)DM*DM, bqkv + DM, nullptr, Kb,
             NTOK, DM, DM, DM, DM, DM, 0, 1,
             0, 0, 0, (long)DM*DM, DM, 0, (long)NTOK*DM, 2, 2);
    }
    bf* Vb = QKV + (size_t)2*NTOK*DM;
    dim3 fgrid(SEQ/FA_BQ, NB*NHD);
    flash_k<<<fgrid, 256, FA_SMEM>>>(Q, Kb, Vb, AO);
    gemm(AO, wproj, bproj, x, x, NTOK, DM, DM, DM, DM, DM, 0, 0);
}

extern "C" void kernel_launch(void* const* d_in, const int* in_sizes, int n_in,
                              void* d_out, int out_size)
{
    const int*   src        = (const int*)  d_in[0];
    const int*   tgt        = (const int*)  d_in[1];
    const float* emb        = (const float*)d_in[5];
    const float* enc_qkv_w  = (const float*)d_in[6];
    const float* enc_qkv_b  = (const float*)d_in[7];
    const float* enc_proj_w = (const float*)d_in[8];
    const float* enc_proj_b = (const float*)d_in[9];
    const float* enc_ff_w1  = (const float*)d_in[10];
    const float* enc_ff_b1  = (const float*)d_in[11];
    const float* enc_ff_w2  = (const float*)d_in[12];
    const float* enc_ff_b2  = (const float*)d_in[13];
    const float* enc_ln_g   = (const float*)d_in[14];
    const float* enc_ln_b   = (const float*)d_in[15];
    const float* enc_norm_g = (const float*)d_in[16];
    const float* enc_norm_b = (const float*)d_in[17];
    const float* dec_qkv_w  = (const float*)d_in[18];
    const float* dec_qkv_b  = (const float*)d_in[19];
    const float* dec_proj_w = (const float*)d_in[20];
    const float* dec_proj_b = (const float*)d_in[21];
    const float* dec_ff_w1  = (const float*)d_in[22];
    const float* dec_ff_b1  = (const float*)d_in[23];
    const float* dec_ff_w2  = (const float*)d_in[24];
    const float* dec_ff_b2  = (const float*)d_in[25];
    const float* dec_ln_g   = (const float*)d_in[26];
    const float* dec_ln_b   = (const float*)d_in[27];
    const float* dec_norm_g = (const float*)d_in[28];
    const float* dec_norm_b = (const float*)d_in[29];
    const float* gen_w      = (const float*)d_in[30];
    const float* gen_b      = (const float*)d_in[31];
    float* out = (float*)d_out;

    cudaFuncSetAttribute(flash_k, cudaFuncAttributeMaxDynamicSharedMemorySize, FA_SMEM);
    cudaFuncSetAttribute(gemm_ms, cudaFuncAttributeMaxDynamicSharedMemorySize, GEMM_SMEM128);
    cudaFuncSetAttribute(gemm_ms512, cudaFuncAttributeMaxDynamicSharedMemorySize, GEMM_SMEM128);

    float *X,*Y;
    bf *Hb,*MEMb,*QKVb,*AOb,*FFb,*W;
    cudaGetSymbolAddress((void**)&X,    g_X);
    cudaGetSymbolAddress((void**)&Y,    g_Y);
    cudaGetSymbolAddress((void**)&Hb,   g_Hb);
    cudaGetSymbolAddress((void**)&MEMb, g_MEMb);
    cudaGetSymbolAddress((void**)&QKVb, g_QKVb);
    cudaGetSymbolAddress((void**)&AOb,  g_AOb);
    cudaGetSymbolAddress((void**)&FFb,  g_FFb);
    cudaGetSymbolAddress((void**)&W,    g_W);

    // ---- one-time (per replay) weight conversion ----
    cvt(enc_qkv_w,  W + O_ENC_QKV,  (long)NLE*3*DM*DM);
    cvt(enc_proj_w, W + O_ENC_PROJ, (long)NLE*DM*DM);
    cvt(enc_ff_w1,  W + O_ENC_FF1,  (long)NLE*DM*HFF);
    cvt(enc_ff_w2,  W + O_ENC_FF2,  (long)NLE*HFF*DM);
    cvt(dec_qkv_w,  W + O_DEC_QKV,  (long)NLD*2*3*DM*DM);
    cvt(dec_proj_w, W + O_DEC_PROJ, (long)NLD*2*DM*DM);
    cvt(dec_ff_w1,  W + O_DEC_FF1,  (long)NLD*DM*HFF);
    cvt(dec_ff_w2,  W + O_DEC_FF2,  (long)NLD*HFF*DM);
    cvt(gen_w,      W + O_GEN,      (long)DM*NV);

    // ---------------- encoder ----------------
    embed_k<<<NTOK,256>>>(src, emb, X);
    for (int l = 0; l < NLE; l++) {
        ln_k<<<NTOK/8,256>>>(X, enc_ln_g + (size_t)(l*2+0)*DM, enc_ln_b + (size_t)(l*2+0)*DM, Hb);
        attention(Hb, Hb,
                  W + O_ENC_QKV + (long)l*3*DM*DM, enc_qkv_b + (size_t)l*3*DM,
                  W + O_ENC_PROJ + (long)l*DM*DM,  enc_proj_b + (size_t)l*DM,
                  X, 1, QKVb, AOb);
        ln_k<<<NTOK/8,256>>>(X, enc_ln_g + (size_t)(l*2+1)*DM, enc_ln_b + (size_t)(l*2+1)*DM, Hb);
        gemm(Hb, W + O_ENC_FF1 + (long)l*DM*HFF, enc_ff_b1 + (size_t)l*HFF, nullptr, FFb,
             NTOK, HFF, DM, DM, HFF, HFF, 1, 1);
        gemm(FFb, W + O_ENC_FF2 + (long)l*HFF*DM, enc_ff_b2 + (size_t)l*DM, X, X,
             NTOK, DM, HFF, HFF, DM, DM, 1, 0);
    }
    ln_k<<<NTOK/8,256>>>(X, enc_norm_g, enc_norm_b, MEMb);

    // ---------------- decoder ----------------
    embed_k<<<NTOK,256>>>(tgt, emb, Y);
    for (int l = 0; l < NLD; l++) {
        ln_k<<<NTOK/8,256>>>(Y, dec_ln_g + (size_t)(l*3+0)*DM, dec_ln_b + (size_t)(l*3+0)*DM, Hb);
        attention(Hb, Hb,
                  W + O_DEC_QKV + (long)(l*2+0)*3*DM*DM, dec_qkv_b + (size_t)(l*2+0)*3*DM,
                  W + O_DEC_PROJ + (long)(l*2+0)*DM*DM,  dec_proj_b + (size_t)(l*2+0)*DM,
                  Y, 1, QKVb, AOb);
        ln_k<<<NTOK/8,256>>>(Y, dec_ln_g + (size_t)(l*3+1)*DM, dec_ln_b + (size_t)(l*3+1)*DM, Hb);
        attention(Hb, MEMb,
                  W + O_DEC_QKV + (long)(l*2+1)*3*DM*DM, dec_qkv_b + (size_t)(l*2+1)*3*DM,
                  W + O_DEC_PROJ + (long)(l*2+1)*DM*DM,  dec_proj_b + (size_t)(l*2+1)*DM,
                  Y, 0, QKVb, AOb);
        ln_k<<<NTOK/8,256>>>(Y, dec_ln_g + (size_t)(l*3+2)*DM, dec_ln_b + (size_t)(l*3+2)*DM, Hb);
        gemm(Hb, W + O_DEC_FF1 + (long)l*DM*HFF, dec_ff_b1 + (size_t)l*HFF, nullptr, FFb,
             NTOK, HFF, DM, DM, HFF, HFF, 1, 1);
        gemm(FFb, W + O_DEC_FF2 + (long)l*HFF*DM, dec_ff_b2 + (size_t)l*DM, Y, Y,
             NTOK, DM, HFF, HFF, DM, DM, 1, 0);
    }
    ln_k<<<NTOK/8,256>>>(Y, dec_norm_g, dec_norm_b, Hb);

    // ---------------- generator + log_softmax ----------------
    gemm(Hb, W + O_GEN, gen_b, nullptr, out, NTOK, NV, DM, DM, NV, NV, 0, 0);
    logsoftmax_k<<<NTOK,256>>>(out);
}